// round 4
// baseline (speedup 1.0000x reference)
#include <cuda_runtime.h>
#include <math.h>

// ---------------- problem constants ----------------
#define BB 2
#define NN 32768
#define CC 512
#define HH 8
#define DH 64
#define GG 64
#define CD 256
#define ROWS (BB*NN)          // 65536
#define INNER (HH*DH)         // 512
#define EPS 1e-5f

// ---------------- scratch ----------------
__device__ float g_fxmid[ROWS * INNER];
__device__ float g_w    [ROWS * INNER];
__device__ float g_npart[256 * 512];
__device__ float g_norm [BB * HH * GG];
__device__ float g_tpart[16 * 32 * 4096];
__device__ float g_tok  [16 * 4096];
__device__ float g_ot   [16 * 4096];
__device__ float g_M    [BB * 512 * 512];
__device__ float g_Wcomb[512 * 512];
__device__ float g_bcomb[512];

// ============================================================
// TF32 GEMM, 128x128x32 tile, 8 warps, double-buffered cp.async,
// in-register cvt.rna (precision), single sync per k-tile.
// SOFTMAX=1: per-head (64-col) softmax epilogue, 3-pass register-light.
// ============================================================
#define A_LDS 36
#define B_LDS 132
#define CT_LDS 132
#define GEMM_SMEM 70656   // 2*(128*36 + 32*132)*4 bytes; epilogue reuses 128*132*4=67584

__device__ __forceinline__ void cp16(void* dst, const void* src) {
    unsigned d = (unsigned)__cvta_generic_to_shared(dst);
    asm volatile("cp.async.cg.shared.global [%0], [%1], 16;" :: "r"(d), "l"(src));
}

__device__ __forceinline__ unsigned f2tf(float f) {
    unsigned u;
    asm("cvt.rna.tf32.f32 %0, %1;" : "=r"(u) : "f"(f));
    return u;
}

__device__ __forceinline__ void mma_tf32(float* c, const unsigned* a, const unsigned* b) {
    asm volatile(
        "mma.sync.aligned.m16n8k8.row.col.f32.tf32.tf32.f32 "
        "{%0,%1,%2,%3},{%4,%5,%6,%7},{%8,%9},{%0,%1,%2,%3};"
        : "+f"(c[0]), "+f"(c[1]), "+f"(c[2]), "+f"(c[3])
        : "r"(a[0]), "r"(a[1]), "r"(a[2]), "r"(a[3]), "r"(b[0]), "r"(b[1]));
}

template<int SOFTMAX>
__global__ __launch_bounds__(256) void tf32_gemm(
    const float* __restrict__ A, const float* __restrict__ B,
    const float* __restrict__ bias, float* __restrict__ C,
    int M, int N, int K, int bRowsPerBatch, int bMatStride)
{
    extern __shared__ float smem_f[];
    float* Asb[2] = { smem_f,        smem_f + 4608 };
    float* Bsb[2] = { smem_f + 9216, smem_f + 9216 + 4224 };

    const int tid  = threadIdx.x;
    const int lane = tid & 31;
    const int warp = tid >> 5;
    const int wr   = warp >> 2;
    const int wc   = warp & 3;
    const int row0 = blockIdx.y * 128;
    const int col0 = blockIdx.x * 128;

    const float* Bp = B;
    if (bRowsPerBatch) Bp += (size_t)(row0 / bRowsPerBatch) * (size_t)bMatStride;

    float c[4][4][4];
#pragma unroll
    for (int i = 0; i < 4; i++)
#pragma unroll
        for (int j = 0; j < 4; j++)
#pragma unroll
            for (int r = 0; r < 4; r++) c[i][j][r] = 0.f;

    const int g = lane >> 2;
    const int t = lane & 3;

    const int ar  = tid >> 3;
    const int akc = (tid & 7) * 4;
    const int bkr = tid >> 5;
    const int bnc = (tid & 31) * 4;

    auto loadTile = [&](int k0, int buf) {
        float* a = Asb[buf];
        float* b = Bsb[buf];
#pragma unroll
        for (int it = 0; it < 4; it++) {
            int r = ar + it * 32;
            cp16(&a[r * A_LDS + akc], A + (size_t)(row0 + r) * K + k0 + akc);
            int kr = bkr + it * 8;
            cp16(&b[kr * B_LDS + bnc], Bp + (size_t)(k0 + kr) * N + col0 + bnc);
        }
    };

    loadTile(0, 0);
    asm volatile("cp.async.commit_group;");

    const int ntiles = K >> 5;
    for (int kt = 0; kt < ntiles; kt++) {
        asm volatile("cp.async.wait_group 0;");
        __syncthreads();
        if (kt + 1 < ntiles) {
            loadTile((kt + 1) << 5, (kt + 1) & 1);
            asm volatile("cp.async.commit_group;");
        }
        const float* As = Asb[kt & 1];
        const float* Bs = Bsb[kt & 1];
#pragma unroll
        for (int ks = 0; ks < 4; ks++) {
            const int kb = ks * 8;
            unsigned a[4][4], b[4][2];
#pragma unroll
            for (int i = 0; i < 4; i++) {
                int rm = wr * 64 + i * 16 + g;
                a[i][0] = f2tf(As[rm * A_LDS + kb + t]);
                a[i][1] = f2tf(As[(rm + 8) * A_LDS + kb + t]);
                a[i][2] = f2tf(As[rm * A_LDS + kb + t + 4]);
                a[i][3] = f2tf(As[(rm + 8) * A_LDS + kb + t + 4]);
            }
#pragma unroll
            for (int j = 0; j < 4; j++) {
                int nb = wc * 32 + j * 8 + g;
                b[j][0] = f2tf(Bs[(kb + t) * B_LDS + nb]);
                b[j][1] = f2tf(Bs[(kb + t + 4) * B_LDS + nb]);
            }
#pragma unroll
            for (int i = 0; i < 4; i++)
#pragma unroll
                for (int j = 0; j < 4; j++)
                    mma_tf32(c[i][j], a[i], b[j]);
        }
        __syncthreads();   // protect smem buffers before next iteration's overwrite
    }

    if (SOFTMAX) {
        // stash logits(+bias) in smem, per-head 3-pass softmax (register-light)
        float* Ct = smem_f;
#pragma unroll
        for (int i = 0; i < 4; i++) {
            int rm = wr * 64 + i * 16 + g;
#pragma unroll
            for (int j = 0; j < 4; j++) {
                int cn = wc * 32 + j * 8 + t * 2;
                float b0 = bias[col0 + cn], b1 = bias[col0 + cn + 1];
                Ct[rm * CT_LDS + cn]           = c[i][j][0] + b0;
                Ct[rm * CT_LDS + cn + 1]       = c[i][j][1] + b1;
                Ct[(rm + 8) * CT_LDS + cn]     = c[i][j][2] + b0;
                Ct[(rm + 8) * CT_LDS + cn + 1] = c[i][j][3] + b1;
            }
        }
        __syncthreads();

        const int r  = tid & 127;
        const int hh = tid >> 7;
        const float4* rp = (const float4*)(Ct + r * CT_LDS + hh * 64);
        // pass 1: max
        float m = -1e30f;
#pragma unroll
        for (int j4 = 0; j4 < 16; j4++) {
            float4 v = rp[j4];
            m = fmaxf(m, fmaxf(fmaxf(v.x, v.y), fmaxf(v.z, v.w)));
        }
        // pass 2: sum of exp
        float s = 0.f;
#pragma unroll
        for (int j4 = 0; j4 < 16; j4++) {
            float4 v = rp[j4];
            s += __expf(v.x - m) + __expf(v.y - m) + __expf(v.z - m) + __expf(v.w - m);
        }
        const float is = 1.0f / s;
        // pass 3: write normalized
        float* wout = C + (size_t)(row0 + r) * N + col0 + hh * 64;
#pragma unroll
        for (int j4 = 0; j4 < 16; j4++) {
            float4 v = rp[j4];
            ((float4*)wout)[j4] = make_float4(__expf(v.x - m) * is, __expf(v.y - m) * is,
                                              __expf(v.z - m) * is, __expf(v.w - m) * is);
        }
    } else {
#pragma unroll
        for (int i = 0; i < 4; i++) {
            int rm = row0 + wr * 64 + i * 16 + g;
#pragma unroll
            for (int j = 0; j < 4; j++) {
                int cn = col0 + wc * 32 + j * 8 + t * 2;
                float b0 = bias[cn], b1 = bias[cn + 1];
                *(float2*)(C + (size_t)rm * N + cn) =
                    make_float2(c[i][j][0] + b0, c[i][j][1] + b1);
                *(float2*)(C + (size_t)(rm + 8) * N + cn) =
                    make_float2(c[i][j][2] + b0, c[i][j][3] + b1);
            }
        }
    }
}

// ============================================================
// Wcomb[c, h*64+g] = invt[h] * sum_d Wx[c, h*64+d] * Wslice[d, g]
// ============================================================
__global__ __launch_bounds__(512) void wcomb_kernel(
    const float* __restrict__ Wx, const float* __restrict__ Wslice,
    const float* __restrict__ temp, float* __restrict__ Wcomb)
{
    __shared__ float sWs[4096];
    __shared__ float sx[512];
    __shared__ float sit[8];
    const int tid = threadIdx.x;
    const int cr = blockIdx.x;
    for (int i = tid; i < 4096; i += 512) sWs[i] = Wslice[i];
    sx[tid] = Wx[(size_t)cr * 512 + tid];
    if (tid < 8) {
        float tv = temp[tid];
        sit[tid] = 1.0f / fminf(fmaxf(tv, 0.1f), 5.0f);
    }
    __syncthreads();
    const int h = tid >> 6, gg = tid & 63;
    float acc = 0.f;
#pragma unroll 8
    for (int d = 0; d < 64; d++)
        acc += sx[h*64 + d] * sWs[d*64 + gg];
    Wcomb[(size_t)cr * 512 + tid] = acc * sit[h];
}

__global__ void bcomb_kernel(
    const float* __restrict__ bx, const float* __restrict__ Wslice,
    const float* __restrict__ bslice, const float* __restrict__ temp,
    float* __restrict__ bcomb)
{
    const int tid = threadIdx.x;      // 512
    const int h = tid >> 6, gg = tid & 63;
    float tv = temp[h];
    float invt = 1.0f / fminf(fmaxf(tv, 0.1f), 5.0f);
    float acc = bslice[gg];
    for (int d = 0; d < 64; d++)
        acc += bx[h*64 + d] * Wslice[d*64 + gg];
    bcomb[tid] = acc * invt;
}

// ============================================================
// norm: two-stage deterministic column sums of w
// ============================================================
__global__ __launch_bounds__(512) void norm_part_kernel(
    const float* __restrict__ w, float* __restrict__ part)
{
    const int blk = blockIdx.x;
    const size_t r0 = (size_t)blk * 256;
    float s = 0.f;
    for (int r = 0; r < 256; r++)
        s += w[(r0 + r) * 512 + threadIdx.x];
    part[(size_t)blk * 512 + threadIdx.x] = s;
}

__global__ void norm_reduce_kernel(const float* __restrict__ part,
                                   float* __restrict__ norm)
{
    int e = blockIdx.x * 256 + threadIdx.x;
    int b = e >> 9, hg = e & 511;
    float s = 0.f;
    for (int c = 0; c < 128; c++)
        s += part[((size_t)(b * 128 + c)) * 512 + hg];
    norm[e] = s;
}

// ============================================================
// tokens partials
// ============================================================
__global__ __launch_bounds__(256) void tokpart_kernel(
    const float* __restrict__ fx, const float* __restrict__ w,
    float* __restrict__ part)
{
    __shared__ float ws[16][64];
    __shared__ float fs[16][64];
    const int chunk = blockIdx.x;
    const int bh = blockIdx.y;
    const int b = bh >> 3, h = bh & 7;
    const size_t rbase = (size_t)b * NN + (size_t)chunk * 1024;

    const int tid = threadIdx.x;
    const int ty = tid >> 4, tx = tid & 15;
    const int lr = tid >> 4, lc4 = tid & 15;

    float acc[4][4];
#pragma unroll
    for (int i = 0; i < 4; i++)
#pragma unroll
        for (int j = 0; j < 4; j++) acc[i][j] = 0.f;

    for (int kt = 0; kt < 1024; kt += 16) {
        size_t row = rbase + kt + lr;
        *(float4*)&ws[lr][lc4*4] = *(const float4*)(w  + row*512 + h*64 + lc4*4);
        *(float4*)&fs[lr][lc4*4] = *(const float4*)(fx + row*512 + h*64 + lc4*4);
        __syncthreads();
#pragma unroll
        for (int k = 0; k < 16; k++) {
            float4 a  = *(const float4*)&ws[k][ty*4];
            float4 bv = *(const float4*)&fs[k][tx*4];
            acc[0][0]+=a.x*bv.x; acc[0][1]+=a.x*bv.y; acc[0][2]+=a.x*bv.z; acc[0][3]+=a.x*bv.w;
            acc[1][0]+=a.y*bv.x; acc[1][1]+=a.y*bv.y; acc[1][2]+=a.y*bv.z; acc[1][3]+=a.y*bv.w;
            acc[2][0]+=a.z*bv.x; acc[2][1]+=a.z*bv.y; acc[2][2]+=a.z*bv.z; acc[2][3]+=a.z*bv.w;
            acc[3][0]+=a.w*bv.x; acc[3][1]+=a.w*bv.y; acc[3][2]+=a.w*bv.z; acc[3][3]+=a.w*bv.w;
        }
        __syncthreads();
    }

    float* p = part + ((size_t)bh * 32 + chunk) * 4096;
#pragma unroll
    for (int ig = 0; ig < 4; ig++) {
        float4 o = make_float4(acc[ig][0], acc[ig][1], acc[ig][2], acc[ig][3]);
        *(float4*)&p[(ty*4+ig)*64 + tx*4] = o;
    }
}

__global__ void tok_reduce_kernel(const float* __restrict__ part,
                                  float* __restrict__ tok)
{
    int idx = blockIdx.x * 256 + threadIdx.x;
    int bh = idx >> 12, gd = idx & 4095;
    float s = 0.f;
    for (int c = 0; c < 32; c++)
        s += part[((size_t)bh * 32 + c) * 4096 + gd];
    tok[idx] = s;
}

// ============================================================
// tiny attention over slice tokens
// ============================================================
__device__ __forceinline__ void row_gemm_sm(
    const float* __restrict__ xrow, int Kd,
    const float* __restrict__ W, const float* __restrict__ bias,
    float* __restrict__ outrow)
{
    float acc[64];
#pragma unroll
    for (int j = 0; j < 64; j++) acc[j] = bias[j];
    for (int d = 0; d < Kd; d++) {
        float xv = xrow[d];
        const float4* W4 = (const float4*)(W + (size_t)d * 64);
#pragma unroll
        for (int j4 = 0; j4 < 16; j4++) {
            float4 wv = W4[j4];
            acc[j4*4+0] += xv*wv.x; acc[j4*4+1] += xv*wv.y;
            acc[j4*4+2] += xv*wv.z; acc[j4*4+3] += xv*wv.w;
        }
    }
#pragma unroll
    for (int j = 0; j < 64; j++) outrow[j] = acc[j];
}

__device__ __forceinline__ void attn_row(
    const float* __restrict__ qrow, const float* __restrict__ Kt,
    const float* __restrict__ Vt, float* __restrict__ o)
{
    float qr[64];
#pragma unroll
    for (int d = 0; d < 64; d++) qr[d] = qrow[d];
    float sc[64];
    float m = -1e30f;
    for (int j = 0; j < 64; j++) {
        const float4* kr = (const float4*)(Kt + j * 64);
        float a = 0.f;
#pragma unroll
        for (int d4 = 0; d4 < 16; d4++) {
            float4 kv = kr[d4];
            a += qr[d4*4]*kv.x + qr[d4*4+1]*kv.y + qr[d4*4+2]*kv.z + qr[d4*4+3]*kv.w;
        }
        sc[j] = a * 0.125f;
        m = fmaxf(m, sc[j]);
    }
    float s = 0.f;
#pragma unroll
    for (int j = 0; j < 64; j++) { sc[j] = expf(sc[j] - m); s += sc[j]; }
    float is = 1.0f / s;
#pragma unroll
    for (int d = 0; d < 64; d++) o[d] = 0.f;
    for (int j = 0; j < 64; j++) {
        float p = sc[j] * is;
        const float4* vr = (const float4*)(Vt + j * 64);
#pragma unroll
        for (int d4 = 0; d4 < 16; d4++) {
            float4 vv = vr[d4];
            o[d4*4+0] += p*vv.x; o[d4*4+1] += p*vv.y;
            o[d4*4+2] += p*vv.z; o[d4*4+3] += p*vv.w;
        }
    }
}

__global__ void attn_kernel(
    const float* __restrict__ ctx,
    const float* __restrict__ Wq, const float* __restrict__ bq,
    const float* __restrict__ Wk, const float* __restrict__ bk,
    const float* __restrict__ Wv, const float* __restrict__ bv,
    const float* __restrict__ Wcq, const float* __restrict__ bcq,
    const float* __restrict__ Wck, const float* __restrict__ bck,
    const float* __restrict__ Wcv, const float* __restrict__ bcv,
    const float* __restrict__ smix,
    const float* __restrict__ tokens, const float* __restrict__ norm,
    float* __restrict__ ot)
{
    extern __shared__ float sm[];
    float* s_tok = sm;
    float* s_q   = sm + 4096;
    float* s_k   = sm + 2*4096;
    float* s_v   = sm + 3*4096;
    float* s_cq  = sm + 4*4096;

    const int bh = blockIdx.x;
    const int i  = threadIdx.x;

    float inv = 1.0f / (norm[bh*64 + i] + EPS);
#pragma unroll 4
    for (int d = 0; d < 64; d++)
        s_tok[i*64 + d] = tokens[((size_t)bh*64 + i)*64 + d] * inv;

    row_gemm_sm(&s_tok[i*64], 64, Wq,  bq,  &s_q[i*64]);
    row_gemm_sm(&s_tok[i*64], 64, Wk,  bk,  &s_k[i*64]);
    row_gemm_sm(&s_tok[i*64], 64, Wv,  bv,  &s_v[i*64]);
    row_gemm_sm(&s_tok[i*64], 64, Wcq, bcq, &s_cq[i*64]);
    __syncthreads();

    float sa[64];
    attn_row(&s_q[i*64], s_k, s_v, sa);
    __syncthreads();

#pragma unroll
    for (int d = 0; d < 64; d++) s_tok[i*64 + d] = sa[d];
    const float* crow = ctx + ((size_t)bh*64 + i) * 256;
    row_gemm_sm(crow, 256, Wck, bck, &s_q[i*64]);
    row_gemm_sm(crow, 256, Wcv, bcv, &s_k[i*64]);
    __syncthreads();

    float ca[64];
    attn_row(&s_cq[i*64], s_q, s_k, ca);

    float gmix = 1.0f / (1.0f + expf(-smix[0]));
#pragma unroll
    for (int d = 0; d < 64; d++)
        ot[((size_t)bh*64 + i)*64 + d] = gmix * s_tok[i*64 + d] + (1.0f - gmix) * ca[d];
}

// ============================================================
// M[b, h*64+g, c] = sum_d out_tok[b,h,g,d] * Wo[h*64+d, c]
// ============================================================
__global__ __launch_bounds__(256) void m_kernel(
    const float* __restrict__ Wo, const float* __restrict__ ot,
    float* __restrict__ M)
{
    __shared__ float s_ot[4096];
    __shared__ float s_wo[64 * 128];
    const int bh = blockIdx.y;
    const int h = bh & 7, b = bh >> 3;
    const int c0 = blockIdx.x * 128;
    const int tid = threadIdx.x;

    for (int idx = tid; idx < 1024; idx += 256)
        ((float4*)s_ot)[idx] = ((const float4*)(ot + (size_t)bh * 4096))[idx];
    for (int idx = tid; idx < 2048; idx += 256) {
        int d = idx >> 5;
        int c4 = idx & 31;
        ((float4*)s_wo)[idx] = *(const float4*)(Wo + (size_t)(h*64 + d)*512 + c0 + c4*4);
    }
    __syncthreads();

    const int g0 = (tid >> 3) * 2;
    const int ct = (tid & 7) * 16;
    float acc[2][16];
#pragma unroll
    for (int g = 0; g < 2; g++)
#pragma unroll
        for (int c = 0; c < 16; c++) acc[g][c] = 0.f;

    for (int d = 0; d < 64; d++) {
        float a0 = s_ot[g0*64 + d];
        float a1 = s_ot[(g0+1)*64 + d];
#pragma unroll
        for (int c4 = 0; c4 < 4; c4++) {
            float4 wv = *(const float4*)&s_wo[d*128 + ct + c4*4];
            acc[0][c4*4+0]+=a0*wv.x; acc[0][c4*4+1]+=a0*wv.y; acc[0][c4*4+2]+=a0*wv.z; acc[0][c4*4+3]+=a0*wv.w;
            acc[1][c4*4+0]+=a1*wv.x; acc[1][c4*4+1]+=a1*wv.y; acc[1][c4*4+2]+=a1*wv.z; acc[1][c4*4+3]+=a1*wv.w;
        }
    }

#pragma unroll
    for (int g = 0; g < 2; g++) {
        float* Mr = M + (size_t)b * 262144 + (size_t)(h*64 + g0 + g) * 512 + c0 + ct;
#pragma unroll
        for (int c4 = 0; c4 < 4; c4++)
            *(float4*)(Mr + c4*4) = make_float4(acc[g][c4*4], acc[g][c4*4+1], acc[g][c4*4+2], acc[g][c4*4+3]);
    }
}

// ============================================================
// host launcher
// ============================================================
extern "C" void kernel_launch(void* const* d_in, const int* in_sizes, int n_in,
                              void* d_out, int out_size)
{
    const float* x      = (const float*)d_in[0];
    const float* ctx    = (const float*)d_in[1];
    const float* Wx     = (const float*)d_in[2];
    const float* bx     = (const float*)d_in[3];
    const float* Wfx    = (const float*)d_in[4];
    const float* bfx    = (const float*)d_in[5];
    const float* Wslice = (const float*)d_in[6];
    const float* bslice = (const float*)d_in[7];
    const float* temp   = (const float*)d_in[8];
    const float* Wq     = (const float*)d_in[9];
    const float* bq     = (const float*)d_in[10];
    const float* Wk     = (const float*)d_in[11];
    const float* bk     = (const float*)d_in[12];
    const float* Wv     = (const float*)d_in[13];
    const float* bv     = (const float*)d_in[14];
    const float* Wcq    = (const float*)d_in[15];
    const float* bcq    = (const float*)d_in[16];
    const float* Wck    = (const float*)d_in[17];
    const float* bck    = (const float*)d_in[18];
    const float* Wcv    = (const float*)d_in[19];
    const float* bcv    = (const float*)d_in[20];
    const float* smix   = (const float*)d_in[21];
    const float* Wo     = (const float*)d_in[22];
    const float* bo     = (const float*)d_in[23];
    float* out = (float*)d_out;

    void *p;
    cudaGetSymbolAddress(&p, g_fxmid); float* fxmid = (float*)p;
    cudaGetSymbolAddress(&p, g_w);     float* w     = (float*)p;
    cudaGetSymbolAddress(&p, g_npart); float* npart = (float*)p;
    cudaGetSymbolAddress(&p, g_norm);  float* norm  = (float*)p;
    cudaGetSymbolAddress(&p, g_tpart); float* tpart = (float*)p;
    cudaGetSymbolAddress(&p, g_tok);   float* tok   = (float*)p;
    cudaGetSymbolAddress(&p, g_ot);    float* ot    = (float*)p;
    cudaGetSymbolAddress(&p, g_M);     float* Mm    = (float*)p;
    cudaGetSymbolAddress(&p, g_Wcomb); float* Wcomb = (float*)p;
    cudaGetSymbolAddress(&p, g_bcomb); float* bcomb = (float*)p;

    cudaFuncSetAttribute(tf32_gemm<0>, cudaFuncAttributeMaxDynamicSharedMemorySize, GEMM_SMEM);
    cudaFuncSetAttribute(tf32_gemm<1>, cudaFuncAttributeMaxDynamicSharedMemorySize, GEMM_SMEM);
    cudaFuncSetAttribute(attn_kernel, cudaFuncAttributeMaxDynamicSharedMemorySize, 5*4096*4);

    dim3 gemmGrid(4, 512);

    // 0: fold Wx@Wslice (+temp) -> Wcomb, bcomb
    wcomb_kernel<<<512, 512>>>(Wx, Wslice, temp, Wcomb);
    bcomb_kernel<<<1, 512>>>(bx, Wslice, bslice, temp, bcomb);
    // 1: logits GEMM + fused softmax -> w
    tf32_gemm<1><<<gemmGrid, 256, GEMM_SMEM>>>(x, Wcomb, bcomb, w, ROWS, INNER, CC, 0, 0);
    // 2: fx projection
    tf32_gemm<0><<<gemmGrid, 256, GEMM_SMEM>>>(x, Wfx, bfx, fxmid, ROWS, INNER, CC, 0, 0);
    // 3,4: norm (deterministic two-stage)
    norm_part_kernel<<<256, 512>>>(w, npart);
    norm_reduce_kernel<<<4, 256>>>(npart, norm);
    // 5,6: tokens = w^T @ fx
    tokpart_kernel<<<dim3(32, 16), 256>>>(fxmid, w, tpart);
    tok_reduce_kernel<<<256, 256>>>(tpart, tok);
    // 7: tiny attention -> out_tok
    attn_kernel<<<16, 64, 5*4096*4>>>(ctx, Wq, bq, Wk, bk, Wv, bv,
                                      Wcq, bcq, Wck, bck, Wcv, bcv,
                                      smix, tok, norm, ot);
    // 8: fold out_tok @ Wo -> M
    m_kernel<<<dim3(4, 16), 256>>>(Wo, ot, Mm);
    // 9: out = w @ M[b] + bo
    tf32_gemm<0><<<gemmGrid, 256, GEMM_SMEM>>>(w, Mm, bo, out, ROWS, CC, INNER, NN, 512*512);
}

// round 5
// speedup vs baseline: 1.7137x; 1.7137x over previous
#include <cuda_runtime.h>
#include <math.h>

// ---------------- problem constants ----------------
#define BB 2
#define NN 32768
#define CC 512
#define HH 8
#define DH 64
#define GG 64
#define CD 256
#define ROWS (BB*NN)          // 65536
#define INNER (HH*DH)         // 512
#define EPS 1e-5f
#define TOK_CHUNKS 64         // 512 rows per chunk

// ---------------- scratch ----------------
__device__ float g_xr   [ROWS * CC];        // tf32-rounded x
__device__ float g_fxmid[ROWS * INNER];
__device__ float g_w    [ROWS * INNER];
__device__ float g_npart[256 * 512];
__device__ float g_norm [BB * HH * GG];
__device__ float g_tpart[16 * TOK_CHUNKS * 4096];
__device__ float g_tok  [16 * 4096];
__device__ float g_ot   [16 * 4096];
__device__ float g_M    [BB * 512 * 512];
__device__ float g_Wcomb[512 * 512];
__device__ float g_bcomb[512];
__device__ float g_Wfxr [512 * 512];

// ---------------- helpers ----------------
__device__ __forceinline__ void cp16(void* dst, const void* src) {
    unsigned d = (unsigned)__cvta_generic_to_shared(dst);
    asm volatile("cp.async.cg.shared.global [%0], [%1], 16;" :: "r"(d), "l"(src));
}
__device__ __forceinline__ float tf32r(float f) {
    unsigned u;
    asm("cvt.rna.tf32.f32 %0, %1;" : "=r"(u) : "f"(f));
    return __uint_as_float(u);
}
__device__ __forceinline__ void mma_tf32(float* c, const unsigned* a, const unsigned* b) {
    asm volatile(
        "mma.sync.aligned.m16n8k8.row.col.f32.tf32.tf32.f32 "
        "{%0,%1,%2,%3},{%4,%5,%6,%7},{%8,%9},{%0,%1,%2,%3};"
        : "+f"(c[0]), "+f"(c[1]), "+f"(c[2]), "+f"(c[3])
        : "r"(a[0]), "r"(a[1]), "r"(a[2]), "r"(a[3]), "r"(b[0]), "r"(b[1]));
}

// ============================================================
// elementwise tf32 rounding (float4 grid-stride)
// ============================================================
__global__ void round_tf32_kernel(const float* __restrict__ in,
                                  float* __restrict__ out, int n4)
{
    int idx = blockIdx.x * blockDim.x + threadIdx.x;
    int stride = gridDim.x * blockDim.x;
    for (; idx < n4; idx += stride) {
        float4 v = ((const float4*)in)[idx];
        v.x = tf32r(v.x); v.y = tf32r(v.y); v.z = tf32r(v.z); v.w = tf32r(v.w);
        ((float4*)out)[idx] = v;
    }
}

// ============================================================
// TF32 GEMM, 128x128x32 tile, 8 warps, double-buffered cp.async.
// Inputs assumed pre-rounded to tf32 -> raw-bit mainloop (fast).
// SOFTMAX=1: per-head softmax epilogue, output tf32-rounded.
// ============================================================
#define A_LDS 36
#define B_LDS 132
#define CT_LDS 132
#define GEMM_SMEM 70656

template<int SOFTMAX>
__global__ __launch_bounds__(256, 2) void tf32_gemm(
    const float* __restrict__ A, const float* __restrict__ B,
    const float* __restrict__ bias, float* __restrict__ C,
    int M, int N, int K, int bRowsPerBatch, int bMatStride)
{
    extern __shared__ float smem_f[];
    float* Asb[2] = { smem_f,        smem_f + 4608 };
    float* Bsb[2] = { smem_f + 9216, smem_f + 9216 + 4224 };

    const int tid  = threadIdx.x;
    const int lane = tid & 31;
    const int warp = tid >> 5;
    const int wr   = warp >> 2;
    const int wc   = warp & 3;
    const int row0 = blockIdx.y * 128;
    const int col0 = blockIdx.x * 128;

    const float* Bp = B;
    if (bRowsPerBatch) Bp += (size_t)(row0 / bRowsPerBatch) * (size_t)bMatStride;

    float c[4][4][4];
#pragma unroll
    for (int i = 0; i < 4; i++)
#pragma unroll
        for (int j = 0; j < 4; j++)
#pragma unroll
            for (int r = 0; r < 4; r++) c[i][j][r] = 0.f;

    const int g = lane >> 2;
    const int t = lane & 3;

    const int ar  = tid >> 3;
    const int akc = (tid & 7) * 4;
    const int bkr = tid >> 5;
    const int bnc = (tid & 31) * 4;

    auto loadTile = [&](int k0, int buf) {
        float* a = Asb[buf];
        float* b = Bsb[buf];
#pragma unroll
        for (int it = 0; it < 4; it++) {
            int r = ar + it * 32;
            cp16(&a[r * A_LDS + akc], A + (size_t)(row0 + r) * K + k0 + akc);
            int kr = bkr + it * 8;
            cp16(&b[kr * B_LDS + bnc], Bp + (size_t)(k0 + kr) * N + col0 + bnc);
        }
    };

    loadTile(0, 0);
    asm volatile("cp.async.commit_group;");

    const int ntiles = K >> 5;
    for (int kt = 0; kt < ntiles; kt++) {
        asm volatile("cp.async.wait_group 0;");
        __syncthreads();
        if (kt + 1 < ntiles) {
            loadTile((kt + 1) << 5, (kt + 1) & 1);
            asm volatile("cp.async.commit_group;");
        }
        const float* As = Asb[kt & 1];
        const float* Bs = Bsb[kt & 1];
#pragma unroll
        for (int ks = 0; ks < 4; ks++) {
            const int kb = ks * 8;
            unsigned a[4][4], b[4][2];
#pragma unroll
            for (int i = 0; i < 4; i++) {
                int rm = wr * 64 + i * 16 + g;
                a[i][0] = __float_as_uint(As[rm * A_LDS + kb + t]);
                a[i][1] = __float_as_uint(As[(rm + 8) * A_LDS + kb + t]);
                a[i][2] = __float_as_uint(As[rm * A_LDS + kb + t + 4]);
                a[i][3] = __float_as_uint(As[(rm + 8) * A_LDS + kb + t + 4]);
            }
#pragma unroll
            for (int j = 0; j < 4; j++) {
                int nb = wc * 32 + j * 8 + g;
                b[j][0] = __float_as_uint(Bs[(kb + t) * B_LDS + nb]);
                b[j][1] = __float_as_uint(Bs[(kb + t + 4) * B_LDS + nb]);
            }
#pragma unroll
            for (int i = 0; i < 4; i++)
#pragma unroll
                for (int j = 0; j < 4; j++)
                    mma_tf32(c[i][j], a[i], b[j]);
        }
        __syncthreads();
    }

    if (SOFTMAX) {
        float* Ct = smem_f;
#pragma unroll
        for (int i = 0; i < 4; i++) {
            int rm = wr * 64 + i * 16 + g;
#pragma unroll
            for (int j = 0; j < 4; j++) {
                int cn = wc * 32 + j * 8 + t * 2;
                float b0 = bias[col0 + cn], b1 = bias[col0 + cn + 1];
                Ct[rm * CT_LDS + cn]           = c[i][j][0] + b0;
                Ct[rm * CT_LDS + cn + 1]       = c[i][j][1] + b1;
                Ct[(rm + 8) * CT_LDS + cn]     = c[i][j][2] + b0;
                Ct[(rm + 8) * CT_LDS + cn + 1] = c[i][j][3] + b1;
            }
        }
        __syncthreads();

        const int r  = tid & 127;
        const int hh = tid >> 7;
        const float4* rp = (const float4*)(Ct + r * CT_LDS + hh * 64);
        float m = -1e30f;
#pragma unroll
        for (int j4 = 0; j4 < 16; j4++) {
            float4 v = rp[j4];
            m = fmaxf(m, fmaxf(fmaxf(v.x, v.y), fmaxf(v.z, v.w)));
        }
        float s = 0.f;
#pragma unroll
        for (int j4 = 0; j4 < 16; j4++) {
            float4 v = rp[j4];
            s += __expf(v.x - m) + __expf(v.y - m) + __expf(v.z - m) + __expf(v.w - m);
        }
        const float is = 1.0f / s;
        float* wout = C + (size_t)(row0 + r) * N + col0 + hh * 64;
#pragma unroll
        for (int j4 = 0; j4 < 16; j4++) {
            float4 v = rp[j4];
            ((float4*)wout)[j4] = make_float4(
                tf32r(__expf(v.x - m) * is), tf32r(__expf(v.y - m) * is),
                tf32r(__expf(v.z - m) * is), tf32r(__expf(v.w - m) * is));
        }
    } else {
#pragma unroll
        for (int i = 0; i < 4; i++) {
            int rm = row0 + wr * 64 + i * 16 + g;
#pragma unroll
            for (int j = 0; j < 4; j++) {
                int cn = col0 + wc * 32 + j * 8 + t * 2;
                float b0 = bias[cn], b1 = bias[cn + 1];
                *(float2*)(C + (size_t)rm * N + cn) =
                    make_float2(c[i][j][0] + b0, c[i][j][1] + b1);
                *(float2*)(C + (size_t)(rm + 8) * N + cn) =
                    make_float2(c[i][j][2] + b0, c[i][j][3] + b1);
            }
        }
    }
}

// ============================================================
// Wcomb (tf32-rounded) + bcomb
// ============================================================
__global__ __launch_bounds__(512) void wcomb_kernel(
    const float* __restrict__ Wx, const float* __restrict__ Wslice,
    const float* __restrict__ temp, float* __restrict__ Wcomb)
{
    __shared__ float sWs[4096];
    __shared__ float sx[512];
    __shared__ float sit[8];
    const int tid = threadIdx.x;
    const int cr = blockIdx.x;
    for (int i = tid; i < 4096; i += 512) sWs[i] = Wslice[i];
    sx[tid] = Wx[(size_t)cr * 512 + tid];
    if (tid < 8) {
        float tv = temp[tid];
        sit[tid] = 1.0f / fminf(fmaxf(tv, 0.1f), 5.0f);
    }
    __syncthreads();
    const int h = tid >> 6, gg = tid & 63;
    float acc = 0.f;
#pragma unroll 8
    for (int d = 0; d < 64; d++)
        acc += sx[h*64 + d] * sWs[d*64 + gg];
    Wcomb[(size_t)cr * 512 + tid] = tf32r(acc * sit[h]);
}

__global__ void bcomb_kernel(
    const float* __restrict__ bx, const float* __restrict__ Wslice,
    const float* __restrict__ bslice, const float* __restrict__ temp,
    float* __restrict__ bcomb)
{
    const int tid = threadIdx.x;
    const int h = tid >> 6, gg = tid & 63;
    float tv = temp[h];
    float invt = 1.0f / fminf(fmaxf(tv, 0.1f), 5.0f);
    float acc = bslice[gg];
    for (int d = 0; d < 64; d++)
        acc += bx[h*64 + d] * Wslice[d*64 + gg];
    bcomb[tid] = acc * invt;
}

// ============================================================
// norm: two-stage deterministic column sums of w
// ============================================================
__global__ __launch_bounds__(512) void norm_part_kernel(
    const float* __restrict__ w, float* __restrict__ part)
{
    const int blk = blockIdx.x;
    const size_t r0 = (size_t)blk * 256;
    float s = 0.f;
    for (int r = 0; r < 256; r++)
        s += w[(r0 + r) * 512 + threadIdx.x];
    part[(size_t)blk * 512 + threadIdx.x] = s;
}

__global__ void norm_reduce_kernel(const float* __restrict__ part,
                                   float* __restrict__ norm)
{
    int e = blockIdx.x * 256 + threadIdx.x;
    int b = e >> 9, hg = e & 511;
    float s = 0.f;
    for (int c = 0; c < 128; c++)
        s += part[((size_t)(b * 128 + c)) * 512 + hg];
    norm[e] = s;
}

// ============================================================
// tokens partials: 512-row chunks, 32-row double-buffered tiles
// grid (TOK_CHUNKS, 16 bh), 256 threads
// ============================================================
__global__ __launch_bounds__(256) void tokpart_kernel(
    const float* __restrict__ fx, const float* __restrict__ w,
    float* __restrict__ part)
{
    __shared__ float ws[2][32][64];
    __shared__ float fs[2][32][64];
    const int chunk = blockIdx.x;
    const int bh = blockIdx.y;
    const int b = bh >> 3, h = bh & 7;
    const size_t rbase = (size_t)b * NN + (size_t)chunk * 512;

    const int tid = threadIdx.x;
    const int ty = tid >> 4, tx = tid & 15;

    float acc[4][4];
#pragma unroll
    for (int i = 0; i < 4; i++)
#pragma unroll
        for (int j = 0; j < 4; j++) acc[i][j] = 0.f;

    auto loadTile = [&](int kt, int buf) {
#pragma unroll
        for (int it = 0; it < 2; it++) {
            int s = tid + it * 256;            // 0..511
            int r = s >> 4;                    // 0..31
            int c4 = (s & 15) * 4;             // 0..60
            size_t row = rbase + (size_t)kt * 32 + r;
            cp16(&ws[buf][r][c4], w  + row * 512 + h * 64 + c4);
            cp16(&fs[buf][r][c4], fx + row * 512 + h * 64 + c4);
        }
    };

    loadTile(0, 0);
    asm volatile("cp.async.commit_group;");

    for (int kt = 0; kt < 16; kt++) {
        asm volatile("cp.async.wait_group 0;");
        __syncthreads();
        if (kt + 1 < 16) {
            loadTile(kt + 1, (kt + 1) & 1);
            asm volatile("cp.async.commit_group;");
        }
        const int buf = kt & 1;
#pragma unroll
        for (int k = 0; k < 32; k++) {
            float4 a  = *(const float4*)&ws[buf][k][ty*4];
            float4 bv = *(const float4*)&fs[buf][k][tx*4];
            acc[0][0]+=a.x*bv.x; acc[0][1]+=a.x*bv.y; acc[0][2]+=a.x*bv.z; acc[0][3]+=a.x*bv.w;
            acc[1][0]+=a.y*bv.x; acc[1][1]+=a.y*bv.y; acc[1][2]+=a.y*bv.z; acc[1][3]+=a.y*bv.w;
            acc[2][0]+=a.z*bv.x; acc[2][1]+=a.z*bv.y; acc[2][2]+=a.z*bv.z; acc[2][3]+=a.z*bv.w;
            acc[3][0]+=a.w*bv.x; acc[3][1]+=a.w*bv.y; acc[3][2]+=a.w*bv.z; acc[3][3]+=a.w*bv.w;
        }
        __syncthreads();
    }

    float* p = part + ((size_t)bh * TOK_CHUNKS + chunk) * 4096;
#pragma unroll
    for (int ig = 0; ig < 4; ig++) {
        float4 o = make_float4(acc[ig][0], acc[ig][1], acc[ig][2], acc[ig][3]);
        *(float4*)&p[(ty*4+ig)*64 + tx*4] = o;
    }
}

__global__ void tok_reduce_kernel(const float* __restrict__ part,
                                  float* __restrict__ tok)
{
    int idx = blockIdx.x * 256 + threadIdx.x;
    int bh = idx >> 12, gd = idx & 4095;
    float s = 0.f;
    for (int c = 0; c < TOK_CHUNKS; c++)
        s += part[((size_t)bh * TOK_CHUNKS + c) * 4096 + gd];
    tok[idx] = s;
}

// ============================================================
// tiny attention: 16 blocks x 256 threads, task-parallel phases
// ============================================================
template<int NC>
__device__ __forceinline__ void row_gemm_cols(
    const float* __restrict__ xrow, int Kd,
    const float* __restrict__ W, const float* __restrict__ bias,
    float* __restrict__ outp, int c0)
{
    float acc[NC];
#pragma unroll
    for (int j = 0; j < NC; j++) acc[j] = bias[c0 + j];
    for (int d = 0; d < Kd; d++) {
        float xv = xrow[d];
        const float4* W4 = (const float4*)(W + (size_t)d * 64 + c0);
#pragma unroll
        for (int j4 = 0; j4 < NC/4; j4++) {
            float4 wv = W4[j4];
            acc[j4*4+0] += xv*wv.x; acc[j4*4+1] += xv*wv.y;
            acc[j4*4+2] += xv*wv.z; acc[j4*4+3] += xv*wv.w;
        }
    }
#pragma unroll
    for (int j = 0; j < NC; j++) outp[c0 + j] = acc[j];
}

__device__ __forceinline__ void attn_row(
    const float* __restrict__ qrow, const float* __restrict__ Kt,
    const float* __restrict__ Vt, float* __restrict__ o)
{
    float qr[64];
#pragma unroll
    for (int d = 0; d < 64; d++) qr[d] = qrow[d];
    float sc[64];
    float m = -1e30f;
    for (int j = 0; j < 64; j++) {
        const float4* kr = (const float4*)(Kt + j * 64);
        float a = 0.f;
#pragma unroll
        for (int d4 = 0; d4 < 16; d4++) {
            float4 kv = kr[d4];
            a += qr[d4*4]*kv.x + qr[d4*4+1]*kv.y + qr[d4*4+2]*kv.z + qr[d4*4+3]*kv.w;
        }
        sc[j] = a * 0.125f;
        m = fmaxf(m, sc[j]);
    }
    float s = 0.f;
#pragma unroll
    for (int j = 0; j < 64; j++) { sc[j] = expf(sc[j] - m); s += sc[j]; }
    float is = 1.0f / s;
#pragma unroll
    for (int d = 0; d < 64; d++) o[d] = 0.f;
    for (int j = 0; j < 64; j++) {
        float p = sc[j] * is;
        const float4* vr = (const float4*)(Vt + j * 64);
#pragma unroll
        for (int d4 = 0; d4 < 16; d4++) {
            float4 vv = vr[d4];
            o[d4*4+0] += p*vv.x; o[d4*4+1] += p*vv.y;
            o[d4*4+2] += p*vv.z; o[d4*4+3] += p*vv.w;
        }
    }
}

__global__ __launch_bounds__(256) void attn_kernel(
    const float* __restrict__ ctx,
    const float* __restrict__ Wq, const float* __restrict__ bq,
    const float* __restrict__ Wk, const float* __restrict__ bk,
    const float* __restrict__ Wv, const float* __restrict__ bv,
    const float* __restrict__ Wcq, const float* __restrict__ bcq,
    const float* __restrict__ Wck, const float* __restrict__ bck,
    const float* __restrict__ Wcv, const float* __restrict__ bcv,
    const float* __restrict__ smix,
    const float* __restrict__ tokens, const float* __restrict__ norm,
    float* __restrict__ ot)
{
    extern __shared__ float sm[];
    float* s_tok = sm;              // later: sa result
    float* s_q   = sm + 4096;
    float* s_k   = sm + 2*4096;
    float* s_v   = sm + 3*4096;
    float* s_cq  = sm + 4*4096;     // later: ca result
    float* s_ck  = sm + 5*4096;
    float* s_cv  = sm + 6*4096;

    const int bh = blockIdx.x;
    const int tid = threadIdx.x;

    // phase 0: normalized tokens -> smem
    for (int idx = tid; idx < 4096; idx += 256) {
        int row = idx >> 6;
        float inv = 1.0f / (norm[bh*64 + row] + EPS);
        s_tok[idx] = tokens[(size_t)bh*4096 + idx] * inv;
    }
    __syncthreads();

    // phase 1: q/k/v/cq projections, one per 64-thread group
    {
        const int pid = tid >> 6;
        const int i   = tid & 63;
        const float* W; const float* bb; float* dst;
        if (pid == 0)      { W = Wq;  bb = bq;  dst = s_q;  }
        else if (pid == 1) { W = Wk;  bb = bk;  dst = s_k;  }
        else if (pid == 2) { W = Wv;  bb = bv;  dst = s_v;  }
        else               { W = Wcq; bb = bcq; dst = s_cq; }
        row_gemm_cols<64>(&s_tok[i*64], 64, W, bb, &dst[i*64], 0);
    }
    // phase 1b: ck / cv from context (Kd=256), 2 threads per row
    {
        const int mat = tid >> 7;          // 0: ck, 1: cv
        const int sub = tid & 127;
        const int i   = sub >> 1;          // row 0..63
        const int c0  = (sub & 1) * 32;
        const float* crow = ctx + ((size_t)bh*64 + i) * 256;
        if (mat == 0) row_gemm_cols<32>(crow, 256, Wck, bck, &s_ck[i*64], c0);
        else          row_gemm_cols<32>(crow, 256, Wcv, bcv, &s_cv[i*64], c0);
    }
    __syncthreads();

    // phase 2: self-attn rows (threads 0-63) || cross-attn rows (64-127)
    if (tid < 64) {
        float o[64];
        attn_row(&s_q[tid*64], s_k, s_v, o);
#pragma unroll
        for (int d = 0; d < 64; d++) s_tok[tid*64 + d] = o[d];
    } else if (tid < 128) {
        const int i = tid - 64;
        float o[64];
        attn_row(&s_cq[i*64], s_ck, s_cv, o);
#pragma unroll
        for (int d = 0; d < 64; d++) s_cq[i*64 + d] = o[d];
    }
    __syncthreads();

    // phase 3: gate-mix and write out_tok
    const float gmix = 1.0f / (1.0f + expf(-smix[0]));
    for (int idx = tid; idx < 4096; idx += 256)
        ot[(size_t)bh*4096 + idx] = gmix * s_tok[idx] + (1.0f - gmix) * s_cq[idx];
}

// ============================================================
// M[b, h*64+g, c] = sum_d out_tok * Wo  (tf32-rounded output)
// ============================================================
__global__ __launch_bounds__(256) void m_kernel(
    const float* __restrict__ Wo, const float* __restrict__ ot,
    float* __restrict__ M)
{
    __shared__ float s_ot[4096];
    __shared__ float s_wo[64 * 128];
    const int bh = blockIdx.y;
    const int h = bh & 7, b = bh >> 3;
    const int c0 = blockIdx.x * 128;
    const int tid = threadIdx.x;

    for (int idx = tid; idx < 1024; idx += 256)
        ((float4*)s_ot)[idx] = ((const float4*)(ot + (size_t)bh * 4096))[idx];
    for (int idx = tid; idx < 2048; idx += 256) {
        int d = idx >> 5;
        int c4 = idx & 31;
        ((float4*)s_wo)[idx] = *(const float4*)(Wo + (size_t)(h*64 + d)*512 + c0 + c4*4);
    }
    __syncthreads();

    const int g0 = (tid >> 3) * 2;
    const int ct = (tid & 7) * 16;
    float acc[2][16];
#pragma unroll
    for (int g = 0; g < 2; g++)
#pragma unroll
        for (int c = 0; c < 16; c++) acc[g][c] = 0.f;

    for (int d = 0; d < 64; d++) {
        float a0 = s_ot[g0*64 + d];
        float a1 = s_ot[(g0+1)*64 + d];
#pragma unroll
        for (int c4 = 0; c4 < 4; c4++) {
            float4 wv = *(const float4*)&s_wo[d*128 + ct + c4*4];
            acc[0][c4*4+0]+=a0*wv.x; acc[0][c4*4+1]+=a0*wv.y; acc[0][c4*4+2]+=a0*wv.z; acc[0][c4*4+3]+=a0*wv.w;
            acc[1][c4*4+0]+=a1*wv.x; acc[1][c4*4+1]+=a1*wv.y; acc[1][c4*4+2]+=a1*wv.z; acc[1][c4*4+3]+=a1*wv.w;
        }
    }

#pragma unroll
    for (int g = 0; g < 2; g++) {
        float* Mr = M + (size_t)b * 262144 + (size_t)(h*64 + g0 + g) * 512 + c0 + ct;
#pragma unroll
        for (int c4 = 0; c4 < 4; c4++)
            *(float4*)(Mr + c4*4) = make_float4(
                tf32r(acc[g][c4*4]), tf32r(acc[g][c4*4+1]),
                tf32r(acc[g][c4*4+2]), tf32r(acc[g][c4*4+3]));
    }
}

// ============================================================
// host launcher
// ============================================================
extern "C" void kernel_launch(void* const* d_in, const int* in_sizes, int n_in,
                              void* d_out, int out_size)
{
    const float* x      = (const float*)d_in[0];
    const float* ctx    = (const float*)d_in[1];
    const float* Wx     = (const float*)d_in[2];
    const float* bx     = (const float*)d_in[3];
    const float* Wfx    = (const float*)d_in[4];
    const float* bfx    = (const float*)d_in[5];
    const float* Wslice = (const float*)d_in[6];
    const float* bslice = (const float*)d_in[7];
    const float* temp   = (const float*)d_in[8];
    const float* Wq     = (const float*)d_in[9];
    const float* bq     = (const float*)d_in[10];
    const float* Wk     = (const float*)d_in[11];
    const float* bk     = (const float*)d_in[12];
    const float* Wv     = (const float*)d_in[13];
    const float* bv     = (const float*)d_in[14];
    const float* Wcq    = (const float*)d_in[15];
    const float* bcq    = (const float*)d_in[16];
    const float* Wck    = (const float*)d_in[17];
    const float* bck    = (const float*)d_in[18];
    const float* Wcv    = (const float*)d_in[19];
    const float* bcv    = (const float*)d_in[20];
    const float* smix   = (const float*)d_in[21];
    const float* Wo     = (const float*)d_in[22];
    const float* bo     = (const float*)d_in[23];
    float* out = (float*)d_out;

    void *p;
    cudaGetSymbolAddress(&p, g_xr);    float* xr    = (float*)p;
    cudaGetSymbolAddress(&p, g_fxmid); float* fxmid = (float*)p;
    cudaGetSymbolAddress(&p, g_w);     float* w     = (float*)p;
    cudaGetSymbolAddress(&p, g_npart); float* npart = (float*)p;
    cudaGetSymbolAddress(&p, g_norm);  float* norm  = (float*)p;
    cudaGetSymbolAddress(&p, g_tpart); float* tpart = (float*)p;
    cudaGetSymbolAddress(&p, g_tok);   float* tok   = (float*)p;
    cudaGetSymbolAddress(&p, g_ot);    float* ot    = (float*)p;
    cudaGetSymbolAddress(&p, g_M);     float* Mm    = (float*)p;
    cudaGetSymbolAddress(&p, g_Wcomb); float* Wcomb = (float*)p;
    cudaGetSymbolAddress(&p, g_bcomb); float* bcomb = (float*)p;
    cudaGetSymbolAddress(&p, g_Wfxr);  float* Wfxr  = (float*)p;

    cudaFuncSetAttribute(tf32_gemm<0>, cudaFuncAttributeMaxDynamicSharedMemorySize, GEMM_SMEM);
    cudaFuncSetAttribute(tf32_gemm<1>, cudaFuncAttributeMaxDynamicSharedMemorySize, GEMM_SMEM);
    cudaFuncSetAttribute(attn_kernel, cudaFuncAttributeMaxDynamicSharedMemorySize, 7*4096*4);

    dim3 gemmGrid(4, 512);

    // 0: tf32 pre-rounding of GEMM inputs
    round_tf32_kernel<<<4096, 256>>>(x, xr, ROWS*CC/4);
    round_tf32_kernel<<<256, 256>>>(Wfx, Wfxr, 512*512/4);
    wcomb_kernel<<<512, 512>>>(Wx, Wslice, temp, Wcomb);
    bcomb_kernel<<<1, 512>>>(bx, Wslice, bslice, temp, bcomb);
    // 1: logits GEMM + fused softmax -> w (tf32-rounded)
    tf32_gemm<1><<<gemmGrid, 256, GEMM_SMEM>>>(xr, Wcomb, bcomb, w, ROWS, INNER, CC, 0, 0);
    // 2: fx projection
    tf32_gemm<0><<<gemmGrid, 256, GEMM_SMEM>>>(xr, Wfxr, bfx, fxmid, ROWS, INNER, CC, 0, 0);
    // 3,4: norm
    norm_part_kernel<<<256, 512>>>(w, npart);
    norm_reduce_kernel<<<4, 256>>>(npart, norm);
    // 5,6: tokens = w^T @ fx
    tokpart_kernel<<<dim3(TOK_CHUNKS, 16), 256>>>(fxmid, w, tpart);
    tok_reduce_kernel<<<256, 256>>>(tpart, tok);
    // 7: tiny attention -> out_tok
    attn_kernel<<<16, 256, 7*4096*4>>>(ctx, Wq, bq, Wk, bk, Wv, bv,
                                       Wcq, bcq, Wck, bck, Wcv, bcv,
                                       smix, tok, norm, ot);
    // 8: fold out_tok @ Wo -> M (tf32-rounded)
    m_kernel<<<dim3(4, 16), 256>>>(Wo, ot, Mm);
    // 9: out = w @ M[b] + bo
    tf32_gemm<0><<<gemmGrid, 256, GEMM_SMEM>>>(w, Mm, bo, out, ROWS, CC, INNER, NN, 512*512);
}

// round 6
// speedup vs baseline: 1.8016x; 1.0513x over previous
#include <cuda_runtime.h>
#include <math.h>

// ---------------- problem constants ----------------
#define BB 2
#define NN 32768
#define CC 512
#define HH 8
#define DH 64
#define GG 64
#define CD 256
#define ROWS (BB*NN)          // 65536
#define INNER (HH*DH)         // 512
#define EPS 1e-5f
#define TOK_CHUNKS 64

// ---------------- scratch ----------------
__device__ float g_xr   [ROWS * CC];        // tf32-rounded, k-pair-permuted x
__device__ float g_fxmid[ROWS * INNER];
__device__ float g_w    [ROWS * INNER];
__device__ float g_npart[512 * 512];
__device__ float g_norm [BB * HH * GG];
__device__ float g_tpart[16 * TOK_CHUNKS * 4096];
__device__ float g_tok  [16 * 4096];
__device__ float g_ot   [16 * 4096];
__device__ float g_M    [BB * 512 * 512];
__device__ float g_Wcat [512 * 1024];       // [Wcomb | Wfx_rounded]
__device__ float g_bcomb[512];

// ---------------- helpers ----------------
__device__ __forceinline__ void cp16(void* dst, const void* src) {
    unsigned d = (unsigned)__cvta_generic_to_shared(dst);
    asm volatile("cp.async.cg.shared.global [%0], [%1], 16;" :: "r"(d), "l"(src));
}
__device__ __forceinline__ float tf32r(float f) {
    unsigned u;
    asm("cvt.rna.tf32.f32 %0, %1;" : "=r"(u) : "f"(f));
    return __uint_as_float(u);
}
__device__ __forceinline__ void mma_tf32(float* c, const unsigned* a, const unsigned* b) {
    asm volatile(
        "mma.sync.aligned.m16n8k8.row.col.f32.tf32.tf32.f32 "
        "{%0,%1,%2,%3},{%4,%5,%6,%7},{%8,%9},{%0,%1,%2,%3};"
        : "+f"(c[0]), "+f"(c[1]), "+f"(c[2]), "+f"(c[3])
        : "r"(a[0]), "r"(a[1]), "r"(a[2]), "r"(a[3]), "r"(b[0]), "r"(b[1]));
}

// ============================================================
// round + k-pair-permute x: per 8-group, storage = {k0,k4,k1,k5,k2,k6,k3,k7}
// ============================================================
__global__ void round_perm8_kernel(const float* __restrict__ in,
                                   float* __restrict__ out, int n8)
{
    int idx = blockIdx.x * blockDim.x + threadIdx.x;
    int stride = gridDim.x * blockDim.x;
    for (; idx < n8; idx += stride) {
        float4 lo = ((const float4*)in)[idx*2];
        float4 hi = ((const float4*)in)[idx*2 + 1];
        float4 o0 = make_float4(tf32r(lo.x), tf32r(hi.x), tf32r(lo.y), tf32r(hi.y));
        float4 o1 = make_float4(tf32r(lo.z), tf32r(hi.z), tf32r(lo.w), tf32r(hi.w));
        ((float4*)out)[idx*2]     = o0;
        ((float4*)out)[idx*2 + 1] = o1;
    }
}

// Wfx (rounded) -> Wcat columns 512..1023 (row stride 1024)
__global__ void wfx_cat_kernel(const float* __restrict__ Wfx,
                               float* __restrict__ Wcat)
{
    int idx = blockIdx.x * blockDim.x + threadIdx.x;   // over 512*512/4
    int r = idx >> 7;           // 128 float4 per row
    int c4 = idx & 127;
    float4 v = ((const float4*)(Wfx + (size_t)r * 512))[c4];
    v.x = tf32r(v.x); v.y = tf32r(v.y); v.z = tf32r(v.z); v.w = tf32r(v.w);
    ((float4*)(Wcat + (size_t)r * 1024 + 512))[c4] = v;
}

// ============================================================
// Wcomb -> Wcat cols 0..511 (tf32-rounded), bcomb folded into block 0
// ============================================================
__global__ __launch_bounds__(512) void wcomb_kernel(
    const float* __restrict__ Wx, const float* __restrict__ Wslice,
    const float* __restrict__ temp,
    const float* __restrict__ bx, const float* __restrict__ bslice,
    float* __restrict__ Wcat, float* __restrict__ bcomb)
{
    __shared__ float sWs[4096];
    __shared__ float sx[512];
    __shared__ float sit[8];
    const int tid = threadIdx.x;
    const int cr = blockIdx.x;
    for (int i = tid; i < 4096; i += 512) sWs[i] = Wslice[i];
    sx[tid] = Wx[(size_t)cr * 512 + tid];
    if (tid < 8) {
        float tv = temp[tid];
        sit[tid] = 1.0f / fminf(fmaxf(tv, 0.1f), 5.0f);
    }
    __syncthreads();
    const int h = tid >> 6, gg = tid & 63;
    float acc = 0.f;
#pragma unroll 8
    for (int d = 0; d < 64; d++)
        acc += sx[h*64 + d] * sWs[d*64 + gg];
    Wcat[(size_t)cr * 1024 + tid] = tf32r(acc * sit[h]);

    if (blockIdx.x == 0) {
        float acc2 = bslice[gg];
        for (int d = 0; d < 64; d++)
            acc2 += bx[h*64 + d] * sWs[d*64 + gg];
        bcomb[tid] = acc2 * sit[h];
    }
}

// ============================================================
// TF32 GEMM 128x128x32, 8 warps, double-buffered cp.async.
// PERM=1: A smem in k-pair layout (input pre-permuted) -> LDS.64 frags.
// MODE=0: plain epilogue (bias=biasA, out=Cw, stride 512).
// MODE=1: split epilogue: col0<512 -> softmax -> Cw + npart;
//                         col0>=512 -> plain(biasB) -> Cf.
// ============================================================
#define B_LDS 132
#define CT_LDS 132

template<int MODE, int PERM>
__global__ __launch_bounds__(256, 2) void tf32_gemm(
    const float* __restrict__ A, const float* __restrict__ B,
    const float* __restrict__ biasA, const float* __restrict__ biasB,
    float* __restrict__ Cw, float* __restrict__ Cf, float* __restrict__ npart,
    int M, int N, int K, int bRowsPerBatch, int bMatStride)
{
    constexpr int ALDS = PERM ? 40 : 36;
    constexpr int ASZ  = 128 * ALDS;
    extern __shared__ float smem_f[];
    float* Asb[2] = { smem_f,           smem_f + ASZ };
    float* Bsb[2] = { smem_f + 2*ASZ,   smem_f + 2*ASZ + 4224 };

    const int tid  = threadIdx.x;
    const int lane = tid & 31;
    const int warp = tid >> 5;
    const int wr   = warp >> 2;
    const int wc   = warp & 3;
    const int row0 = blockIdx.y * 128;
    const int col0 = blockIdx.x * 128;

    const float* Bp = B;
    if (bRowsPerBatch) Bp += (size_t)(row0 / bRowsPerBatch) * (size_t)bMatStride;

    float c[4][4][4];
#pragma unroll
    for (int i = 0; i < 4; i++)
#pragma unroll
        for (int j = 0; j < 4; j++)
#pragma unroll
            for (int r = 0; r < 4; r++) c[i][j][r] = 0.f;

    const int g = lane >> 2;
    const int t = lane & 3;

    const int ar  = tid >> 3;
    const int akc = (tid & 7) * 4;
    const int bkr = tid >> 5;
    const int bnc = (tid & 31) * 4;

    auto loadTile = [&](int k0, int buf) {
        float* a = Asb[buf];
        float* b = Bsb[buf];
#pragma unroll
        for (int it = 0; it < 4; it++) {
            int r = ar + it * 32;
            cp16(&a[r * ALDS + akc], A + (size_t)(row0 + r) * K + k0 + akc);
            int kr = bkr + it * 8;
            cp16(&b[kr * B_LDS + bnc], Bp + (size_t)(k0 + kr) * N + col0 + bnc);
        }
    };

    loadTile(0, 0);
    asm volatile("cp.async.commit_group;");

    const int ntiles = K >> 5;
    for (int kt = 0; kt < ntiles; kt++) {
        asm volatile("cp.async.wait_group 0;");
        __syncthreads();
        if (kt + 1 < ntiles) {
            loadTile((kt + 1) << 5, (kt + 1) & 1);
            asm volatile("cp.async.commit_group;");
        }
        const float* As = Asb[kt & 1];
        const float* Bs = Bsb[kt & 1];
#pragma unroll
        for (int ks = 0; ks < 4; ks++) {
            const int kb = ks * 8;
            unsigned a[4][4], b[4][2];
            if (PERM) {
#pragma unroll
                for (int i = 0; i < 4; i++) {
                    int rm = wr * 64 + i * 16 + g;
                    float2 v0 = *(const float2*)&As[rm * ALDS + kb + t*2];
                    float2 v1 = *(const float2*)&As[(rm + 8) * ALDS + kb + t*2];
                    a[i][0] = __float_as_uint(v0.x);
                    a[i][1] = __float_as_uint(v1.x);
                    a[i][2] = __float_as_uint(v0.y);
                    a[i][3] = __float_as_uint(v1.y);
                }
            } else {
#pragma unroll
                for (int i = 0; i < 4; i++) {
                    int rm = wr * 64 + i * 16 + g;
                    a[i][0] = __float_as_uint(As[rm * ALDS + kb + t]);
                    a[i][1] = __float_as_uint(As[(rm + 8) * ALDS + kb + t]);
                    a[i][2] = __float_as_uint(As[rm * ALDS + kb + t + 4]);
                    a[i][3] = __float_as_uint(As[(rm + 8) * ALDS + kb + t + 4]);
                }
            }
#pragma unroll
            for (int j = 0; j < 4; j++) {
                int nb = wc * 32 + j * 8 + g;
                b[j][0] = __float_as_uint(Bs[(kb + t) * B_LDS + nb]);
                b[j][1] = __float_as_uint(Bs[(kb + t + 4) * B_LDS + nb]);
            }
#pragma unroll
            for (int i = 0; i < 4; i++)
#pragma unroll
                for (int j = 0; j < 4; j++)
                    mma_tf32(c[i][j], a[i], b[j]);
        }
        __syncthreads();
    }

    const bool do_softmax = (MODE == 1) && (col0 < 512);
    if (do_softmax) {
        float* Ct = smem_f;
#pragma unroll
        for (int i = 0; i < 4; i++) {
            int rm = wr * 64 + i * 16 + g;
#pragma unroll
            for (int j = 0; j < 4; j++) {
                int cn = wc * 32 + j * 8 + t * 2;
                float b0 = biasA[col0 + cn], b1 = biasA[col0 + cn + 1];
                Ct[rm * CT_LDS + cn]           = c[i][j][0] + b0;
                Ct[rm * CT_LDS + cn + 1]       = c[i][j][1] + b1;
                Ct[(rm + 8) * CT_LDS + cn]     = c[i][j][2] + b0;
                Ct[(rm + 8) * CT_LDS + cn + 1] = c[i][j][3] + b1;
            }
        }
        __syncthreads();

        const int r  = tid & 127;
        const int hh = tid >> 7;
        float* rp = Ct + r * CT_LDS + hh * 64;
        float m = -1e30f;
#pragma unroll
        for (int j4 = 0; j4 < 16; j4++) {
            float4 v = ((const float4*)rp)[j4];
            m = fmaxf(m, fmaxf(fmaxf(v.x, v.y), fmaxf(v.z, v.w)));
        }
        float s = 0.f;
#pragma unroll
        for (int j4 = 0; j4 < 16; j4++) {
            float4 v = ((const float4*)rp)[j4];
            s += __expf(v.x - m) + __expf(v.y - m) + __expf(v.z - m) + __expf(v.w - m);
        }
        const float is = 1.0f / s;
        float* wout = Cw + (size_t)(row0 + r) * 512 + col0 + hh * 64;
#pragma unroll
        for (int j4 = 0; j4 < 16; j4++) {
            float4 v = ((const float4*)rp)[j4];
            float4 o = make_float4(
                tf32r(__expf(v.x - m) * is), tf32r(__expf(v.y - m) * is),
                tf32r(__expf(v.z - m) * is), tf32r(__expf(v.w - m) * is));
            ((float4*)wout)[j4] = o;
            ((float4*)rp)[j4] = o;   // keep normalized values for column sums
        }
        __syncthreads();
        // per-block norm partials: column sums over 128 rows
        if (tid < 128) {
            float cs = 0.f;
            for (int rr = 0; rr < 128; rr++)
                cs += Ct[rr * CT_LDS + tid];
            npart[(size_t)blockIdx.y * 512 + col0 + tid] = cs;
        }
    } else {
        const float* bb = (MODE == 1) ? biasB : biasA;
        const int cbase = (MODE == 1) ? (col0 - 512) : col0;
        float* Cp = (MODE == 1) ? Cf : Cw;
#pragma unroll
        for (int i = 0; i < 4; i++) {
            int rm = row0 + wr * 64 + i * 16 + g;
#pragma unroll
            for (int j = 0; j < 4; j++) {
                int cn = cbase + wc * 32 + j * 8 + t * 2;
                float b0 = bb[cn], b1 = bb[cn + 1];
                *(float2*)(Cp + (size_t)rm * 512 + cn) =
                    make_float2(c[i][j][0] + b0, c[i][j][1] + b1);
                *(float2*)(Cp + (size_t)(rm + 8) * 512 + cn) =
                    make_float2(c[i][j][2] + b0, c[i][j][3] + b1);
            }
        }
    }
}

// ============================================================
// norm reduce from per-block partials
// ============================================================
__global__ void norm_reduce_kernel(const float* __restrict__ npart,
                                   float* __restrict__ norm)
{
    int e = blockIdx.x * 256 + threadIdx.x;   // 1024 entries
    int b = e >> 9, hg = e & 511;
    float s = 0.f;
    for (int rb = 0; rb < 256; rb++)
        s += npart[((size_t)(b * 256 + rb)) * 512 + hg];
    norm[e] = s;
}

// ============================================================
// tokens partials: 512-row chunks, 32-row double-buffered tiles
// ============================================================
__global__ __launch_bounds__(256) void tokpart_kernel(
    const float* __restrict__ fx, const float* __restrict__ w,
    float* __restrict__ part)
{
    __shared__ float ws[2][32][64];
    __shared__ float fs[2][32][64];
    const int chunk = blockIdx.x;
    const int bh = blockIdx.y;
    const int b = bh >> 3, h = bh & 7;
    const size_t rbase = (size_t)b * NN + (size_t)chunk * 512;

    const int tid = threadIdx.x;
    const int ty = tid >> 4, tx = tid & 15;

    float acc[4][4];
#pragma unroll
    for (int i = 0; i < 4; i++)
#pragma unroll
        for (int j = 0; j < 4; j++) acc[i][j] = 0.f;

    auto loadTile = [&](int kt, int buf) {
#pragma unroll
        for (int it = 0; it < 2; it++) {
            int s = tid + it * 256;
            int r = s >> 4;
            int c4 = (s & 15) * 4;
            size_t row = rbase + (size_t)kt * 32 + r;
            cp16(&ws[buf][r][c4], w  + row * 512 + h * 64 + c4);
            cp16(&fs[buf][r][c4], fx + row * 512 + h * 64 + c4);
        }
    };

    loadTile(0, 0);
    asm volatile("cp.async.commit_group;");

    for (int kt = 0; kt < 16; kt++) {
        asm volatile("cp.async.wait_group 0;");
        __syncthreads();
        if (kt + 1 < 16) {
            loadTile(kt + 1, (kt + 1) & 1);
            asm volatile("cp.async.commit_group;");
        }
        const int buf = kt & 1;
#pragma unroll
        for (int k = 0; k < 32; k++) {
            float4 a  = *(const float4*)&ws[buf][k][ty*4];
            float4 bv = *(const float4*)&fs[buf][k][tx*4];
            acc[0][0]+=a.x*bv.x; acc[0][1]+=a.x*bv.y; acc[0][2]+=a.x*bv.z; acc[0][3]+=a.x*bv.w;
            acc[1][0]+=a.y*bv.x; acc[1][1]+=a.y*bv.y; acc[1][2]+=a.y*bv.z; acc[1][3]+=a.y*bv.w;
            acc[2][0]+=a.z*bv.x; acc[2][1]+=a.z*bv.y; acc[2][2]+=a.z*bv.z; acc[2][3]+=a.z*bv.w;
            acc[3][0]+=a.w*bv.x; acc[3][1]+=a.w*bv.y; acc[3][2]+=a.w*bv.z; acc[3][3]+=a.w*bv.w;
        }
        __syncthreads();
    }

    float* p = part + ((size_t)bh * TOK_CHUNKS + chunk) * 4096;
#pragma unroll
    for (int ig = 0; ig < 4; ig++) {
        float4 o = make_float4(acc[ig][0], acc[ig][1], acc[ig][2], acc[ig][3]);
        *(float4*)&p[(ty*4+ig)*64 + tx*4] = o;
    }
}

__global__ void tok_reduce_kernel(const float* __restrict__ part,
                                  float* __restrict__ tok)
{
    int idx = blockIdx.x * 256 + threadIdx.x;
    int bh = idx >> 12, gd = idx & 4095;
    float s = 0.f;
    for (int c = 0; c < TOK_CHUNKS; c++)
        s += part[((size_t)bh * TOK_CHUNKS + c) * 4096 + gd];
    tok[idx] = s;
}

// ============================================================
// tiny attention: 16 blocks x 256 threads, task-parallel phases
// ============================================================
template<int NC>
__device__ __forceinline__ void row_gemm_cols(
    const float* __restrict__ xrow, int Kd,
    const float* __restrict__ W, const float* __restrict__ bias,
    float* __restrict__ outp, int c0)
{
    float acc[NC];
#pragma unroll
    for (int j = 0; j < NC; j++) acc[j] = bias[c0 + j];
    for (int d = 0; d < Kd; d++) {
        float xv = xrow[d];
        const float4* W4 = (const float4*)(W + (size_t)d * 64 + c0);
#pragma unroll
        for (int j4 = 0; j4 < NC/4; j4++) {
            float4 wv = W4[j4];
            acc[j4*4+0] += xv*wv.x; acc[j4*4+1] += xv*wv.y;
            acc[j4*4+2] += xv*wv.z; acc[j4*4+3] += xv*wv.w;
        }
    }
#pragma unroll
    for (int j = 0; j < NC; j++) outp[c0 + j] = acc[j];
}

__device__ __forceinline__ void attn_row(
    const float* __restrict__ qrow, const float* __restrict__ Kt,
    const float* __restrict__ Vt, float* __restrict__ o)
{
    float qr[64];
#pragma unroll
    for (int d = 0; d < 64; d++) qr[d] = qrow[d];
    float sc[64];
    float m = -1e30f;
    for (int j = 0; j < 64; j++) {
        const float4* kr = (const float4*)(Kt + j * 64);
        float a = 0.f;
#pragma unroll
        for (int d4 = 0; d4 < 16; d4++) {
            float4 kv = kr[d4];
            a += qr[d4*4]*kv.x + qr[d4*4+1]*kv.y + qr[d4*4+2]*kv.z + qr[d4*4+3]*kv.w;
        }
        sc[j] = a * 0.125f;
        m = fmaxf(m, sc[j]);
    }
    float s = 0.f;
#pragma unroll
    for (int j = 0; j < 64; j++) { sc[j] = expf(sc[j] - m); s += sc[j]; }
    float is = 1.0f / s;
#pragma unroll
    for (int d = 0; d < 64; d++) o[d] = 0.f;
    for (int j = 0; j < 64; j++) {
        float p = sc[j] * is;
        const float4* vr = (const float4*)(Vt + j * 64);
#pragma unroll
        for (int d4 = 0; d4 < 16; d4++) {
            float4 vv = vr[d4];
            o[d4*4+0] += p*vv.x; o[d4*4+1] += p*vv.y;
            o[d4*4+2] += p*vv.z; o[d4*4+3] += p*vv.w;
        }
    }
}

__global__ __launch_bounds__(256) void attn_kernel(
    const float* __restrict__ ctx,
    const float* __restrict__ Wq, const float* __restrict__ bq,
    const float* __restrict__ Wk, const float* __restrict__ bk,
    const float* __restrict__ Wv, const float* __restrict__ bv,
    const float* __restrict__ Wcq, const float* __restrict__ bcq,
    const float* __restrict__ Wck, const float* __restrict__ bck,
    const float* __restrict__ Wcv, const float* __restrict__ bcv,
    const float* __restrict__ smix,
    const float* __restrict__ tokens, const float* __restrict__ norm,
    float* __restrict__ ot)
{
    extern __shared__ float sm[];
    float* s_tok = sm;
    float* s_q   = sm + 4096;
    float* s_k   = sm + 2*4096;
    float* s_v   = sm + 3*4096;
    float* s_cq  = sm + 4*4096;
    float* s_ck  = sm + 5*4096;
    float* s_cv  = sm + 6*4096;

    const int bh = blockIdx.x;
    const int tid = threadIdx.x;

    for (int idx = tid; idx < 4096; idx += 256) {
        int row = idx >> 6;
        float inv = 1.0f / (norm[bh*64 + row] + EPS);
        s_tok[idx] = tokens[(size_t)bh*4096 + idx] * inv;
    }
    __syncthreads();

    {
        const int pid = tid >> 6;
        const int i   = tid & 63;
        const float* W; const float* bb; float* dst;
        if (pid == 0)      { W = Wq;  bb = bq;  dst = s_q;  }
        else if (pid == 1) { W = Wk;  bb = bk;  dst = s_k;  }
        else if (pid == 2) { W = Wv;  bb = bv;  dst = s_v;  }
        else               { W = Wcq; bb = bcq; dst = s_cq; }
        row_gemm_cols<64>(&s_tok[i*64], 64, W, bb, &dst[i*64], 0);
    }
    {
        const int mat = tid >> 7;
        const int sub = tid & 127;
        const int i   = sub >> 1;
        const int c0  = (sub & 1) * 32;
        const float* crow = ctx + ((size_t)bh*64 + i) * 256;
        if (mat == 0) row_gemm_cols<32>(crow, 256, Wck, bck, &s_ck[i*64], c0);
        else          row_gemm_cols<32>(crow, 256, Wcv, bcv, &s_cv[i*64], c0);
    }
    __syncthreads();

    if (tid < 64) {
        float o[64];
        attn_row(&s_q[tid*64], s_k, s_v, o);
#pragma unroll
        for (int d = 0; d < 64; d++) s_tok[tid*64 + d] = o[d];
    } else if (tid < 128) {
        const int i = tid - 64;
        float o[64];
        attn_row(&s_cq[i*64], s_ck, s_cv, o);
#pragma unroll
        for (int d = 0; d < 64; d++) s_cq[i*64 + d] = o[d];
    }
    __syncthreads();

    const float gmix = 1.0f / (1.0f + expf(-smix[0]));
    for (int idx = tid; idx < 4096; idx += 256)
        ot[(size_t)bh*4096 + idx] = gmix * s_tok[idx] + (1.0f - gmix) * s_cq[idx];
}

// ============================================================
// M[b, h*64+g, c] = sum_d out_tok * Wo  (tf32-rounded output)
// ============================================================
__global__ __launch_bounds__(256) void m_kernel(
    const float* __restrict__ Wo, const float* __restrict__ ot,
    float* __restrict__ M)
{
    __shared__ float s_ot[4096];
    __shared__ float s_wo[64 * 128];
    const int bh = blockIdx.y;
    const int h = bh & 7, b = bh >> 3;
    const int c0 = blockIdx.x * 128;
    const int tid = threadIdx.x;

    for (int idx = tid; idx < 1024; idx += 256)
        ((float4*)s_ot)[idx] = ((const float4*)(ot + (size_t)bh * 4096))[idx];
    for (int idx = tid; idx < 2048; idx += 256) {
        int d = idx >> 5;
        int c4 = idx & 31;
        ((float4*)s_wo)[idx] = *(const float4*)(Wo + (size_t)(h*64 + d)*512 + c0 + c4*4);
    }
    __syncthreads();

    const int g0 = (tid >> 3) * 2;
    const int ct = (tid & 7) * 16;
    float acc[2][16];
#pragma unroll
    for (int g = 0; g < 2; g++)
#pragma unroll
        for (int c = 0; c < 16; c++) acc[g][c] = 0.f;

    for (int d = 0; d < 64; d++) {
        float a0 = s_ot[g0*64 + d];
        float a1 = s_ot[(g0+1)*64 + d];
#pragma unroll
        for (int c4 = 0; c4 < 4; c4++) {
            float4 wv = *(const float4*)&s_wo[d*128 + ct + c4*4];
            acc[0][c4*4+0]+=a0*wv.x; acc[0][c4*4+1]+=a0*wv.y; acc[0][c4*4+2]+=a0*wv.z; acc[0][c4*4+3]+=a0*wv.w;
            acc[1][c4*4+0]+=a1*wv.x; acc[1][c4*4+1]+=a1*wv.y; acc[1][c4*4+2]+=a1*wv.z; acc[1][c4*4+3]+=a1*wv.w;
        }
    }

#pragma unroll
    for (int g = 0; g < 2; g++) {
        float* Mr = M + (size_t)b * 262144 + (size_t)(h*64 + g0 + g) * 512 + c0 + ct;
#pragma unroll
        for (int c4 = 0; c4 < 4; c4++)
            *(float4*)(Mr + c4*4) = make_float4(
                tf32r(acc[g][c4*4]), tf32r(acc[g][c4*4+1]),
                tf32r(acc[g][c4*4+2]), tf32r(acc[g][c4*4+3]));
    }
}

// ============================================================
// host launcher
// ============================================================
extern "C" void kernel_launch(void* const* d_in, const int* in_sizes, int n_in,
                              void* d_out, int out_size)
{
    const float* x      = (const float*)d_in[0];
    const float* ctx    = (const float*)d_in[1];
    const float* Wx     = (const float*)d_in[2];
    const float* bx     = (const float*)d_in[3];
    const float* Wfx    = (const float*)d_in[4];
    const float* bfx    = (const float*)d_in[5];
    const float* Wslice = (const float*)d_in[6];
    const float* bslice = (const float*)d_in[7];
    const float* temp   = (const float*)d_in[8];
    const float* Wq     = (const float*)d_in[9];
    const float* bq     = (const float*)d_in[10];
    const float* Wk     = (const float*)d_in[11];
    const float* bk     = (const float*)d_in[12];
    const float* Wv     = (const float*)d_in[13];
    const float* bv     = (const float*)d_in[14];
    const float* Wcq    = (const float*)d_in[15];
    const float* bcq    = (const float*)d_in[16];
    const float* Wck    = (const float*)d_in[17];
    const float* bck    = (const float*)d_in[18];
    const float* Wcv    = (const float*)d_in[19];
    const float* bcv    = (const float*)d_in[20];
    const float* smix   = (const float*)d_in[21];
    const float* Wo     = (const float*)d_in[22];
    const float* bo     = (const float*)d_in[23];
    float* out = (float*)d_out;

    void *p;
    cudaGetSymbolAddress(&p, g_xr);    float* xr    = (float*)p;
    cudaGetSymbolAddress(&p, g_fxmid); float* fxmid = (float*)p;
    cudaGetSymbolAddress(&p, g_w);     float* w     = (float*)p;
    cudaGetSymbolAddress(&p, g_npart); float* npart = (float*)p;
    cudaGetSymbolAddress(&p, g_norm);  float* norm  = (float*)p;
    cudaGetSymbolAddress(&p, g_tpart); float* tpart = (float*)p;
    cudaGetSymbolAddress(&p, g_tok);   float* tok   = (float*)p;
    cudaGetSymbolAddress(&p, g_ot);    float* ot    = (float*)p;
    cudaGetSymbolAddress(&p, g_M);     float* Mm    = (float*)p;
    cudaGetSymbolAddress(&p, g_Wcat);  float* Wcat  = (float*)p;
    cudaGetSymbolAddress(&p, g_bcomb); float* bcomb = (float*)p;

    const int SM1 = (2*128*40 + 2*32*132) * 4;   // 74752
    const int SM0 = (2*128*36 + 2*32*132) * 4;   // 70656
    cudaFuncSetAttribute(tf32_gemm<1,1>, cudaFuncAttributeMaxDynamicSharedMemorySize, SM1);
    cudaFuncSetAttribute(tf32_gemm<0,0>, cudaFuncAttributeMaxDynamicSharedMemorySize, SM0);
    cudaFuncSetAttribute(attn_kernel, cudaFuncAttributeMaxDynamicSharedMemorySize, 7*4096*4);

    // 0: round+permute x; assemble Wcat = [Wcomb | Wfx]; bcomb
    round_perm8_kernel<<<2048, 256>>>(x, xr, ROWS*CC/8);
    wfx_cat_kernel<<<256, 256>>>(Wfx, Wcat);
    wcomb_kernel<<<512, 512>>>(Wx, Wslice, temp, bx, bslice, Wcat, bcomb);
    // 1: merged GEMM: softmax->w(+npart) | plain->fxmid
    tf32_gemm<1,1><<<dim3(8, 512), 256, SM1>>>(
        xr, Wcat, bcomb, bfx, w, fxmid, npart, ROWS, 1024, CC, 0, 0);
    // 2: norm from npart
    norm_reduce_kernel<<<4, 256>>>(npart, norm);
    // 3: tokens = w^T @ fx
    tokpart_kernel<<<dim3(TOK_CHUNKS, 16), 256>>>(fxmid, w, tpart);
    tok_reduce_kernel<<<256, 256>>>(tpart, tok);
    // 4: tiny attention
    attn_kernel<<<16, 256, 7*4096*4>>>(ctx, Wq, bq, Wk, bk, Wv, bv,
                                       Wcq, bcq, Wck, bck, Wcv, bcv,
                                       smix, tok, norm, ot);
    // 5: fold out_tok @ Wo -> M
    m_kernel<<<dim3(4, 16), 256>>>(Wo, ot, Mm);
    // 6: out = w @ M[b] + bo
    tf32_gemm<0,0><<<dim3(4, 512), 256, SM0>>>(
        w, Mm, bo, nullptr, out, nullptr, nullptr, ROWS, 512, INNER, NN, 512*512);
}

// round 8
// speedup vs baseline: 2.2194x; 1.2319x over previous
#include <cuda_runtime.h>
#include <cuda_fp16.h>
#include <math.h>
#include <stdint.h>

// ---------------- problem constants ----------------
#define BB 2
#define NN 32768
#define CC 512
#define HH 8
#define DH 64
#define GG 64
#define CD 256
#define ROWS (BB*NN)          // 65536
#define INNER (HH*DH)         // 512
#define EPS 1e-5f
#define TOK_CHUNKS 64

// ---------------- scratch ----------------
__device__ __half g_xh   [ROWS * CC];       // fp16 x
__device__ __half g_wh   [ROWS * INNER];    // fp16 w (softmax output)
__device__ __half g_fxh  [ROWS * INNER];    // fp16 fx projection
__device__ float  g_npart[512 * 512];
__device__ float  g_norm [BB * HH * GG];
__device__ float  g_tpart[16 * TOK_CHUNKS * 4096];
__device__ float  g_tok  [16 * 4096];
__device__ float  g_ot   [16 * 4096];
__device__ __half g_MTh  [BB * 512 * 512];  // M transposed [b][c][inner], fp16
__device__ __half g_WcatTh[1024 * 512];     // [n][k]: [Wcomb | Wfx]^T, fp16
__device__ float  g_bcomb[512];

// ---------------- helpers ----------------
__device__ __forceinline__ void cp16(void* dst, const void* src) {
    unsigned d = (unsigned)__cvta_generic_to_shared(dst);
    asm volatile("cp.async.cg.shared.global [%0], [%1], 16;" :: "r"(d), "l"(src));
}
__device__ __forceinline__ void mma_f16(float* c, const unsigned* a, const unsigned* b) {
    asm volatile(
        "mma.sync.aligned.m16n8k16.row.col.f32.f16.f16.f32 "
        "{%0,%1,%2,%3},{%4,%5,%6,%7},{%8,%9},{%0,%1,%2,%3};"
        : "+f"(c[0]), "+f"(c[1]), "+f"(c[2]), "+f"(c[3])
        : "r"(a[0]), "r"(a[1]), "r"(a[2]), "r"(a[3]), "r"(b[0]), "r"(b[1]));
}

// ============================================================
// x (fp32) -> xh (fp16)
// ============================================================
__global__ void round_f16_kernel(const float* __restrict__ in,
                                 __half* __restrict__ out, int n4)
{
    int idx = blockIdx.x * blockDim.x + threadIdx.x;
    int stride = gridDim.x * blockDim.x;
    for (; idx < n4; idx += stride) {
        float4 v = ((const float4*)in)[idx];
        __half2* o = (__half2*)out + idx * 2;
        o[0] = __floats2half2_rn(v.x, v.y);
        o[1] = __floats2half2_rn(v.z, v.w);
    }
}

// Wfx -> WcatTh rows 512..1023 (transposed [n][k], fp16)
__global__ void wfx_cat_kernel(const float* __restrict__ Wfx,
                               __half* __restrict__ WcatT)
{
    int idx = blockIdx.x * blockDim.x + threadIdx.x;   // 512*512
    int k = idx >> 9;
    int n = idx & 511;
    WcatT[(size_t)(512 + n) * 512 + k] = __float2half_rn(Wfx[(size_t)k * 512 + n]);
}

// Wcomb -> WcatTh rows 0..511 (transposed, fp16), bcomb in block 0
__global__ __launch_bounds__(512) void wcomb_kernel(
    const float* __restrict__ Wx, const float* __restrict__ Wslice,
    const float* __restrict__ temp,
    const float* __restrict__ bx, const float* __restrict__ bslice,
    __half* __restrict__ WcatT, float* __restrict__ bcomb)
{
    __shared__ float sWs[4096];
    __shared__ float sx[512];
    __shared__ float sit[8];
    const int tid = threadIdx.x;
    const int cr = blockIdx.x;          // k index
    for (int i = tid; i < 4096; i += 512) sWs[i] = Wslice[i];
    sx[tid] = Wx[(size_t)cr * 512 + tid];
    if (tid < 8) {
        float tv = temp[tid];
        sit[tid] = 1.0f / fminf(fmaxf(tv, 0.1f), 5.0f);
    }
    __syncthreads();
    const int h = tid >> 6, gg = tid & 63;
    float acc = 0.f;
#pragma unroll 8
    for (int d = 0; d < 64; d++)
        acc += sx[h*64 + d] * sWs[d*64 + gg];
    WcatT[(size_t)tid * 512 + cr] = __float2half_rn(acc * sit[h]);

    if (blockIdx.x == 0) {
        float acc2 = bslice[gg];
        for (int d = 0; d < 64; d++)
            acc2 += bx[h*64 + d] * sWs[d*64 + gg];
        bcomb[tid] = acc2 * sit[h];
    }
}

// ============================================================
// FP16 GEMM 128x128x32, 8 warps, double-buffered cp.async.
// A: [m][k] fp16 row-major. B: [n][k] fp16 (transposed).
// MODE=1 (merged): col0<512 -> softmax -> wh + npart; else bias -> fxh.
// MODE=0 (final): out float = A@B^T + bias, B per-batch.
// smem bytes: A bufs 2x10240, B bufs 2x10240 = 40960.
//   MODE1 epilogue reuses smem as Ct float (128x132x4 = 67584).
// ============================================================
#define AH 40     // padded k-stride (halves)
#define SM_MAIN 40960
#define SM_MODE1 67584

template<int MODE>
__global__ __launch_bounds__(256, 2) void f16_gemm(
    const __half* __restrict__ A, const __half* __restrict__ BT,
    const float* __restrict__ biasA, const float* __restrict__ biasB,
    __half* __restrict__ wOut, __half* __restrict__ fxOut,
    float* __restrict__ outF, float* __restrict__ npart,
    int K, int bRowsPerBatch, int bMatStride)
{
    extern __shared__ char smem[];
    __half* Asb[2] = { (__half*)smem,           (__half*)(smem + 10240) };
    __half* Bsb[2] = { (__half*)(smem + 20480), (__half*)(smem + 30720) };

    const int tid  = threadIdx.x;
    const int lane = tid & 31;
    const int warp = tid >> 5;
    const int wr   = warp >> 2;
    const int wc   = warp & 3;
    const int row0 = blockIdx.y * 128;
    const int col0 = blockIdx.x * 128;

    const __half* Bp = BT;
    if (bRowsPerBatch) Bp += (size_t)(row0 / bRowsPerBatch) * (size_t)bMatStride;

    float c[4][4][4];
#pragma unroll
    for (int i = 0; i < 4; i++)
#pragma unroll
        for (int j = 0; j < 4; j++)
#pragma unroll
            for (int r = 0; r < 4; r++) c[i][j][r] = 0.f;

    const int g = lane >> 2;
    const int t = lane & 3;

    // staging coords: tile 128 rows x 32 halves (64B/row = 4 cp16 chunks)
    const int sr  = tid >> 2;            // 0..63, +64 per it
    const int skc = (tid & 3) * 8;       // half offset in row

    auto loadTile = [&](int k0, int buf) {
        __half* a = Asb[buf];
        __half* b = Bsb[buf];
#pragma unroll
        for (int it = 0; it < 2; it++) {
            int r = sr + it * 64;
            cp16(&a[r * AH + skc], A  + (size_t)(row0 + r) * K + k0 + skc);
            cp16(&b[r * AH + skc], Bp + (size_t)(col0 + r) * K + k0 + skc);
        }
    };

    loadTile(0, 0);
    asm volatile("cp.async.commit_group;");

    const int ntiles = K >> 5;
    for (int kt = 0; kt < ntiles; kt++) {
        asm volatile("cp.async.wait_group 0;");
        __syncthreads();
        if (kt + 1 < ntiles) {
            loadTile((kt + 1) << 5, (kt + 1) & 1);
            asm volatile("cp.async.commit_group;");
        }
        const __half* As = Asb[kt & 1];
        const __half* Bs = Bsb[kt & 1];
#pragma unroll
        for (int ks = 0; ks < 2; ks++) {
            const int kb = ks * 16;
            unsigned a[4][4], b[4][2];
#pragma unroll
            for (int i = 0; i < 4; i++) {
                int rm = wr * 64 + i * 16 + g;
                a[i][0] = *(const unsigned*)&As[rm * AH + kb + 2*t];
                a[i][1] = *(const unsigned*)&As[(rm + 8) * AH + kb + 2*t];
                a[i][2] = *(const unsigned*)&As[rm * AH + kb + 2*t + 8];
                a[i][3] = *(const unsigned*)&As[(rm + 8) * AH + kb + 2*t + 8];
            }
#pragma unroll
            for (int j = 0; j < 4; j++) {
                int nb = wc * 32 + j * 8 + g;
                b[j][0] = *(const unsigned*)&Bs[nb * AH + kb + 2*t];
                b[j][1] = *(const unsigned*)&Bs[nb * AH + kb + 2*t + 8];
            }
#pragma unroll
            for (int i = 0; i < 4; i++)
#pragma unroll
                for (int j = 0; j < 4; j++)
                    mma_f16(c[i][j], a[i], b[j]);
        }
        __syncthreads();
    }

    if (MODE == 1 && col0 < 512) {
        // logits(+bias) -> Ct, per-head softmax, write wh + npart
        float* Ct = (float*)smem;
#pragma unroll
        for (int i = 0; i < 4; i++) {
            int rm = wr * 64 + i * 16 + g;
#pragma unroll
            for (int j = 0; j < 4; j++) {
                int cn = wc * 32 + j * 8 + t * 2;
                float b0 = biasA[col0 + cn], b1 = biasA[col0 + cn + 1];
                Ct[rm * 132 + cn]           = c[i][j][0] + b0;
                Ct[rm * 132 + cn + 1]       = c[i][j][1] + b1;
                Ct[(rm + 8) * 132 + cn]     = c[i][j][2] + b0;
                Ct[(rm + 8) * 132 + cn + 1] = c[i][j][3] + b1;
            }
        }
        __syncthreads();

        const int r  = tid & 127;
        const int hh = tid >> 7;
        float* rp = Ct + r * 132 + hh * 64;
        float m = -1e30f;
#pragma unroll
        for (int j4 = 0; j4 < 16; j4++) {
            float4 v = ((const float4*)rp)[j4];
            m = fmaxf(m, fmaxf(fmaxf(v.x, v.y), fmaxf(v.z, v.w)));
        }
        float s = 0.f;
#pragma unroll
        for (int j4 = 0; j4 < 16; j4++) {
            float4 v = ((const float4*)rp)[j4];
            s += __expf(v.x - m) + __expf(v.y - m) + __expf(v.z - m) + __expf(v.w - m);
        }
        const float is = 1.0f / s;
        __half2* wout = (__half2*)(wOut + (size_t)(row0 + r) * 512 + col0 + hh * 64);
#pragma unroll
        for (int j4 = 0; j4 < 16; j4++) {
            float4 v = ((const float4*)rp)[j4];
            float e0 = __expf(v.x - m) * is, e1 = __expf(v.y - m) * is;
            float e2 = __expf(v.z - m) * is, e3 = __expf(v.w - m) * is;
            __half2 h0 = __floats2half2_rn(e0, e1);
            __half2 h1 = __floats2half2_rn(e2, e3);
            wout[j4*2]   = h0;
            wout[j4*2+1] = h1;
            // store the half-rounded values for exact norm consistency
            float2 f0 = __half22float2(h0), f1 = __half22float2(h1);
            ((float4*)rp)[j4] = make_float4(f0.x, f0.y, f1.x, f1.y);
        }
        __syncthreads();
        if (tid < 128) {
            float cs = 0.f;
            for (int rr = 0; rr < 128; rr++)
                cs += Ct[rr * 132 + tid];
            npart[(size_t)blockIdx.y * 512 + col0 + tid] = cs;
        }
    } else if (MODE == 1) {
        const int cg0 = col0 - 512;
#pragma unroll
        for (int i = 0; i < 4; i++) {
            int rm = row0 + wr * 64 + i * 16 + g;
#pragma unroll
            for (int j = 0; j < 4; j++) {
                int cn = cg0 + wc * 32 + j * 8 + t * 2;
                float b0 = biasB[cn], b1 = biasB[cn + 1];
                *(__half2*)(fxOut + (size_t)rm * 512 + cn) =
                    __floats2half2_rn(c[i][j][0] + b0, c[i][j][1] + b1);
                *(__half2*)(fxOut + (size_t)(rm + 8) * 512 + cn) =
                    __floats2half2_rn(c[i][j][2] + b0, c[i][j][3] + b1);
            }
        }
    } else {
#pragma unroll
        for (int i = 0; i < 4; i++) {
            int rm = row0 + wr * 64 + i * 16 + g;
#pragma unroll
            for (int j = 0; j < 4; j++) {
                int cn = col0 + wc * 32 + j * 8 + t * 2;
                float b0 = biasA[cn], b1 = biasA[cn + 1];
                *(float2*)(outF + (size_t)rm * 512 + cn) =
                    make_float2(c[i][j][0] + b0, c[i][j][1] + b1);
                *(float2*)(outF + (size_t)(rm + 8) * 512 + cn) =
                    make_float2(c[i][j][2] + b0, c[i][j][3] + b1);
            }
        }
    }
}

// ============================================================
// norm reduce
// ============================================================
__global__ void norm_reduce_kernel(const float* __restrict__ npart,
                                   float* __restrict__ norm)
{
    int e = blockIdx.x * 256 + threadIdx.x;
    int b = e >> 9, hg = e & 511;
    float s = 0.f;
    for (int rb = 0; rb < 256; rb++)
        s += npart[((size_t)(b * 256 + rb)) * 512 + hg];
    norm[e] = s;
}

// ============================================================
// tokens partials (fp16 inputs, fp32 accum)
// ============================================================
__global__ __launch_bounds__(256) void tokpart_kernel(
    const __half* __restrict__ fx, const __half* __restrict__ w,
    float* __restrict__ part)
{
    __shared__ __half ws[2][32][64];
    __shared__ __half fs[2][32][64];
    const int chunk = blockIdx.x;
    const int bh = blockIdx.y;
    const int b = bh >> 3, h = bh & 7;
    const size_t rbase = (size_t)b * NN + (size_t)chunk * 512;

    const int tid = threadIdx.x;
    const int ty = tid >> 4, tx = tid & 15;

    float acc[4][4];
#pragma unroll
    for (int i = 0; i < 4; i++)
#pragma unroll
        for (int j = 0; j < 4; j++) acc[i][j] = 0.f;

    auto loadTile = [&](int kt, int buf) {
        // 32 rows x 64 halves = 128B/row = 8 cp16 chunks/row = 256 chunks
        int r = tid >> 3;            // 0..31
        int c8 = (tid & 7) * 8;      // half offset
        size_t row = rbase + (size_t)kt * 32 + r;
        cp16(&ws[buf][r][c8], w  + row * 512 + h * 64 + c8);
        cp16(&fs[buf][r][c8], fx + row * 512 + h * 64 + c8);
    };

    loadTile(0, 0);
    asm volatile("cp.async.commit_group;");

    for (int kt = 0; kt < 16; kt++) {
        asm volatile("cp.async.wait_group 0;");
        __syncthreads();
        if (kt + 1 < 16) {
            loadTile(kt + 1, (kt + 1) & 1);
            asm volatile("cp.async.commit_group;");
        }
        const int buf = kt & 1;
#pragma unroll
        for (int k = 0; k < 32; k++) {
            const __half2* a2 = (const __half2*)&ws[buf][k][ty*4];
            const __half2* b2 = (const __half2*)&fs[buf][k][tx*4];
            float2 a01 = __half22float2(a2[0]);
            float2 a23 = __half22float2(a2[1]);
            float2 b01 = __half22float2(b2[0]);
            float2 b23 = __half22float2(b2[1]);
            float av[4] = {a01.x, a01.y, a23.x, a23.y};
            float bv[4] = {b01.x, b01.y, b23.x, b23.y};
#pragma unroll
            for (int i = 0; i < 4; i++)
#pragma unroll
                for (int j = 0; j < 4; j++)
                    acc[i][j] += av[i] * bv[j];
        }
        __syncthreads();
    }

    float* p = part + ((size_t)bh * TOK_CHUNKS + chunk) * 4096;
#pragma unroll
    for (int ig = 0; ig < 4; ig++) {
        float4 o = make_float4(acc[ig][0], acc[ig][1], acc[ig][2], acc[ig][3]);
        *(float4*)&p[(ty*4+ig)*64 + tx*4] = o;
    }
}

__global__ void tok_reduce_kernel(const float* __restrict__ part,
                                  float* __restrict__ tok)
{
    int idx = blockIdx.x * 256 + threadIdx.x;
    int bh = idx >> 12, gd = idx & 4095;
    float s = 0.f;
    for (int c = 0; c < TOK_CHUNKS; c++)
        s += part[((size_t)bh * TOK_CHUNKS + c) * 4096 + gd];
    tok[idx] = s;
}

// ============================================================
// tiny attention (unchanged)
// ============================================================
template<int NC>
__device__ __forceinline__ void row_gemm_cols(
    const float* __restrict__ xrow, int Kd,
    const float* __restrict__ W, const float* __restrict__ bias,
    float* __restrict__ outp, int c0)
{
    float acc[NC];
#pragma unroll
    for (int j = 0; j < NC; j++) acc[j] = bias[c0 + j];
    for (int d = 0; d < Kd; d++) {
        float xv = xrow[d];
        const float4* W4 = (const float4*)(W + (size_t)d * 64 + c0);
#pragma unroll
        for (int j4 = 0; j4 < NC/4; j4++) {
            float4 wv = W4[j4];
            acc[j4*4+0] += xv*wv.x; acc[j4*4+1] += xv*wv.y;
            acc[j4*4+2] += xv*wv.z; acc[j4*4+3] += xv*wv.w;
        }
    }
#pragma unroll
    for (int j = 0; j < NC; j++) outp[c0 + j] = acc[j];
}

__device__ __forceinline__ void attn_row(
    const float* __restrict__ qrow, const float* __restrict__ Kt,
    const float* __restrict__ Vt, float* __restrict__ o)
{
    float qr[64];
#pragma unroll
    for (int d = 0; d < 64; d++) qr[d] = qrow[d];
    float sc[64];
    float m = -1e30f;
    for (int j = 0; j < 64; j++) {
        const float4* kr = (const float4*)(Kt + j * 64);
        float a = 0.f;
#pragma unroll
        for (int d4 = 0; d4 < 16; d4++) {
            float4 kv = kr[d4];
            a += qr[d4*4]*kv.x + qr[d4*4+1]*kv.y + qr[d4*4+2]*kv.z + qr[d4*4+3]*kv.w;
        }
        sc[j] = a * 0.125f;
        m = fmaxf(m, sc[j]);
    }
    float s = 0.f;
#pragma unroll
    for (int j = 0; j < 64; j++) { sc[j] = expf(sc[j] - m); s += sc[j]; }
    float is = 1.0f / s;
#pragma unroll
    for (int d = 0; d < 64; d++) o[d] = 0.f;
    for (int j = 0; j < 64; j++) {
        float p = sc[j] * is;
        const float4* vr = (const float4*)(Vt + j * 64);
#pragma unroll
        for (int d4 = 0; d4 < 16; d4++) {
            float4 vv = vr[d4];
            o[d4*4+0] += p*vv.x; o[d4*4+1] += p*vv.y;
            o[d4*4+2] += p*vv.z; o[d4*4+3] += p*vv.w;
        }
    }
}

__global__ __launch_bounds__(256) void attn_kernel(
    const float* __restrict__ ctx,
    const float* __restrict__ Wq, const float* __restrict__ bq,
    const float* __restrict__ Wk, const float* __restrict__ bk,
    const float* __restrict__ Wv, const float* __restrict__ bv,
    const float* __restrict__ Wcq, const float* __restrict__ bcq,
    const float* __restrict__ Wck, const float* __restrict__ bck,
    const float* __restrict__ Wcv, const float* __restrict__ bcv,
    const float* __restrict__ smix,
    const float* __restrict__ tokens, const float* __restrict__ norm,
    float* __restrict__ ot)
{
    extern __shared__ float sm[];
    float* s_tok = sm;
    float* s_q   = sm + 4096;
    float* s_k   = sm + 2*4096;
    float* s_v   = sm + 3*4096;
    float* s_cq  = sm + 4*4096;
    float* s_ck  = sm + 5*4096;
    float* s_cv  = sm + 6*4096;

    const int bh = blockIdx.x;
    const int tid = threadIdx.x;

    for (int idx = tid; idx < 4096; idx += 256) {
        int row = idx >> 6;
        float inv = 1.0f / (norm[bh*64 + row] + EPS);
        s_tok[idx] = tokens[(size_t)bh*4096 + idx] * inv;
    }
    __syncthreads();

    {
        const int pid = tid >> 6;
        const int i   = tid & 63;
        const float* W; const float* bb; float* dst;
        if (pid == 0)      { W = Wq;  bb = bq;  dst = s_q;  }
        else if (pid == 1) { W = Wk;  bb = bk;  dst = s_k;  }
        else if (pid == 2) { W = Wv;  bb = bv;  dst = s_v;  }
        else               { W = Wcq; bb = bcq; dst = s_cq; }
        row_gemm_cols<64>(&s_tok[i*64], 64, W, bb, &dst[i*64], 0);
    }
    {
        const int mat = tid >> 7;
        const int sub = tid & 127;
        const int i   = sub >> 1;
        const int c0  = (sub & 1) * 32;
        const float* crow = ctx + ((size_t)bh*64 + i) * 256;
        if (mat == 0) row_gemm_cols<32>(crow, 256, Wck, bck, &s_ck[i*64], c0);
        else          row_gemm_cols<32>(crow, 256, Wcv, bcv, &s_cv[i*64], c0);
    }
    __syncthreads();

    if (tid < 64) {
        float o[64];
        attn_row(&s_q[tid*64], s_k, s_v, o);
#pragma unroll
        for (int d = 0; d < 64; d++) s_tok[tid*64 + d] = o[d];
    } else if (tid < 128) {
        const int i = tid - 64;
        float o[64];
        attn_row(&s_cq[i*64], s_ck, s_cv, o);
#pragma unroll
        for (int d = 0; d < 64; d++) s_cq[i*64 + d] = o[d];
    }
    __syncthreads();

    const float gmix = 1.0f / (1.0f + expf(-smix[0]));
    for (int idx = tid; idx < 4096; idx += 256)
        ot[(size_t)bh*4096 + idx] = gmix * s_tok[idx] + (1.0f - gmix) * s_cq[idx];
}

// ============================================================
// M^T[b][c][hg] = sum_d out_tok[b,hg,d] * Wo[h*64+d, c]  (fp16 out)
// ============================================================
__global__ __launch_bounds__(256) void m_kernel(
    const float* __restrict__ Wo, const float* __restrict__ ot,
    __half* __restrict__ MT)
{
    __shared__ float s_ot[4096];
    __shared__ float s_wo[64 * 128];
    const int bh = blockIdx.y;
    const int h = bh & 7, b = bh >> 3;
    const int c0 = blockIdx.x * 128;
    const int tid = threadIdx.x;

    for (int idx = tid; idx < 1024; idx += 256)
        ((float4*)s_ot)[idx] = ((const float4*)(ot + (size_t)bh * 4096))[idx];
    for (int idx = tid; idx < 2048; idx += 256) {
        int d = idx >> 5;
        int c4 = idx & 31;
        ((float4*)s_wo)[idx] = *(const float4*)(Wo + (size_t)(h*64 + d)*512 + c0 + c4*4);
    }
    __syncthreads();

    const int g0 = (tid >> 3) * 2;
    const int ct = (tid & 7) * 16;
    float acc[2][16];
#pragma unroll
    for (int g = 0; g < 2; g++)
#pragma unroll
        for (int c = 0; c < 16; c++) acc[g][c] = 0.f;

    for (int d = 0; d < 64; d++) {
        float a0 = s_ot[g0*64 + d];
        float a1 = s_ot[(g0+1)*64 + d];
#pragma unroll
        for (int c4 = 0; c4 < 4; c4++) {
            float4 wv = *(const float4*)&s_wo[d*128 + ct + c4*4];
            acc[0][c4*4+0]+=a0*wv.x; acc[0][c4*4+1]+=a0*wv.y; acc[0][c4*4+2]+=a0*wv.z; acc[0][c4*4+3]+=a0*wv.w;
            acc[1][c4*4+0]+=a1*wv.x; acc[1][c4*4+1]+=a1*wv.y; acc[1][c4*4+2]+=a1*wv.z; acc[1][c4*4+3]+=a1*wv.w;
        }
    }

    // transposed store: MT[b][c][hg]
#pragma unroll
    for (int g = 0; g < 2; g++) {
        int hg = h*64 + g0 + g;
#pragma unroll
        for (int c = 0; c < 16; c++)
            MT[(size_t)b * 262144 + (size_t)(c0 + ct + c) * 512 + hg] =
                __float2half_rn(acc[g][c]);
    }
}

// ============================================================
// host launcher
// ============================================================
extern "C" void kernel_launch(void* const* d_in, const int* in_sizes, int n_in,
                              void* d_out, int out_size)
{
    const float* x      = (const float*)d_in[0];
    const float* ctx    = (const float*)d_in[1];
    const float* Wx     = (const float*)d_in[2];
    const float* bx     = (const float*)d_in[3];
    const float* Wfx    = (const float*)d_in[4];
    const float* bfx    = (const float*)d_in[5];
    const float* Wslice = (const float*)d_in[6];
    const float* bslice = (const float*)d_in[7];
    const float* temp   = (const float*)d_in[8];
    const float* Wq     = (const float*)d_in[9];
    const float* bq     = (const float*)d_in[10];
    const float* Wk     = (const float*)d_in[11];
    const float* bk     = (const float*)d_in[12];
    const float* Wv     = (const float*)d_in[13];
    const float* bv     = (const float*)d_in[14];
    const float* Wcq    = (const float*)d_in[15];
    const float* bcq    = (const float*)d_in[16];
    const float* Wck    = (const float*)d_in[17];
    const float* bck    = (const float*)d_in[18];
    const float* Wcv    = (const float*)d_in[19];
    const float* bcv    = (const float*)d_in[20];
    const float* smix   = (const float*)d_in[21];
    const float* Wo     = (const float*)d_in[22];
    const float* bo     = (const float*)d_in[23];
    float* out = (float*)d_out;

    void *p;
    cudaGetSymbolAddress(&p, g_xh);    __half* xh    = (__half*)p;
    cudaGetSymbolAddress(&p, g_wh);    __half* wh    = (__half*)p;
    cudaGetSymbolAddress(&p, g_fxh);   __half* fxh   = (__half*)p;
    cudaGetSymbolAddress(&p, g_npart); float* npart  = (float*)p;
    cudaGetSymbolAddress(&p, g_norm);  float* norm   = (float*)p;
    cudaGetSymbolAddress(&p, g_tpart); float* tpart  = (float*)p;
    cudaGetSymbolAddress(&p, g_tok);   float* tok    = (float*)p;
    cudaGetSymbolAddress(&p, g_ot);    float* ot     = (float*)p;
    cudaGetSymbolAddress(&p, g_MTh);   __half* MTh   = (__half*)p;
    cudaGetSymbolAddress(&p, g_WcatTh);__half* WcatT = (__half*)p;
    cudaGetSymbolAddress(&p, g_bcomb); float* bcomb  = (float*)p;

    cudaFuncSetAttribute(f16_gemm<1>, cudaFuncAttributeMaxDynamicSharedMemorySize, SM_MODE1);
    cudaFuncSetAttribute(f16_gemm<0>, cudaFuncAttributeMaxDynamicSharedMemorySize, SM_MAIN);
    cudaFuncSetAttribute(attn_kernel, cudaFuncAttributeMaxDynamicSharedMemorySize, 7*4096*4);

    // 0: x -> fp16; assemble WcatT^T fp16; bcomb
    round_f16_kernel<<<2048, 256>>>(x, xh, ROWS*CC/4);
    wfx_cat_kernel<<<1024, 256>>>(Wfx, WcatT);
    wcomb_kernel<<<512, 512>>>(Wx, Wslice, temp, bx, bslice, WcatT, bcomb);
    // 1: merged fp16 GEMM: softmax->wh(+npart) | bias->fxh
    f16_gemm<1><<<dim3(8, 512), 256, SM_MODE1>>>(
        xh, WcatT, bcomb, bfx, wh, fxh, nullptr, npart, CC, 0, 0);
    // 2: norm
    norm_reduce_kernel<<<4, 256>>>(npart, norm);
    // 3: tokens = w^T @ fx
    tokpart_kernel<<<dim3(TOK_CHUNKS, 16), 256>>>(fxh, wh, tpart);
    tok_reduce_kernel<<<256, 256>>>(tpart, tok);
    // 4: tiny attention
    attn_kernel<<<16, 256, 7*4096*4>>>(ctx, Wq, bq, Wk, bk, Wv, bv,
                                       Wcq, bcq, Wck, bck, Wcv, bcv,
                                       smix, tok, norm, ot);
    // 5: fold out_tok @ Wo -> M^T (fp16)
    m_kernel<<<dim3(4, 16), 256>>>(Wo, ot, MTh);
    // 6: out = w @ M[b] + bo (fp16 GEMM, B per-batch)
    f16_gemm<0><<<dim3(4, 512), 256, SM_MAIN>>>(
        wh, MTh, bo, nullptr, nullptr, nullptr, out, nullptr, INNER, NN, 512*512);
}

// round 9
// speedup vs baseline: 2.4589x; 1.1079x over previous
#include <cuda_runtime.h>
#include <cuda_fp16.h>
#include <math.h>
#include <stdint.h>

// ---------------- problem constants ----------------
#define BB 2
#define NN 32768
#define CC 512
#define HH 8
#define DH 64
#define GG 64
#define CD 256
#define ROWS (BB*NN)          // 65536
#define INNER (HH*DH)         // 512
#define EPS 1e-5f
#define TOK_CHUNKS 64

// ---------------- scratch ----------------
__device__ __half g_xh   [ROWS * CC];
__device__ __half g_wh   [ROWS * INNER];
__device__ __half g_fxh  [ROWS * INNER];
__device__ float  g_npart[512 * 512];
__device__ float  g_norm [BB * HH * GG];
__device__ float  g_tpart[16 * TOK_CHUNKS * 4096];
__device__ float  g_tok  [16 * 4096];
__device__ float  g_ot   [16 * 4096];
__device__ __half g_MTh  [BB * 512 * 512];
__device__ __half g_WcatTh[1024 * 512];
__device__ float  g_bcomb[512];

// ---------------- helpers ----------------
__device__ __forceinline__ void cp16(void* dst, const void* src) {
    unsigned d = (unsigned)__cvta_generic_to_shared(dst);
    asm volatile("cp.async.cg.shared.global [%0], [%1], 16;" :: "r"(d), "l"(src));
}
__device__ __forceinline__ void mma_f16(float* c, const unsigned* a, const unsigned* b) {
    asm volatile(
        "mma.sync.aligned.m16n8k16.row.col.f32.f16.f16.f32 "
        "{%0,%1,%2,%3},{%4,%5,%6,%7},{%8,%9},{%0,%1,%2,%3};"
        : "+f"(c[0]), "+f"(c[1]), "+f"(c[2]), "+f"(c[3])
        : "r"(a[0]), "r"(a[1]), "r"(a[2]), "r"(a[3]), "r"(b[0]), "r"(b[1]));
}
#define LDSM4(r0, r1, r2, r3, addr) \
    asm volatile("ldmatrix.sync.aligned.m8n8.x4.shared.b16 {%0,%1,%2,%3}, [%4];" \
        : "=r"(r0), "=r"(r1), "=r"(r2), "=r"(r3) : "r"(addr))

// ============================================================
// x (fp32) -> xh (fp16)
// ============================================================
__global__ void round_f16_kernel(const float* __restrict__ in,
                                 __half* __restrict__ out, int n4)
{
    int idx = blockIdx.x * blockDim.x + threadIdx.x;
    int stride = gridDim.x * blockDim.x;
    for (; idx < n4; idx += stride) {
        float4 v = ((const float4*)in)[idx];
        __half2* o = (__half2*)out + idx * 2;
        o[0] = __floats2half2_rn(v.x, v.y);
        o[1] = __floats2half2_rn(v.z, v.w);
    }
}

// Wfx -> WcatTh rows 512..1023 (transposed [n][k], fp16)
__global__ void wfx_cat_kernel(const float* __restrict__ Wfx,
                               __half* __restrict__ WcatT)
{
    int idx = blockIdx.x * blockDim.x + threadIdx.x;
    int k = idx >> 9;
    int n = idx & 511;
    WcatT[(size_t)(512 + n) * 512 + k] = __float2half_rn(Wfx[(size_t)k * 512 + n]);
}

// Wcomb -> WcatTh rows 0..511 (transposed, fp16), bcomb in block 0
__global__ __launch_bounds__(512) void wcomb_kernel(
    const float* __restrict__ Wx, const float* __restrict__ Wslice,
    const float* __restrict__ temp,
    const float* __restrict__ bx, const float* __restrict__ bslice,
    __half* __restrict__ WcatT, float* __restrict__ bcomb)
{
    __shared__ float sWs[4096];
    __shared__ float sx[512];
    __shared__ float sit[8];
    const int tid = threadIdx.x;
    const int cr = blockIdx.x;
    for (int i = tid; i < 4096; i += 512) sWs[i] = Wslice[i];
    sx[tid] = Wx[(size_t)cr * 512 + tid];
    if (tid < 8) {
        float tv = temp[tid];
        sit[tid] = 1.0f / fminf(fmaxf(tv, 0.1f), 5.0f);
    }
    __syncthreads();
    const int h = tid >> 6, gg = tid & 63;
    float acc = 0.f;
#pragma unroll 8
    for (int d = 0; d < 64; d++)
        acc += sx[h*64 + d] * sWs[d*64 + gg];
    WcatT[(size_t)tid * 512 + cr] = __float2half_rn(acc * sit[h]);

    if (blockIdx.x == 0) {
        float acc2 = bslice[gg];
        for (int d = 0; d < 64; d++)
            acc2 += bx[h*64 + d] * sWs[d*64 + gg];
        bcomb[tid] = acc2 * sit[h];
    }
}

// ============================================================
// FP16 GEMM 128x128x32, 8 warps, double-buffered cp.async,
// ldmatrix fragment loads.
// ============================================================
#define AH 40     // padded k-stride (halves), 80B rows
#define SM_MAIN 40960
#define SM_MODE1 67584

template<int MODE>
__global__ __launch_bounds__(256, 2) void f16_gemm(
    const __half* __restrict__ A, const __half* __restrict__ BT,
    const float* __restrict__ biasA, const float* __restrict__ biasB,
    __half* __restrict__ wOut, __half* __restrict__ fxOut,
    float* __restrict__ outF, float* __restrict__ npart,
    int K, int bRowsPerBatch, int bMatStride)
{
    extern __shared__ char smem[];
    __half* Asb[2] = { (__half*)smem,           (__half*)(smem + 10240) };
    __half* Bsb[2] = { (__half*)(smem + 20480), (__half*)(smem + 30720) };

    const int tid  = threadIdx.x;
    const int lane = tid & 31;
    const int warp = tid >> 5;
    const int wr   = warp >> 2;
    const int wc   = warp & 3;
    const int row0 = blockIdx.y * 128;
    const int col0 = blockIdx.x * 128;

    const __half* Bp = BT;
    if (bRowsPerBatch) Bp += (size_t)(row0 / bRowsPerBatch) * (size_t)bMatStride;

    float c[4][4][4];
#pragma unroll
    for (int i = 0; i < 4; i++)
#pragma unroll
        for (int j = 0; j < 4; j++)
#pragma unroll
            for (int r = 0; r < 4; r++) c[i][j][r] = 0.f;

    const int g = lane >> 2;
    const int t = lane & 3;

    // ldmatrix per-lane byte offsets (buffer/kb independent)
    const uint32_t As0 = (uint32_t)__cvta_generic_to_shared(Asb[0]);
    const uint32_t Bs0 = (uint32_t)__cvta_generic_to_shared(Bsb[0]);
    uint32_t aOff[4], bOff[2];
#pragma unroll
    for (int i = 0; i < 4; i++)
        aOff[i] = (uint32_t)(((wr*64 + i*16 + (lane & 15)) * AH + ((lane >> 4) << 3)) * 2);
#pragma unroll
    for (int jp = 0; jp < 2; jp++)
        bOff[jp] = (uint32_t)(((wc*32 + jp*16 + ((lane >> 4) << 3) + (lane & 7)) * AH
                               + (((lane >> 3) & 1) << 3)) * 2);

    // staging coords
    const int sr  = tid >> 2;
    const int skc = (tid & 3) * 8;

    auto loadTile = [&](int k0, int buf) {
        __half* a = Asb[buf];
        __half* b = Bsb[buf];
#pragma unroll
        for (int it = 0; it < 2; it++) {
            int r = sr + it * 64;
            cp16(&a[r * AH + skc], A  + (size_t)(row0 + r) * K + k0 + skc);
            cp16(&b[r * AH + skc], Bp + (size_t)(col0 + r) * K + k0 + skc);
        }
    };

    loadTile(0, 0);
    asm volatile("cp.async.commit_group;");

    const int ntiles = K >> 5;
    for (int kt = 0; kt < ntiles; kt++) {
        asm volatile("cp.async.wait_group 0;");
        __syncthreads();
        if (kt + 1 < ntiles) {
            loadTile((kt + 1) << 5, (kt + 1) & 1);
            asm volatile("cp.async.commit_group;");
        }
        const uint32_t aBuf = As0 + (kt & 1) * 10240;
        const uint32_t bBuf = Bs0 + (kt & 1) * 10240;
#pragma unroll
        for (int ks = 0; ks < 2; ks++) {
            const uint32_t kbB = ks * 32;   // kb halves * 2 bytes
            unsigned a[4][4], b[4][2];
#pragma unroll
            for (int i = 0; i < 4; i++)
                LDSM4(a[i][0], a[i][1], a[i][2], a[i][3], aBuf + aOff[i] + kbB);
            LDSM4(b[0][0], b[0][1], b[1][0], b[1][1], bBuf + bOff[0] + kbB);
            LDSM4(b[2][0], b[2][1], b[3][0], b[3][1], bBuf + bOff[1] + kbB);
#pragma unroll
            for (int i = 0; i < 4; i++)
#pragma unroll
                for (int j = 0; j < 4; j++)
                    mma_f16(c[i][j], a[i], b[j]);
        }
        __syncthreads();
    }

    if (MODE == 1 && col0 < 512) {
        float* Ct = (float*)smem;
#pragma unroll
        for (int i = 0; i < 4; i++) {
            int rm = wr * 64 + i * 16 + g;
#pragma unroll
            for (int j = 0; j < 4; j++) {
                int cn = wc * 32 + j * 8 + t * 2;
                float b0 = biasA[col0 + cn], b1 = biasA[col0 + cn + 1];
                Ct[rm * 132 + cn]           = c[i][j][0] + b0;
                Ct[rm * 132 + cn + 1]       = c[i][j][1] + b1;
                Ct[(rm + 8) * 132 + cn]     = c[i][j][2] + b0;
                Ct[(rm + 8) * 132 + cn + 1] = c[i][j][3] + b1;
            }
        }
        __syncthreads();

        const int r  = tid & 127;
        const int hh = tid >> 7;
        float* rp = Ct + r * 132 + hh * 64;
        float m = -1e30f;
#pragma unroll
        for (int j4 = 0; j4 < 16; j4++) {
            float4 v = ((const float4*)rp)[j4];
            m = fmaxf(m, fmaxf(fmaxf(v.x, v.y), fmaxf(v.z, v.w)));
        }
        float s = 0.f;
#pragma unroll
        for (int j4 = 0; j4 < 16; j4++) {
            float4 v = ((const float4*)rp)[j4];
            s += __expf(v.x - m) + __expf(v.y - m) + __expf(v.z - m) + __expf(v.w - m);
        }
        const float is = 1.0f / s;
        __half2* wout = (__half2*)(wOut + (size_t)(row0 + r) * 512 + col0 + hh * 64);
#pragma unroll
        for (int j4 = 0; j4 < 16; j4++) {
            float4 v = ((const float4*)rp)[j4];
            float e0 = __expf(v.x - m) * is, e1 = __expf(v.y - m) * is;
            float e2 = __expf(v.z - m) * is, e3 = __expf(v.w - m) * is;
            __half2 h0 = __floats2half2_rn(e0, e1);
            __half2 h1 = __floats2half2_rn(e2, e3);
            wout[j4*2]   = h0;
            wout[j4*2+1] = h1;
            float2 f0 = __half22float2(h0), f1 = __half22float2(h1);
            ((float4*)rp)[j4] = make_float4(f0.x, f0.y, f1.x, f1.y);
        }
        __syncthreads();
        if (tid < 128) {
            float cs = 0.f;
            for (int rr = 0; rr < 128; rr++)
                cs += Ct[rr * 132 + tid];
            npart[(size_t)blockIdx.y * 512 + col0 + tid] = cs;
        }
    } else if (MODE == 1) {
        const int cg0 = col0 - 512;
#pragma unroll
        for (int i = 0; i < 4; i++) {
            int rm = row0 + wr * 64 + i * 16 + g;
#pragma unroll
            for (int j = 0; j < 4; j++) {
                int cn = cg0 + wc * 32 + j * 8 + t * 2;
                float b0 = biasB[cn], b1 = biasB[cn + 1];
                *(__half2*)(fxOut + (size_t)rm * 512 + cn) =
                    __floats2half2_rn(c[i][j][0] + b0, c[i][j][1] + b1);
                *(__half2*)(fxOut + (size_t)(rm + 8) * 512 + cn) =
                    __floats2half2_rn(c[i][j][2] + b0, c[i][j][3] + b1);
            }
        }
    } else {
#pragma unroll
        for (int i = 0; i < 4; i++) {
            int rm = row0 + wr * 64 + i * 16 + g;
#pragma unroll
            for (int j = 0; j < 4; j++) {
                int cn = col0 + wc * 32 + j * 8 + t * 2;
                float b0 = biasA[cn], b1 = biasA[cn + 1];
                *(float2*)(outF + (size_t)rm * 512 + cn) =
                    make_float2(c[i][j][0] + b0, c[i][j][1] + b1);
                *(float2*)(outF + (size_t)(rm + 8) * 512 + cn) =
                    make_float2(c[i][j][2] + b0, c[i][j][3] + b1);
            }
        }
    }
}

// ============================================================
// norm reduce
// ============================================================
__global__ void norm_reduce_kernel(const float* __restrict__ npart,
                                   float* __restrict__ norm)
{
    int e = blockIdx.x * 256 + threadIdx.x;
    int b = e >> 9, hg = e & 511;
    float s = 0.f;
    for (int rb = 0; rb < 256; rb++)
        s += npart[((size_t)(b * 256 + rb)) * 512 + hg];
    norm[e] = s;
}

// ============================================================
// tokens partials (fp16 inputs, fp32 accum)
// ============================================================
__global__ __launch_bounds__(256) void tokpart_kernel(
    const __half* __restrict__ fx, const __half* __restrict__ w,
    float* __restrict__ part)
{
    __shared__ __half ws[2][32][64];
    __shared__ __half fs[2][32][64];
    const int chunk = blockIdx.x;
    const int bh = blockIdx.y;
    const int b = bh >> 3, h = bh & 7;
    const size_t rbase = (size_t)b * NN + (size_t)chunk * 512;

    const int tid = threadIdx.x;
    const int ty = tid >> 4, tx = tid & 15;

    float acc[4][4];
#pragma unroll
    for (int i = 0; i < 4; i++)
#pragma unroll
        for (int j = 0; j < 4; j++) acc[i][j] = 0.f;

    auto loadTile = [&](int kt, int buf) {
        int r = tid >> 3;
        int c8 = (tid & 7) * 8;
        size_t row = rbase + (size_t)kt * 32 + r;
        cp16(&ws[buf][r][c8], w  + row * 512 + h * 64 + c8);
        cp16(&fs[buf][r][c8], fx + row * 512 + h * 64 + c8);
    };

    loadTile(0, 0);
    asm volatile("cp.async.commit_group;");

    for (int kt = 0; kt < 16; kt++) {
        asm volatile("cp.async.wait_group 0;");
        __syncthreads();
        if (kt + 1 < 16) {
            loadTile(kt + 1, (kt + 1) & 1);
            asm volatile("cp.async.commit_group;");
        }
        const int buf = kt & 1;
#pragma unroll
        for (int k = 0; k < 32; k++) {
            const __half2* a2 = (const __half2*)&ws[buf][k][ty*4];
            const __half2* b2 = (const __half2*)&fs[buf][k][tx*4];
            float2 a01 = __half22float2(a2[0]);
            float2 a23 = __half22float2(a2[1]);
            float2 b01 = __half22float2(b2[0]);
            float2 b23 = __half22float2(b2[1]);
            float av[4] = {a01.x, a01.y, a23.x, a23.y};
            float bv[4] = {b01.x, b01.y, b23.x, b23.y};
#pragma unroll
            for (int i = 0; i < 4; i++)
#pragma unroll
                for (int j = 0; j < 4; j++)
                    acc[i][j] += av[i] * bv[j];
        }
        __syncthreads();
    }

    float* p = part + ((size_t)bh * TOK_CHUNKS + chunk) * 4096;
#pragma unroll
    for (int ig = 0; ig < 4; ig++) {
        float4 o = make_float4(acc[ig][0], acc[ig][1], acc[ig][2], acc[ig][3]);
        *(float4*)&p[(ty*4+ig)*64 + tx*4] = o;
    }
}

__global__ void tok_reduce_kernel(const float* __restrict__ part,
                                  float* __restrict__ tok)
{
    int idx = blockIdx.x * 256 + threadIdx.x;
    int bh = idx >> 12, gd = idx & 4095;
    float s = 0.f;
    for (int c = 0; c < TOK_CHUNKS; c++)
        s += part[((size_t)bh * TOK_CHUNKS + c) * 4096 + gd];
    tok[idx] = s;
}

// ============================================================
// tiny attention
// ============================================================
template<int NC>
__device__ __forceinline__ void row_gemm_cols(
    const float* __restrict__ xrow, int Kd,
    const float* __restrict__ W, const float* __restrict__ bias,
    float* __restrict__ outp, int c0)
{
    float acc[NC];
#pragma unroll
    for (int j = 0; j < NC; j++) acc[j] = bias[c0 + j];
    for (int d = 0; d < Kd; d++) {
        float xv = xrow[d];
        const float4* W4 = (const float4*)(W + (size_t)d * 64 + c0);
#pragma unroll
        for (int j4 = 0; j4 < NC/4; j4++) {
            float4 wv = W4[j4];
            acc[j4*4+0] += xv*wv.x; acc[j4*4+1] += xv*wv.y;
            acc[j4*4+2] += xv*wv.z; acc[j4*4+3] += xv*wv.w;
        }
    }
#pragma unroll
    for (int j = 0; j < NC; j++) outp[c0 + j] = acc[j];
}

__device__ __forceinline__ void attn_row(
    const float* __restrict__ qrow, const float* __restrict__ Kt,
    const float* __restrict__ Vt, float* __restrict__ o)
{
    float qr[64];
#pragma unroll
    for (int d = 0; d < 64; d++) qr[d] = qrow[d];
    float sc[64];
    float m = -1e30f;
    for (int j = 0; j < 64; j++) {
        const float4* kr = (const float4*)(Kt + j * 64);
        float a = 0.f;
#pragma unroll
        for (int d4 = 0; d4 < 16; d4++) {
            float4 kv = kr[d4];
            a += qr[d4*4]*kv.x + qr[d4*4+1]*kv.y + qr[d4*4+2]*kv.z + qr[d4*4+3]*kv.w;
        }
        sc[j] = a * 0.125f;
        m = fmaxf(m, sc[j]);
    }
    float s = 0.f;
#pragma unroll
    for (int j = 0; j < 64; j++) { sc[j] = expf(sc[j] - m); s += sc[j]; }
    float is = 1.0f / s;
#pragma unroll
    for (int d = 0; d < 64; d++) o[d] = 0.f;
    for (int j = 0; j < 64; j++) {
        float p = sc[j] * is;
        const float4* vr = (const float4*)(Vt + j * 64);
#pragma unroll
        for (int d4 = 0; d4 < 16; d4++) {
            float4 vv = vr[d4];
            o[d4*4+0] += p*vv.x; o[d4*4+1] += p*vv.y;
            o[d4*4+2] += p*vv.z; o[d4*4+3] += p*vv.w;
        }
    }
}

__global__ __launch_bounds__(256) void attn_kernel(
    const float* __restrict__ ctx,
    const float* __restrict__ Wq, const float* __restrict__ bq,
    const float* __restrict__ Wk, const float* __restrict__ bk,
    const float* __restrict__ Wv, const float* __restrict__ bv,
    const float* __restrict__ Wcq, const float* __restrict__ bcq,
    const float* __restrict__ Wck, const float* __restrict__ bck,
    const float* __restrict__ Wcv, const float* __restrict__ bcv,
    const float* __restrict__ smix,
    const float* __restrict__ tokens, const float* __restrict__ norm,
    float* __restrict__ ot)
{
    extern __shared__ float sm[];
    float* s_tok = sm;
    float* s_q   = sm + 4096;
    float* s_k   = sm + 2*4096;
    float* s_v   = sm + 3*4096;
    float* s_cq  = sm + 4*4096;
    float* s_ck  = sm + 5*4096;
    float* s_cv  = sm + 6*4096;

    const int bh = blockIdx.x;
    const int tid = threadIdx.x;

    for (int idx = tid; idx < 4096; idx += 256) {
        int row = idx >> 6;
        float inv = 1.0f / (norm[bh*64 + row] + EPS);
        s_tok[idx] = tokens[(size_t)bh*4096 + idx] * inv;
    }
    __syncthreads();

    {
        const int pid = tid >> 6;
        const int i   = tid & 63;
        const float* W; const float* bb; float* dst;
        if (pid == 0)      { W = Wq;  bb = bq;  dst = s_q;  }
        else if (pid == 1) { W = Wk;  bb = bk;  dst = s_k;  }
        else if (pid == 2) { W = Wv;  bb = bv;  dst = s_v;  }
        else               { W = Wcq; bb = bcq; dst = s_cq; }
        row_gemm_cols<64>(&s_tok[i*64], 64, W, bb, &dst[i*64], 0);
    }
    {
        const int mat = tid >> 7;
        const int sub = tid & 127;
        const int i   = sub >> 1;
        const int c0  = (sub & 1) * 32;
        const float* crow = ctx + ((size_t)bh*64 + i) * 256;
        if (mat == 0) row_gemm_cols<32>(crow, 256, Wck, bck, &s_ck[i*64], c0);
        else          row_gemm_cols<32>(crow, 256, Wcv, bcv, &s_cv[i*64], c0);
    }
    __syncthreads();

    if (tid < 64) {
        float o[64];
        attn_row(&s_q[tid*64], s_k, s_v, o);
#pragma unroll
        for (int d = 0; d < 64; d++) s_tok[tid*64 + d] = o[d];
    } else if (tid < 128) {
        const int i = tid - 64;
        float o[64];
        attn_row(&s_cq[i*64], s_ck, s_cv, o);
#pragma unroll
        for (int d = 0; d < 64; d++) s_cq[i*64 + d] = o[d];
    }
    __syncthreads();

    const float gmix = 1.0f / (1.0f + expf(-smix[0]));
    for (int idx = tid; idx < 4096; idx += 256)
        ot[(size_t)bh*4096 + idx] = gmix * s_tok[idx] + (1.0f - gmix) * s_cq[idx];
}

// ============================================================
// M^T[b][c][hg] = sum_d out_tok[b,hg,d] * Wo[h*64+d, c]  (fp16 out)
// ============================================================
__global__ __launch_bounds__(256) void m_kernel(
    const float* __restrict__ Wo, const float* __restrict__ ot,
    __half* __restrict__ MT)
{
    __shared__ float s_ot[4096];
    __shared__ float s_wo[64 * 128];
    const int bh = blockIdx.y;
    const int h = bh & 7, b = bh >> 3;
    const int c0 = blockIdx.x * 128;
    const int tid = threadIdx.x;

    for (int idx = tid; idx < 1024; idx += 256)
        ((float4*)s_ot)[idx] = ((const float4*)(ot + (size_t)bh * 4096))[idx];
    for (int idx = tid; idx < 2048; idx += 256) {
        int d = idx >> 5;
        int c4 = idx & 31;
        ((float4*)s_wo)[idx] = *(const float4*)(Wo + (size_t)(h*64 + d)*512 + c0 + c4*4);
    }
    __syncthreads();

    const int g0 = (tid >> 3) * 2;
    const int ct = (tid & 7) * 16;
    float acc[2][16];
#pragma unroll
    for (int g = 0; g < 2; g++)
#pragma unroll
        for (int c = 0; c < 16; c++) acc[g][c] = 0.f;

    for (int d = 0; d < 64; d++) {
        float a0 = s_ot[g0*64 + d];
        float a1 = s_ot[(g0+1)*64 + d];
#pragma unroll
        for (int c4 = 0; c4 < 4; c4++) {
            float4 wv = *(const float4*)&s_wo[d*128 + ct + c4*4];
            acc[0][c4*4+0]+=a0*wv.x; acc[0][c4*4+1]+=a0*wv.y; acc[0][c4*4+2]+=a0*wv.z; acc[0][c4*4+3]+=a0*wv.w;
            acc[1][c4*4+0]+=a1*wv.x; acc[1][c4*4+1]+=a1*wv.y; acc[1][c4*4+2]+=a1*wv.z; acc[1][c4*4+3]+=a1*wv.w;
        }
    }

#pragma unroll
    for (int g = 0; g < 2; g++) {
        int hg = h*64 + g0 + g;
#pragma unroll
        for (int c = 0; c < 16; c++)
            MT[(size_t)b * 262144 + (size_t)(c0 + ct + c) * 512 + hg] =
                __float2half_rn(acc[g][c]);
    }
}

// ============================================================
// host launcher
// ============================================================
extern "C" void kernel_launch(void* const* d_in, const int* in_sizes, int n_in,
                              void* d_out, int out_size)
{
    const float* x      = (const float*)d_in[0];
    const float* ctx    = (const float*)d_in[1];
    const float* Wx     = (const float*)d_in[2];
    const float* bx     = (const float*)d_in[3];
    const float* Wfx    = (const float*)d_in[4];
    const float* bfx    = (const float*)d_in[5];
    const float* Wslice = (const float*)d_in[6];
    const float* bslice = (const float*)d_in[7];
    const float* temp   = (const float*)d_in[8];
    const float* Wq     = (const float*)d_in[9];
    const float* bq     = (const float*)d_in[10];
    const float* Wk     = (const float*)d_in[11];
    const float* bk     = (const float*)d_in[12];
    const float* Wv     = (const float*)d_in[13];
    const float* bv     = (const float*)d_in[14];
    const float* Wcq    = (const float*)d_in[15];
    const float* bcq    = (const float*)d_in[16];
    const float* Wck    = (const float*)d_in[17];
    const float* bck    = (const float*)d_in[18];
    const float* Wcv    = (const float*)d_in[19];
    const float* bcv    = (const float*)d_in[20];
    const float* smix   = (const float*)d_in[21];
    const float* Wo     = (const float*)d_in[22];
    const float* bo     = (const float*)d_in[23];
    float* out = (float*)d_out;

    void *p;
    cudaGetSymbolAddress(&p, g_xh);    __half* xh    = (__half*)p;
    cudaGetSymbolAddress(&p, g_wh);    __half* wh    = (__half*)p;
    cudaGetSymbolAddress(&p, g_fxh);   __half* fxh   = (__half*)p;
    cudaGetSymbolAddress(&p, g_npart); float* npart  = (float*)p;
    cudaGetSymbolAddress(&p, g_norm);  float* norm   = (float*)p;
    cudaGetSymbolAddress(&p, g_tpart); float* tpart  = (float*)p;
    cudaGetSymbolAddress(&p, g_tok);   float* tok    = (float*)p;
    cudaGetSymbolAddress(&p, g_ot);    float* ot     = (float*)p;
    cudaGetSymbolAddress(&p, g_MTh);   __half* MTh   = (__half*)p;
    cudaGetSymbolAddress(&p, g_WcatTh);__half* WcatT = (__half*)p;
    cudaGetSymbolAddress(&p, g_bcomb); float* bcomb  = (float*)p;

    cudaFuncSetAttribute(f16_gemm<1>, cudaFuncAttributeMaxDynamicSharedMemorySize, SM_MODE1);
    cudaFuncSetAttribute(f16_gemm<0>, cudaFuncAttributeMaxDynamicSharedMemorySize, SM_MAIN);
    cudaFuncSetAttribute(attn_kernel, cudaFuncAttributeMaxDynamicSharedMemorySize, 7*4096*4);

    // 0: x -> fp16; assemble WcatT^T fp16; bcomb
    round_f16_kernel<<<2048, 256>>>(x, xh, ROWS*CC/4);
    wfx_cat_kernel<<<1024, 256>>>(Wfx, WcatT);
    wcomb_kernel<<<512, 512>>>(Wx, Wslice, temp, bx, bslice, WcatT, bcomb);
    // 1: merged fp16 GEMM: softmax->wh(+npart) | bias->fxh
    f16_gemm<1><<<dim3(8, 512), 256, SM_MODE1>>>(
        xh, WcatT, bcomb, bfx, wh, fxh, nullptr, npart, CC, 0, 0);
    // 2: norm
    norm_reduce_kernel<<<4, 256>>>(npart, norm);
    // 3: tokens = w^T @ fx
    tokpart_kernel<<<dim3(TOK_CHUNKS, 16), 256>>>(fxh, wh, tpart);
    tok_reduce_kernel<<<256, 256>>>(tpart, tok);
    // 4: tiny attention
    attn_kernel<<<16, 256, 7*4096*4>>>(ctx, Wq, bq, Wk, bk, Wv, bv,
                                       Wcq, bcq, Wck, bck, Wcv, bcv,
                                       smix, tok, norm, ot);
    // 5: fold out_tok @ Wo -> M^T (fp16)
    m_kernel<<<dim3(4, 16), 256>>>(Wo, ot, MTh);
    // 6: out = w @ M[b] + bo (fp16 GEMM, B per-batch)
    f16_gemm<0><<<dim3(4, 512), 256, SM_MAIN>>>(
        wh, MTh, bo, nullptr, nullptr, nullptr, out, nullptr, INNER, NN, 512*512);
}

// round 10
// speedup vs baseline: 2.7050x; 1.1001x over previous
#include <cuda_runtime.h>
#include <cuda_fp16.h>
#include <math.h>
#include <stdint.h>

// ---------------- problem constants ----------------
#define BB 2
#define NN 32768
#define CC 512
#define HH 8
#define DH 64
#define GG 64
#define CD 256
#define ROWS (BB*NN)          // 65536
#define INNER (HH*DH)         // 512
#define EPS 1e-5f
#define TOK_CHUNKS 64

// ---------------- scratch ----------------
__device__ __half g_xh   [ROWS * CC];
__device__ __half g_wh   [ROWS * INNER];
__device__ __half g_fxh  [ROWS * INNER];
__device__ float  g_npart[512 * 512];
__device__ float  g_norm [BB * HH * GG];
__device__ float  g_tpart[16 * TOK_CHUNKS * 4096];
__device__ float  g_tok  [16 * 4096];
__device__ float  g_ot   [16 * 4096];
__device__ __half g_MTh  [BB * 512 * 512];
__device__ __half g_WcatTh[1024 * 512];
__device__ float  g_bcomb[512];

// ---------------- helpers ----------------
__device__ __forceinline__ void cp16(void* dst, const void* src) {
    unsigned d = (unsigned)__cvta_generic_to_shared(dst);
    asm volatile("cp.async.cg.shared.global [%0], [%1], 16;" :: "r"(d), "l"(src));
}
__device__ __forceinline__ void mma_f16(float* c, const unsigned* a, const unsigned* b) {
    asm volatile(
        "mma.sync.aligned.m16n8k16.row.col.f32.f16.f16.f32 "
        "{%0,%1,%2,%3},{%4,%5,%6,%7},{%8,%9},{%0,%1,%2,%3};"
        : "+f"(c[0]), "+f"(c[1]), "+f"(c[2]), "+f"(c[3])
        : "r"(a[0]), "r"(a[1]), "r"(a[2]), "r"(a[3]), "r"(b[0]), "r"(b[1]));
}
#define LDSM4(r0, r1, r2, r3, addr) \
    asm volatile("ldmatrix.sync.aligned.m8n8.x4.shared.b16 {%0,%1,%2,%3}, [%4];" \
        : "=r"(r0), "=r"(r1), "=r"(r2), "=r"(r3) : "r"(addr))

// ============================================================
// x (fp32) -> xh (fp16)
// ============================================================
__global__ void round_f16_kernel(const float* __restrict__ in,
                                 __half* __restrict__ out, int n4)
{
    int idx = blockIdx.x * blockDim.x + threadIdx.x;
    int stride = gridDim.x * blockDim.x;
    for (; idx < n4; idx += stride) {
        float4 v = ((const float4*)in)[idx];
        __half2* o = (__half2*)out + idx * 2;
        o[0] = __floats2half2_rn(v.x, v.y);
        o[1] = __floats2half2_rn(v.z, v.w);
    }
}

// Wfx -> WcatTh rows 512..1023 (transposed [n][k], fp16)
__global__ void wfx_cat_kernel(const float* __restrict__ Wfx,
                               __half* __restrict__ WcatT)
{
    int idx = blockIdx.x * blockDim.x + threadIdx.x;
    int k = idx >> 9;
    int n = idx & 511;
    WcatT[(size_t)(512 + n) * 512 + k] = __float2half_rn(Wfx[(size_t)k * 512 + n]);
}

// Wcomb -> WcatTh rows 0..511 (transposed, fp16), bcomb in block 0
__global__ __launch_bounds__(512) void wcomb_kernel(
    const float* __restrict__ Wx, const float* __restrict__ Wslice,
    const float* __restrict__ temp,
    const float* __restrict__ bx, const float* __restrict__ bslice,
    __half* __restrict__ WcatT, float* __restrict__ bcomb)
{
    __shared__ float sWs[4096];
    __shared__ float sx[512];
    __shared__ float sit[8];
    const int tid = threadIdx.x;
    const int cr = blockIdx.x;
    for (int i = tid; i < 4096; i += 512) sWs[i] = Wslice[i];
    sx[tid] = Wx[(size_t)cr * 512 + tid];
    if (tid < 8) {
        float tv = temp[tid];
        sit[tid] = 1.0f / fminf(fmaxf(tv, 0.1f), 5.0f);
    }
    __syncthreads();
    const int h = tid >> 6, gg = tid & 63;
    float acc = 0.f;
#pragma unroll 8
    for (int d = 0; d < 64; d++)
        acc += sx[h*64 + d] * sWs[d*64 + gg];
    WcatT[(size_t)tid * 512 + cr] = __float2half_rn(acc * sit[h]);

    if (blockIdx.x == 0) {
        float acc2 = bslice[gg];
        for (int d = 0; d < 64; d++)
            acc2 += bx[h*64 + d] * sWs[d*64 + gg];
        bcomb[tid] = acc2 * sit[h];
    }
}

// ============================================================
// FP16 GEMM 128x128x32, 8 warps (warp tile 32x64), 4-stage cp.async,
// ldmatrix fragment loads, register-resident softmax epilogue.
// ============================================================
#define AH 40     // padded k-stride (halves), 80B rows
#define STG_BYTES 10240
#define SM_GEMM (8 * STG_BYTES)   // 4 A stages + 4 B stages = 81920

template<int MODE>
__global__ __launch_bounds__(256, 2) void f16_gemm(
    const __half* __restrict__ A, const __half* __restrict__ BT,
    const float* __restrict__ biasA, const float* __restrict__ biasB,
    __half* __restrict__ wOut, __half* __restrict__ fxOut,
    float* __restrict__ outF, float* __restrict__ npart,
    int K, int bRowsPerBatch, int bMatStride)
{
    extern __shared__ char smem[];

    const int tid  = threadIdx.x;
    const int lane = tid & 31;
    const int warp = tid >> 5;
    const int wr   = warp >> 1;    // 0..3 (32 rows each)
    const int wc   = warp & 1;     // 0..1 (64 cols each)
    const int row0 = blockIdx.y * 128;
    const int col0 = blockIdx.x * 128;

    const __half* Bp = BT;
    if (bRowsPerBatch) Bp += (size_t)(row0 / bRowsPerBatch) * (size_t)bMatStride;

    float c[2][8][4];
#pragma unroll
    for (int i = 0; i < 2; i++)
#pragma unroll
        for (int j = 0; j < 8; j++)
#pragma unroll
            for (int r = 0; r < 4; r++) c[i][j][r] = 0.f;

    const int g = lane >> 2;
    const int t = lane & 3;

    const uint32_t As0 = (uint32_t)__cvta_generic_to_shared(smem);
    const uint32_t Bs0 = As0 + 4 * STG_BYTES;
    uint32_t aOff[2], bOff[4];
#pragma unroll
    for (int i = 0; i < 2; i++)
        aOff[i] = (uint32_t)(((wr*32 + i*16 + (lane & 15)) * AH + ((lane >> 4) << 3)) * 2);
#pragma unroll
    for (int jp = 0; jp < 4; jp++)
        bOff[jp] = (uint32_t)(((wc*64 + jp*16 + ((lane >> 4) << 3) + (lane & 7)) * AH
                               + (((lane >> 3) & 1) << 3)) * 2);

    // staging coords
    const int sr  = tid >> 2;
    const int skc = (tid & 3) * 8;

    auto stage = [&](int kt, int buf) {
        __half* a = (__half*)(smem + buf * STG_BYTES);
        __half* b = (__half*)(smem + 4 * STG_BYTES + buf * STG_BYTES);
        const int k0 = kt << 5;
#pragma unroll
        for (int it = 0; it < 2; it++) {
            int r = sr + it * 64;
            cp16(&a[r * AH + skc], A  + (size_t)(row0 + r) * K + k0 + skc);
            cp16(&b[r * AH + skc], Bp + (size_t)(col0 + r) * K + k0 + skc);
        }
    };

    const int ntiles = K >> 5;   // >= 4 in all uses
    stage(0, 0); asm volatile("cp.async.commit_group;");
    stage(1, 1); asm volatile("cp.async.commit_group;");
    stage(2, 2); asm volatile("cp.async.commit_group;");

    for (int kt = 0; kt < ntiles; kt++) {
        asm volatile("cp.async.wait_group 2;");
        __syncthreads();
        if (kt + 3 < ntiles) stage(kt + 3, (kt + 3) & 3);
        asm volatile("cp.async.commit_group;");

        const uint32_t aBuf = As0 + (kt & 3) * STG_BYTES;
        const uint32_t bBuf = Bs0 + (kt & 3) * STG_BYTES;
#pragma unroll
        for (int ks = 0; ks < 2; ks++) {
            const uint32_t kbB = ks * 32;
            unsigned a[2][4], b[8][2];
#pragma unroll
            for (int i = 0; i < 2; i++)
                LDSM4(a[i][0], a[i][1], a[i][2], a[i][3], aBuf + aOff[i] + kbB);
#pragma unroll
            for (int jp = 0; jp < 4; jp++)
                LDSM4(b[jp*2][0], b[jp*2][1], b[jp*2+1][0], b[jp*2+1][1],
                      bBuf + bOff[jp] + kbB);
#pragma unroll
            for (int i = 0; i < 2; i++)
#pragma unroll
                for (int j = 0; j < 8; j++)
                    mma_f16(c[i][j], a[i], b[j]);
        }
        __syncthreads();
    }

    if (MODE == 1 && col0 < 512) {
        const int colbase = col0 + wc * 64;
        // bias add
        float bv[16];
#pragma unroll
        for (int j = 0; j < 8; j++) {
            bv[j*2]   = biasA[colbase + j*8 + t*2];
            bv[j*2+1] = biasA[colbase + j*8 + t*2 + 1];
        }
#pragma unroll
        for (int i = 0; i < 2; i++)
#pragma unroll
            for (int j = 0; j < 8; j++) {
                c[i][j][0] += bv[j*2];   c[i][j][1] += bv[j*2+1];
                c[i][j][2] += bv[j*2];   c[i][j][3] += bv[j*2+1];
            }

        float cs[16];
#pragma unroll
        for (int m = 0; m < 16; m++) cs[m] = 0.f;

        // per-row softmax: 4 row instances (i, h2); row's 64 cols live in t-quad
#pragma unroll
        for (int i = 0; i < 2; i++)
#pragma unroll
            for (int h2 = 0; h2 < 2; h2++) {
                float mx = -1e30f;
#pragma unroll
                for (int j = 0; j < 8; j++)
                    mx = fmaxf(mx, fmaxf(c[i][j][h2*2], c[i][j][h2*2+1]));
                mx = fmaxf(mx, __shfl_xor_sync(0xffffffffu, mx, 1));
                mx = fmaxf(mx, __shfl_xor_sync(0xffffffffu, mx, 2));
                float s = 0.f;
#pragma unroll
                for (int j = 0; j < 8; j++) {
                    float e0 = __expf(c[i][j][h2*2]   - mx);
                    float e1 = __expf(c[i][j][h2*2+1] - mx);
                    c[i][j][h2*2] = e0; c[i][j][h2*2+1] = e1;
                    s += e0 + e1;
                }
                s += __shfl_xor_sync(0xffffffffu, s, 1);
                s += __shfl_xor_sync(0xffffffffu, s, 2);
                const float is = 1.0f / s;
                const size_t row = (size_t)(row0 + wr*32 + i*16 + h2*8 + g);
#pragma unroll
                for (int j = 0; j < 8; j++) {
                    __half2 h = __floats2half2_rn(c[i][j][h2*2]*is, c[i][j][h2*2+1]*is);
                    *(__half2*)(wOut + row * 512 + colbase + j*8 + t*2) = h;
                    float2 f = __half22float2(h);
                    cs[j*2] += f.x; cs[j*2+1] += f.y;
                }
            }

        // column sums: reduce over g lanes, then across warps via smem
#pragma unroll
        for (int m = 0; m < 16; m++) {
            cs[m] += __shfl_xor_sync(0xffffffffu, cs[m], 4);
            cs[m] += __shfl_xor_sync(0xffffffffu, cs[m], 8);
            cs[m] += __shfl_xor_sync(0xffffffffu, cs[m], 16);
        }
        float* npsum = (float*)smem;   // 4*128 floats; buffers dead
        if (lane < 4) {
#pragma unroll
            for (int j = 0; j < 8; j++) {
                npsum[wr*128 + wc*64 + j*8 + lane*2]     = cs[j*2];
                npsum[wr*128 + wc*64 + j*8 + lane*2 + 1] = cs[j*2+1];
            }
        }
        __syncthreads();
        if (tid < 128)
            npart[(size_t)blockIdx.y * 512 + col0 + tid] =
                npsum[tid] + npsum[128+tid] + npsum[256+tid] + npsum[384+tid];
    } else if (MODE == 1) {
        const int cg = col0 - 512 + wc * 64;
#pragma unroll
        for (int i = 0; i < 2; i++) {
            int rm = row0 + wr*32 + i*16 + g;
#pragma unroll
            for (int j = 0; j < 8; j++) {
                int cn = cg + j*8 + t*2;
                float b0 = biasB[cn], b1 = biasB[cn + 1];
                *(__half2*)(fxOut + (size_t)rm * 512 + cn) =
                    __floats2half2_rn(c[i][j][0] + b0, c[i][j][1] + b1);
                *(__half2*)(fxOut + (size_t)(rm + 8) * 512 + cn) =
                    __floats2half2_rn(c[i][j][2] + b0, c[i][j][3] + b1);
            }
        }
    } else {
        const int cg = col0 + wc * 64;
#pragma unroll
        for (int i = 0; i < 2; i++) {
            int rm = row0 + wr*32 + i*16 + g;
#pragma unroll
            for (int j = 0; j < 8; j++) {
                int cn = cg + j*8 + t*2;
                float b0 = biasA[cn], b1 = biasA[cn + 1];
                *(float2*)(outF + (size_t)rm * 512 + cn) =
                    make_float2(c[i][j][0] + b0, c[i][j][1] + b1);
                *(float2*)(outF + (size_t)(rm + 8) * 512 + cn) =
                    make_float2(c[i][j][2] + b0, c[i][j][3] + b1);
            }
        }
    }
}

// ============================================================
// norm reduce
// ============================================================
__global__ void norm_reduce_kernel(const float* __restrict__ npart,
                                   float* __restrict__ norm)
{
    int e = blockIdx.x * 256 + threadIdx.x;
    int b = e >> 9, hg = e & 511;
    float s = 0.f;
    for (int rb = 0; rb < 256; rb++)
        s += npart[((size_t)(b * 256 + rb)) * 512 + hg];
    norm[e] = s;
}

// ============================================================
// tokens partials (fp16 inputs, fp32 accum)
// ============================================================
__global__ __launch_bounds__(256) void tokpart_kernel(
    const __half* __restrict__ fx, const __half* __restrict__ w,
    float* __restrict__ part)
{
    __shared__ __half ws[2][32][64];
    __shared__ __half fs[2][32][64];
    const int chunk = blockIdx.x;
    const int bh = blockIdx.y;
    const int b = bh >> 3, h = bh & 7;
    const size_t rbase = (size_t)b * NN + (size_t)chunk * 512;

    const int tid = threadIdx.x;
    const int ty = tid >> 4, tx = tid & 15;

    float acc[4][4];
#pragma unroll
    for (int i = 0; i < 4; i++)
#pragma unroll
        for (int j = 0; j < 4; j++) acc[i][j] = 0.f;

    auto loadTile = [&](int kt, int buf) {
        int r = tid >> 3;
        int c8 = (tid & 7) * 8;
        size_t row = rbase + (size_t)kt * 32 + r;
        cp16(&ws[buf][r][c8], w  + row * 512 + h * 64 + c8);
        cp16(&fs[buf][r][c8], fx + row * 512 + h * 64 + c8);
    };

    loadTile(0, 0);
    asm volatile("cp.async.commit_group;");

    for (int kt = 0; kt < 16; kt++) {
        asm volatile("cp.async.wait_group 0;");
        __syncthreads();
        if (kt + 1 < 16) {
            loadTile(kt + 1, (kt + 1) & 1);
            asm volatile("cp.async.commit_group;");
        }
        const int buf = kt & 1;
#pragma unroll
        for (int k = 0; k < 32; k++) {
            const __half2* a2 = (const __half2*)&ws[buf][k][ty*4];
            const __half2* b2 = (const __half2*)&fs[buf][k][tx*4];
            float2 a01 = __half22float2(a2[0]);
            float2 a23 = __half22float2(a2[1]);
            float2 b01 = __half22float2(b2[0]);
            float2 b23 = __half22float2(b2[1]);
            float av[4] = {a01.x, a01.y, a23.x, a23.y};
            float bv[4] = {b01.x, b01.y, b23.x, b23.y};
#pragma unroll
            for (int i = 0; i < 4; i++)
#pragma unroll
                for (int j = 0; j < 4; j++)
                    acc[i][j] += av[i] * bv[j];
        }
        __syncthreads();
    }

    float* p = part + ((size_t)bh * TOK_CHUNKS + chunk) * 4096;
#pragma unroll
    for (int ig = 0; ig < 4; ig++) {
        float4 o = make_float4(acc[ig][0], acc[ig][1], acc[ig][2], acc[ig][3]);
        *(float4*)&p[(ty*4+ig)*64 + tx*4] = o;
    }
}

__global__ void tok_reduce_kernel(const float* __restrict__ part,
                                  float* __restrict__ tok)
{
    int idx = blockIdx.x * 256 + threadIdx.x;
    int bh = idx >> 12, gd = idx & 4095;
    float s = 0.f;
    for (int c = 0; c < TOK_CHUNKS; c++)
        s += part[((size_t)bh * TOK_CHUNKS + c) * 4096 + gd];
    tok[idx] = s;
}

// ============================================================
// tiny attention
// ============================================================
template<int NC>
__device__ __forceinline__ void row_gemm_cols(
    const float* __restrict__ xrow, int Kd,
    const float* __restrict__ W, const float* __restrict__ bias,
    float* __restrict__ outp, int c0)
{
    float acc[NC];
#pragma unroll
    for (int j = 0; j < NC; j++) acc[j] = bias[c0 + j];
    for (int d = 0; d < Kd; d++) {
        float xv = xrow[d];
        const float4* W4 = (const float4*)(W + (size_t)d * 64 + c0);
#pragma unroll
        for (int j4 = 0; j4 < NC/4; j4++) {
            float4 wv = W4[j4];
            acc[j4*4+0] += xv*wv.x; acc[j4*4+1] += xv*wv.y;
            acc[j4*4+2] += xv*wv.z; acc[j4*4+3] += xv*wv.w;
        }
    }
#pragma unroll
    for (int j = 0; j < NC; j++) outp[c0 + j] = acc[j];
}

__device__ __forceinline__ void attn_row(
    const float* __restrict__ qrow, const float* __restrict__ Kt,
    const float* __restrict__ Vt, float* __restrict__ o)
{
    float qr[64];
#pragma unroll
    for (int d = 0; d < 64; d++) qr[d] = qrow[d];
    float sc[64];
    float m = -1e30f;
    for (int j = 0; j < 64; j++) {
        const float4* kr = (const float4*)(Kt + j * 64);
        float a = 0.f;
#pragma unroll
        for (int d4 = 0; d4 < 16; d4++) {
            float4 kv = kr[d4];
            a += qr[d4*4]*kv.x + qr[d4*4+1]*kv.y + qr[d4*4+2]*kv.z + qr[d4*4+3]*kv.w;
        }
        sc[j] = a * 0.125f;
        m = fmaxf(m, sc[j]);
    }
    float s = 0.f;
#pragma unroll
    for (int j = 0; j < 64; j++) { sc[j] = expf(sc[j] - m); s += sc[j]; }
    float is = 1.0f / s;
#pragma unroll
    for (int d = 0; d < 64; d++) o[d] = 0.f;
    for (int j = 0; j < 64; j++) {
        float p = sc[j] * is;
        const float4* vr = (const float4*)(Vt + j * 64);
#pragma unroll
        for (int d4 = 0; d4 < 16; d4++) {
            float4 vv = vr[d4];
            o[d4*4+0] += p*vv.x; o[d4*4+1] += p*vv.y;
            o[d4*4+2] += p*vv.z; o[d4*4+3] += p*vv.w;
        }
    }
}

__global__ __launch_bounds__(256) void attn_kernel(
    const float* __restrict__ ctx,
    const float* __restrict__ Wq, const float* __restrict__ bq,
    const float* __restrict__ Wk, const float* __restrict__ bk,
    const float* __restrict__ Wv, const float* __restrict__ bv,
    const float* __restrict__ Wcq, const float* __restrict__ bcq,
    const float* __restrict__ Wck, const float* __restrict__ bck,
    const float* __restrict__ Wcv, const float* __restrict__ bcv,
    const float* __restrict__ smix,
    const float* __restrict__ tokens, const float* __restrict__ norm,
    float* __restrict__ ot)
{
    extern __shared__ float sm[];
    float* s_tok = sm;
    float* s_q   = sm + 4096;
    float* s_k   = sm + 2*4096;
    float* s_v   = sm + 3*4096;
    float* s_cq  = sm + 4*4096;
    float* s_ck  = sm + 5*4096;
    float* s_cv  = sm + 6*4096;

    const int bh = blockIdx.x;
    const int tid = threadIdx.x;

    for (int idx = tid; idx < 4096; idx += 256) {
        int row = idx >> 6;
        float inv = 1.0f / (norm[bh*64 + row] + EPS);
        s_tok[idx] = tokens[(size_t)bh*4096 + idx] * inv;
    }
    __syncthreads();

    {
        const int pid = tid >> 6;
        const int i   = tid & 63;
        const float* W; const float* bb; float* dst;
        if (pid == 0)      { W = Wq;  bb = bq;  dst = s_q;  }
        else if (pid == 1) { W = Wk;  bb = bk;  dst = s_k;  }
        else if (pid == 2) { W = Wv;  bb = bv;  dst = s_v;  }
        else               { W = Wcq; bb = bcq; dst = s_cq; }
        row_gemm_cols<64>(&s_tok[i*64], 64, W, bb, &dst[i*64], 0);
    }
    {
        const int mat = tid >> 7;
        const int sub = tid & 127;
        const int i   = sub >> 1;
        const int c0  = (sub & 1) * 32;
        const float* crow = ctx + ((size_t)bh*64 + i) * 256;
        if (mat == 0) row_gemm_cols<32>(crow, 256, Wck, bck, &s_ck[i*64], c0);
        else          row_gemm_cols<32>(crow, 256, Wcv, bcv, &s_cv[i*64], c0);
    }
    __syncthreads();

    if (tid < 64) {
        float o[64];
        attn_row(&s_q[tid*64], s_k, s_v, o);
#pragma unroll
        for (int d = 0; d < 64; d++) s_tok[tid*64 + d] = o[d];
    } else if (tid < 128) {
        const int i = tid - 64;
        float o[64];
        attn_row(&s_cq[i*64], s_ck, s_cv, o);
#pragma unroll
        for (int d = 0; d < 64; d++) s_cq[i*64 + d] = o[d];
    }
    __syncthreads();

    const float gmix = 1.0f / (1.0f + expf(-smix[0]));
    for (int idx = tid; idx < 4096; idx += 256)
        ot[(size_t)bh*4096 + idx] = gmix * s_tok[idx] + (1.0f - gmix) * s_cq[idx];
}

// ============================================================
// M^T[b][c][hg] = sum_d out_tok[b,hg,d] * Wo[h*64+d, c]  (fp16 out)
// ============================================================
__global__ __launch_bounds__(256) void m_kernel(
    const float* __restrict__ Wo, const float* __restrict__ ot,
    __half* __restrict__ MT)
{
    __shared__ float s_ot[4096];
    __shared__ float s_wo[64 * 128];
    const int bh = blockIdx.y;
    const int h = bh & 7, b = bh >> 3;
    const int c0 = blockIdx.x * 128;
    const int tid = threadIdx.x;

    for (int idx = tid; idx < 1024; idx += 256)
        ((float4*)s_ot)[idx] = ((const float4*)(ot + (size_t)bh * 4096))[idx];
    for (int idx = tid; idx < 2048; idx += 256) {
        int d = idx >> 5;
        int c4 = idx & 31;
        ((float4*)s_wo)[idx] = *(const float4*)(Wo + (size_t)(h*64 + d)*512 + c0 + c4*4);
    }
    __syncthreads();

    const int g0 = (tid >> 3) * 2;
    const int ct = (tid & 7) * 16;
    float acc[2][16];
#pragma unroll
    for (int g = 0; g < 2; g++)
#pragma unroll
        for (int c = 0; c < 16; c++) acc[g][c] = 0.f;

    for (int d = 0; d < 64; d++) {
        float a0 = s_ot[g0*64 + d];
        float a1 = s_ot[(g0+1)*64 + d];
#pragma unroll
        for (int c4 = 0; c4 < 4; c4++) {
            float4 wv = *(const float4*)&s_wo[d*128 + ct + c4*4];
            acc[0][c4*4+0]+=a0*wv.x; acc[0][c4*4+1]+=a0*wv.y; acc[0][c4*4+2]+=a0*wv.z; acc[0][c4*4+3]+=a0*wv.w;
            acc[1][c4*4+0]+=a1*wv.x; acc[1][c4*4+1]+=a1*wv.y; acc[1][c4*4+2]+=a1*wv.z; acc[1][c4*4+3]+=a1*wv.w;
        }
    }

#pragma unroll
    for (int g = 0; g < 2; g++) {
        int hg = h*64 + g0 + g;
#pragma unroll
        for (int c = 0; c < 16; c++)
            MT[(size_t)b * 262144 + (size_t)(c0 + ct + c) * 512 + hg] =
                __float2half_rn(acc[g][c]);
    }
}

// ============================================================
// host launcher
// ============================================================
extern "C" void kernel_launch(void* const* d_in, const int* in_sizes, int n_in,
                              void* d_out, int out_size)
{
    const float* x      = (const float*)d_in[0];
    const float* ctx    = (const float*)d_in[1];
    const float* Wx     = (const float*)d_in[2];
    const float* bx     = (const float*)d_in[3];
    const float* Wfx    = (const float*)d_in[4];
    const float* bfx    = (const float*)d_in[5];
    const float* Wslice = (const float*)d_in[6];
    const float* bslice = (const float*)d_in[7];
    const float* temp   = (const float*)d_in[8];
    const float* Wq     = (const float*)d_in[9];
    const float* bq     = (const float*)d_in[10];
    const float* Wk     = (const float*)d_in[11];
    const float* bk     = (const float*)d_in[12];
    const float* Wv     = (const float*)d_in[13];
    const float* bv     = (const float*)d_in[14];
    const float* Wcq    = (const float*)d_in[15];
    const float* bcq    = (const float*)d_in[16];
    const float* Wck    = (const float*)d_in[17];
    const float* bck    = (const float*)d_in[18];
    const float* Wcv    = (const float*)d_in[19];
    const float* bcv    = (const float*)d_in[20];
    const float* smix   = (const float*)d_in[21];
    const float* Wo     = (const float*)d_in[22];
    const float* bo     = (const float*)d_in[23];
    float* out = (float*)d_out;

    void *p;
    cudaGetSymbolAddress(&p, g_xh);    __half* xh    = (__half*)p;
    cudaGetSymbolAddress(&p, g_wh);    __half* wh    = (__half*)p;
    cudaGetSymbolAddress(&p, g_fxh);   __half* fxh   = (__half*)p;
    cudaGetSymbolAddress(&p, g_npart); float* npart  = (float*)p;
    cudaGetSymbolAddress(&p, g_norm);  float* norm   = (float*)p;
    cudaGetSymbolAddress(&p, g_tpart); float* tpart  = (float*)p;
    cudaGetSymbolAddress(&p, g_tok);   float* tok    = (float*)p;
    cudaGetSymbolAddress(&p, g_ot);    float* ot     = (float*)p;
    cudaGetSymbolAddress(&p, g_MTh);   __half* MTh   = (__half*)p;
    cudaGetSymbolAddress(&p, g_WcatTh);__half* WcatT = (__half*)p;
    cudaGetSymbolAddress(&p, g_bcomb); float* bcomb  = (float*)p;

    cudaFuncSetAttribute(f16_gemm<1>, cudaFuncAttributeMaxDynamicSharedMemorySize, SM_GEMM);
    cudaFuncSetAttribute(f16_gemm<0>, cudaFuncAttributeMaxDynamicSharedMemorySize, SM_GEMM);
    cudaFuncSetAttribute(attn_kernel, cudaFuncAttributeMaxDynamicSharedMemorySize, 7*4096*4);

    // 0: x -> fp16; assemble WcatT^T fp16; bcomb
    round_f16_kernel<<<2048, 256>>>(x, xh, ROWS*CC/4);
    wfx_cat_kernel<<<1024, 256>>>(Wfx, WcatT);
    wcomb_kernel<<<512, 512>>>(Wx, Wslice, temp, bx, bslice, WcatT, bcomb);
    // 1: merged fp16 GEMM: softmax->wh(+npart) | bias->fxh
    f16_gemm<1><<<dim3(8, 512), 256, SM_GEMM>>>(
        xh, WcatT, bcomb, bfx, wh, fxh, nullptr, npart, CC, 0, 0);
    // 2: norm
    norm_reduce_kernel<<<4, 256>>>(npart, norm);
    // 3: tokens = w^T @ fx
    tokpart_kernel<<<dim3(TOK_CHUNKS, 16), 256>>>(fxh, wh, tpart);
    tok_reduce_kernel<<<256, 256>>>(tpart, tok);
    // 4: tiny attention
    attn_kernel<<<16, 256, 7*4096*4>>>(ctx, Wq, bq, Wk, bk, Wv, bv,
                                       Wcq, bcq, Wck, bck, Wcv, bcv,
                                       smix, tok, norm, ot);
    // 5: fold out_tok @ Wo -> M^T (fp16)
    m_kernel<<<dim3(4, 16), 256>>>(Wo, ot, MTh);
    // 6: out = w @ M[b] + bo (fp16 GEMM, B per-batch)
    f16_gemm<0><<<dim3(4, 512), 256, SM_GEMM>>>(
        wh, MTh, bo, nullptr, nullptr, nullptr, out, nullptr, INNER, NN, 512*512);
}

// round 11
// speedup vs baseline: 3.1336x; 1.1585x over previous
#include <cuda_runtime.h>
#include <cuda_fp16.h>
#include <math.h>
#include <stdint.h>

// ---------------- problem constants ----------------
#define BB 2
#define NN 32768
#define CC 512
#define HH 8
#define DH 64
#define GG 64
#define CD 256
#define ROWS (BB*NN)          // 65536
#define INNER (HH*DH)         // 512
#define EPS 1e-5f
#define TOK_CHUNKS 16         // 2048 tokens per chunk (MMA tokpart)

// ---------------- scratch ----------------
__device__ __half g_xh   [ROWS * CC];
__device__ __half g_wh   [ROWS * INNER];
__device__ __half g_fxh  [ROWS * INNER];
__device__ float  g_npart[512 * 512];
__device__ float  g_norm [BB * HH * GG];
__device__ float  g_tpart[16 * TOK_CHUNKS * 4096];
__device__ float  g_tok  [16 * 4096];
__device__ float  g_ot   [16 * 4096];
__device__ __half g_MTh  [BB * 512 * 512];
__device__ __half g_WcatTh[1024 * 512];
__device__ float  g_bcomb[512];

// ---------------- helpers ----------------
__device__ __forceinline__ void cp16(void* dst, const void* src) {
    unsigned d = (unsigned)__cvta_generic_to_shared(dst);
    asm volatile("cp.async.cg.shared.global [%0], [%1], 16;" :: "r"(d), "l"(src));
}
__device__ __forceinline__ void mma_f16(float* c, const unsigned* a, const unsigned* b) {
    asm volatile(
        "mma.sync.aligned.m16n8k16.row.col.f32.f16.f16.f32 "
        "{%0,%1,%2,%3},{%4,%5,%6,%7},{%8,%9},{%0,%1,%2,%3};"
        : "+f"(c[0]), "+f"(c[1]), "+f"(c[2]), "+f"(c[3])
        : "r"(a[0]), "r"(a[1]), "r"(a[2]), "r"(a[3]), "r"(b[0]), "r"(b[1]));
}
#define LDSM4(r0, r1, r2, r3, addr) \
    asm volatile("ldmatrix.sync.aligned.m8n8.x4.shared.b16 {%0,%1,%2,%3}, [%4];" \
        : "=r"(r0), "=r"(r1), "=r"(r2), "=r"(r3) : "r"(addr))
#define LDSM4T(r0, r1, r2, r3, addr) \
    asm volatile("ldmatrix.sync.aligned.m8n8.x4.trans.shared.b16 {%0,%1,%2,%3}, [%4];" \
        : "=r"(r0), "=r"(r1), "=r"(r2), "=r"(r3) : "r"(addr))

// ============================================================
// x (fp32) -> xh (fp16)
// ============================================================
__global__ void round_f16_kernel(const float* __restrict__ in,
                                 __half* __restrict__ out, int n4)
{
    int idx = blockIdx.x * blockDim.x + threadIdx.x;
    int stride = gridDim.x * blockDim.x;
    for (; idx < n4; idx += stride) {
        float4 v = ((const float4*)in)[idx];
        __half2* o = (__half2*)out + idx * 2;
        o[0] = __floats2half2_rn(v.x, v.y);
        o[1] = __floats2half2_rn(v.z, v.w);
    }
}

// Wfx -> WcatTh rows 512..1023 (transposed [n][k], fp16)
__global__ void wfx_cat_kernel(const float* __restrict__ Wfx,
                               __half* __restrict__ WcatT)
{
    int idx = blockIdx.x * blockDim.x + threadIdx.x;
    int k = idx >> 9;
    int n = idx & 511;
    WcatT[(size_t)(512 + n) * 512 + k] = __float2half_rn(Wfx[(size_t)k * 512 + n]);
}

// Wcomb -> WcatTh rows 0..511 (transposed, fp16), bcomb in block 0
__global__ __launch_bounds__(512) void wcomb_kernel(
    const float* __restrict__ Wx, const float* __restrict__ Wslice,
    const float* __restrict__ temp,
    const float* __restrict__ bx, const float* __restrict__ bslice,
    __half* __restrict__ WcatT, float* __restrict__ bcomb)
{
    __shared__ float sWs[4096];
    __shared__ float sx[512];
    __shared__ float sit[8];
    const int tid = threadIdx.x;
    const int cr = blockIdx.x;
    for (int i = tid; i < 4096; i += 512) sWs[i] = Wslice[i];
    sx[tid] = Wx[(size_t)cr * 512 + tid];
    if (tid < 8) {
        float tv = temp[tid];
        sit[tid] = 1.0f / fminf(fmaxf(tv, 0.1f), 5.0f);
    }
    __syncthreads();
    const int h = tid >> 6, gg = tid & 63;
    float acc = 0.f;
#pragma unroll 8
    for (int d = 0; d < 64; d++)
        acc += sx[h*64 + d] * sWs[d*64 + gg];
    WcatT[(size_t)tid * 512 + cr] = __float2half_rn(acc * sit[h]);

    if (blockIdx.x == 0) {
        float acc2 = bslice[gg];
        for (int d = 0; d < 64; d++)
            acc2 += bx[h*64 + d] * sWs[d*64 + gg];
        bcomb[tid] = acc2 * sit[h];
    }
}

// ============================================================
// FP16 GEMM 128x128x32, 8 warps (warp tile 32x64), 4-stage cp.async,
// ldmatrix fragment loads, register-resident softmax epilogue.
// ============================================================
#define AH 40     // padded k-stride (halves), 80B rows
#define STG_BYTES 10240
#define SM_GEMM (8 * STG_BYTES)   // 81920

template<int MODE>
__global__ __launch_bounds__(256, 2) void f16_gemm(
    const __half* __restrict__ A, const __half* __restrict__ BT,
    const float* __restrict__ biasA, const float* __restrict__ biasB,
    __half* __restrict__ wOut, __half* __restrict__ fxOut,
    float* __restrict__ outF, float* __restrict__ npart,
    int K, int bRowsPerBatch, int bMatStride)
{
    extern __shared__ char smem[];

    const int tid  = threadIdx.x;
    const int lane = tid & 31;
    const int warp = tid >> 5;
    const int wr   = warp >> 1;
    const int wc   = warp & 1;
    const int row0 = blockIdx.y * 128;
    const int col0 = blockIdx.x * 128;

    const __half* Bp = BT;
    if (bRowsPerBatch) Bp += (size_t)(row0 / bRowsPerBatch) * (size_t)bMatStride;

    float c[2][8][4];
#pragma unroll
    for (int i = 0; i < 2; i++)
#pragma unroll
        for (int j = 0; j < 8; j++)
#pragma unroll
            for (int r = 0; r < 4; r++) c[i][j][r] = 0.f;

    const int g = lane >> 2;
    const int t = lane & 3;

    const uint32_t As0 = (uint32_t)__cvta_generic_to_shared(smem);
    const uint32_t Bs0 = As0 + 4 * STG_BYTES;
    uint32_t aOff[2], bOff[4];
#pragma unroll
    for (int i = 0; i < 2; i++)
        aOff[i] = (uint32_t)(((wr*32 + i*16 + (lane & 15)) * AH + ((lane >> 4) << 3)) * 2);
#pragma unroll
    for (int jp = 0; jp < 4; jp++)
        bOff[jp] = (uint32_t)(((wc*64 + jp*16 + ((lane >> 4) << 3) + (lane & 7)) * AH
                               + (((lane >> 3) & 1) << 3)) * 2);

    const int sr  = tid >> 2;
    const int skc = (tid & 3) * 8;

    auto stage = [&](int kt, int buf) {
        __half* a = (__half*)(smem + buf * STG_BYTES);
        __half* b = (__half*)(smem + 4 * STG_BYTES + buf * STG_BYTES);
        const int k0 = kt << 5;
#pragma unroll
        for (int it = 0; it < 2; it++) {
            int r = sr + it * 64;
            cp16(&a[r * AH + skc], A  + (size_t)(row0 + r) * K + k0 + skc);
            cp16(&b[r * AH + skc], Bp + (size_t)(col0 + r) * K + k0 + skc);
        }
    };

    const int ntiles = K >> 5;
    stage(0, 0); asm volatile("cp.async.commit_group;");
    stage(1, 1); asm volatile("cp.async.commit_group;");
    stage(2, 2); asm volatile("cp.async.commit_group;");

    for (int kt = 0; kt < ntiles; kt++) {
        asm volatile("cp.async.wait_group 2;");
        __syncthreads();
        if (kt + 3 < ntiles) stage(kt + 3, (kt + 3) & 3);
        asm volatile("cp.async.commit_group;");

        const uint32_t aBuf = As0 + (kt & 3) * STG_BYTES;
        const uint32_t bBuf = Bs0 + (kt & 3) * STG_BYTES;
#pragma unroll
        for (int ks = 0; ks < 2; ks++) {
            const uint32_t kbB = ks * 32;
            unsigned a[2][4], b[8][2];
#pragma unroll
            for (int i = 0; i < 2; i++)
                LDSM4(a[i][0], a[i][1], a[i][2], a[i][3], aBuf + aOff[i] + kbB);
#pragma unroll
            for (int jp = 0; jp < 4; jp++)
                LDSM4(b[jp*2][0], b[jp*2][1], b[jp*2+1][0], b[jp*2+1][1],
                      bBuf + bOff[jp] + kbB);
#pragma unroll
            for (int i = 0; i < 2; i++)
#pragma unroll
                for (int j = 0; j < 8; j++)
                    mma_f16(c[i][j], a[i], b[j]);
        }
        __syncthreads();
    }

    if (MODE == 1 && col0 < 512) {
        const int colbase = col0 + wc * 64;
        float bv[16];
#pragma unroll
        for (int j = 0; j < 8; j++) {
            bv[j*2]   = biasA[colbase + j*8 + t*2];
            bv[j*2+1] = biasA[colbase + j*8 + t*2 + 1];
        }
#pragma unroll
        for (int i = 0; i < 2; i++)
#pragma unroll
            for (int j = 0; j < 8; j++) {
                c[i][j][0] += bv[j*2];   c[i][j][1] += bv[j*2+1];
                c[i][j][2] += bv[j*2];   c[i][j][3] += bv[j*2+1];
            }

        float cs[16];
#pragma unroll
        for (int m = 0; m < 16; m++) cs[m] = 0.f;

#pragma unroll
        for (int i = 0; i < 2; i++)
#pragma unroll
            for (int h2 = 0; h2 < 2; h2++) {
                float mx = -1e30f;
#pragma unroll
                for (int j = 0; j < 8; j++)
                    mx = fmaxf(mx, fmaxf(c[i][j][h2*2], c[i][j][h2*2+1]));
                mx = fmaxf(mx, __shfl_xor_sync(0xffffffffu, mx, 1));
                mx = fmaxf(mx, __shfl_xor_sync(0xffffffffu, mx, 2));
                float s = 0.f;
#pragma unroll
                for (int j = 0; j < 8; j++) {
                    float e0 = __expf(c[i][j][h2*2]   - mx);
                    float e1 = __expf(c[i][j][h2*2+1] - mx);
                    c[i][j][h2*2] = e0; c[i][j][h2*2+1] = e1;
                    s += e0 + e1;
                }
                s += __shfl_xor_sync(0xffffffffu, s, 1);
                s += __shfl_xor_sync(0xffffffffu, s, 2);
                const float is = 1.0f / s;
                const size_t row = (size_t)(row0 + wr*32 + i*16 + h2*8 + g);
#pragma unroll
                for (int j = 0; j < 8; j++) {
                    __half2 h = __floats2half2_rn(c[i][j][h2*2]*is, c[i][j][h2*2+1]*is);
                    *(__half2*)(wOut + row * 512 + colbase + j*8 + t*2) = h;
                    float2 f = __half22float2(h);
                    cs[j*2] += f.x; cs[j*2+1] += f.y;
                }
            }

#pragma unroll
        for (int m = 0; m < 16; m++) {
            cs[m] += __shfl_xor_sync(0xffffffffu, cs[m], 4);
            cs[m] += __shfl_xor_sync(0xffffffffu, cs[m], 8);
            cs[m] += __shfl_xor_sync(0xffffffffu, cs[m], 16);
        }
        float* npsum = (float*)smem;
        if (lane < 4) {
#pragma unroll
            for (int j = 0; j < 8; j++) {
                npsum[wr*128 + wc*64 + j*8 + lane*2]     = cs[j*2];
                npsum[wr*128 + wc*64 + j*8 + lane*2 + 1] = cs[j*2+1];
            }
        }
        __syncthreads();
        if (tid < 128)
            npart[(size_t)blockIdx.y * 512 + col0 + tid] =
                npsum[tid] + npsum[128+tid] + npsum[256+tid] + npsum[384+tid];
    } else if (MODE == 1) {
        const int cg = col0 - 512 + wc * 64;
#pragma unroll
        for (int i = 0; i < 2; i++) {
            int rm = row0 + wr*32 + i*16 + g;
#pragma unroll
            for (int j = 0; j < 8; j++) {
                int cn = cg + j*8 + t*2;
                float b0 = biasB[cn], b1 = biasB[cn + 1];
                *(__half2*)(fxOut + (size_t)rm * 512 + cn) =
                    __floats2half2_rn(c[i][j][0] + b0, c[i][j][1] + b1);
                *(__half2*)(fxOut + (size_t)(rm + 8) * 512 + cn) =
                    __floats2half2_rn(c[i][j][2] + b0, c[i][j][3] + b1);
            }
        }
    } else {
        const int cg = col0 + wc * 64;
#pragma unroll
        for (int i = 0; i < 2; i++) {
            int rm = row0 + wr*32 + i*16 + g;
#pragma unroll
            for (int j = 0; j < 8; j++) {
                int cn = cg + j*8 + t*2;
                float b0 = biasA[cn], b1 = biasA[cn + 1];
                *(float2*)(outF + (size_t)rm * 512 + cn) =
                    make_float2(c[i][j][0] + b0, c[i][j][1] + b1);
                *(float2*)(outF + (size_t)(rm + 8) * 512 + cn) =
                    make_float2(c[i][j][2] + b0, c[i][j][3] + b1);
            }
        }
    }
}

// ============================================================
// norm reduce
// ============================================================
__global__ void norm_reduce_kernel(const float* __restrict__ npart,
                                   float* __restrict__ norm)
{
    int e = blockIdx.x * 256 + threadIdx.x;
    int b = e >> 9, hg = e & 511;
    float s = 0.f;
    for (int rb = 0; rb < 256; rb++)
        s += npart[((size_t)(b * 256 + rb)) * 512 + hg];
    norm[e] = s;
}

// ============================================================
// tokens partials via tensor cores:
// tpart[bh][chunk] (64x64) = w_chunk^T (64x2048) @ fx_chunk (2048x64)
// Both operands stored [token][64]; fragments via ldmatrix.trans.
// 8 warps: warp = wm*2+wn covers m16 x n32. Double-buffered 128-token tiles.
// ============================================================
#define WT 72                        // padded stride (halves)
#define TPT_TILE_H (128 * WT)        // halves per tile: 9216
#define TPT_SMEM (4 * TPT_TILE_H * 2) // w0,w1,f0,f1 = 73728 B

__global__ __launch_bounds__(256) void tokpart_mma_kernel(
    const __half* __restrict__ fx, const __half* __restrict__ w,
    float* __restrict__ part)
{
    extern __shared__ char smem[];
    const int chunk = blockIdx.x;
    const int bh = blockIdx.y;
    const int b = bh >> 3, h = bh & 7;
    const size_t rbase = (size_t)b * NN + (size_t)chunk * 2048;

    const int tid  = threadIdx.x;
    const int lane = tid & 31;
    const int warp = tid >> 5;
    const int wm   = warp >> 1;     // 0..3: m16 tile (g dim)
    const int wn   = warp & 1;      // 0..1: n32 half (d dim)

    const uint32_t S0 = (uint32_t)__cvta_generic_to_shared(smem);
    // halves offsets: w buf: buf*9216 ; fx buf: 18432 + buf*9216

    float c[4][4];
#pragma unroll
    for (int nj = 0; nj < 4; nj++)
#pragma unroll
        for (int r = 0; r < 4; r++) c[nj][r] = 0.f;

    // ldmatrix.trans per-lane byte offsets (within a tile, ks=0)
    // A (w): groups: (k-lo,m-lo),(k-lo,m-hi),(k-hi,m-lo),(k-hi,m-hi)
    const uint32_t aOff = (uint32_t)(((((lane >> 4) << 3) + (lane & 7)) * WT
                           + wm*16 + (((lane >> 3) & 1) << 3)) * 2);
    // B (fx): LDSM p: groups: (k-lo,n0),(k-hi,n0),(k-lo,n8),(k-hi,n8)
    uint32_t bOff[2];
#pragma unroll
    for (int p2 = 0; p2 < 2; p2++)
        bOff[p2] = (uint32_t)((((((lane >> 3) & 1) << 3) + (lane & 7)) * WT
                    + wn*32 + p2*16 + ((lane >> 4) << 3)) * 2);

    auto stage = [&](int kt, int buf) {
        __half* wsb = (__half*)smem + buf * TPT_TILE_H;
        __half* fsb = (__half*)smem + 2 * TPT_TILE_H + buf * TPT_TILE_H;
#pragma unroll
        for (int it = 0; it < 4; it++) {
            int s = tid + it * 256;          // 0..1023
            int r = s >> 3;                  // 0..127
            int c8 = (s & 7) * 8;
            size_t row = rbase + (size_t)kt * 128 + r;
            cp16(&wsb[r * WT + c8], w  + row * 512 + h * 64 + c8);
            cp16(&fsb[r * WT + c8], fx + row * 512 + h * 64 + c8);
        }
    };

    stage(0, 0);
    asm volatile("cp.async.commit_group;");

    for (int kt = 0; kt < 16; kt++) {
        asm volatile("cp.async.wait_group 0;");
        __syncthreads();
        if (kt + 1 < 16) {
            stage(kt + 1, (kt + 1) & 1);
            asm volatile("cp.async.commit_group;");
        }
        const int buf = kt & 1;
        const uint32_t wBuf = S0 + buf * TPT_TILE_H * 2;
        const uint32_t fBuf = S0 + (2 + buf) * TPT_TILE_H * 2;
#pragma unroll
        for (int ks = 0; ks < 8; ks++) {
            const uint32_t ksB = (uint32_t)(ks * 16 * WT * 2);   // 2304 B per k16
            unsigned a[4], bb[4][2];
            LDSM4T(a[0], a[1], a[2], a[3], wBuf + aOff + ksB);
            LDSM4T(bb[0][0], bb[0][1], bb[1][0], bb[1][1], fBuf + bOff[0] + ksB);
            LDSM4T(bb[2][0], bb[2][1], bb[3][0], bb[3][1], fBuf + bOff[1] + ksB);
#pragma unroll
            for (int nj = 0; nj < 4; nj++)
                mma_f16(c[nj], a, bb[nj]);
        }
        __syncthreads();
    }

    // epilogue: C[m=g][n=d]; thread (g4=lane>>2, t=lane&3)
    const int g4 = lane >> 2;
    const int t  = lane & 3;
    float* p = part + ((size_t)bh * TOK_CHUNKS + chunk) * 4096;
#pragma unroll
    for (int nj = 0; nj < 4; nj++) {
        int col = wn*32 + nj*8 + t*2;
        *(float2*)&p[(wm*16 + g4) * 64 + col]     = make_float2(c[nj][0], c[nj][1]);
        *(float2*)&p[(wm*16 + g4 + 8) * 64 + col] = make_float2(c[nj][2], c[nj][3]);
    }
}

__global__ void tok_reduce_kernel(const float* __restrict__ part,
                                  float* __restrict__ tok)
{
    int idx = blockIdx.x * 256 + threadIdx.x;
    int bh = idx >> 12, gd = idx & 4095;
    float s = 0.f;
    for (int c = 0; c < TOK_CHUNKS; c++)
        s += part[((size_t)bh * TOK_CHUNKS + c) * 4096 + gd];
    tok[idx] = s;
}

// ============================================================
// tiny attention
// ============================================================
template<int NC>
__device__ __forceinline__ void row_gemm_cols(
    const float* __restrict__ xrow, int Kd,
    const float* __restrict__ W, const float* __restrict__ bias,
    float* __restrict__ outp, int c0)
{
    float acc[NC];
#pragma unroll
    for (int j = 0; j < NC; j++) acc[j] = bias[c0 + j];
    for (int d = 0; d < Kd; d++) {
        float xv = xrow[d];
        const float4* W4 = (const float4*)(W + (size_t)d * 64 + c0);
#pragma unroll
        for (int j4 = 0; j4 < NC/4; j4++) {
            float4 wv = W4[j4];
            acc[j4*4+0] += xv*wv.x; acc[j4*4+1] += xv*wv.y;
            acc[j4*4+2] += xv*wv.z; acc[j4*4+3] += xv*wv.w;
        }
    }
#pragma unroll
    for (int j = 0; j < NC; j++) outp[c0 + j] = acc[j];
}

__device__ __forceinline__ void attn_row(
    const float* __restrict__ qrow, const float* __restrict__ Kt,
    const float* __restrict__ Vt, float* __restrict__ o)
{
    float qr[64];
#pragma unroll
    for (int d = 0; d < 64; d++) qr[d] = qrow[d];
    float sc[64];
    float m = -1e30f;
    for (int j = 0; j < 64; j++) {
        const float4* kr = (const float4*)(Kt + j * 64);
        float a = 0.f;
#pragma unroll
        for (int d4 = 0; d4 < 16; d4++) {
            float4 kv = kr[d4];
            a += qr[d4*4]*kv.x + qr[d4*4+1]*kv.y + qr[d4*4+2]*kv.z + qr[d4*4+3]*kv.w;
        }
        sc[j] = a * 0.125f;
        m = fmaxf(m, sc[j]);
    }
    float s = 0.f;
#pragma unroll
    for (int j = 0; j < 64; j++) { sc[j] = expf(sc[j] - m); s += sc[j]; }
    float is = 1.0f / s;
#pragma unroll
    for (int d = 0; d < 64; d++) o[d] = 0.f;
    for (int j = 0; j < 64; j++) {
        float p = sc[j] * is;
        const float4* vr = (const float4*)(Vt + j * 64);
#pragma unroll
        for (int d4 = 0; d4 < 16; d4++) {
            float4 vv = vr[d4];
            o[d4*4+0] += p*vv.x; o[d4*4+1] += p*vv.y;
            o[d4*4+2] += p*vv.z; o[d4*4+3] += p*vv.w;
        }
    }
}

__global__ __launch_bounds__(256) void attn_kernel(
    const float* __restrict__ ctx,
    const float* __restrict__ Wq, const float* __restrict__ bq,
    const float* __restrict__ Wk, const float* __restrict__ bk,
    const float* __restrict__ Wv, const float* __restrict__ bv,
    const float* __restrict__ Wcq, const float* __restrict__ bcq,
    const float* __restrict__ Wck, const float* __restrict__ bck,
    const float* __restrict__ Wcv, const float* __restrict__ bcv,
    const float* __restrict__ smix,
    const float* __restrict__ tokens, const float* __restrict__ norm,
    float* __restrict__ ot)
{
    extern __shared__ float sm[];
    float* s_tok = sm;
    float* s_q   = sm + 4096;
    float* s_k   = sm + 2*4096;
    float* s_v   = sm + 3*4096;
    float* s_cq  = sm + 4*4096;
    float* s_ck  = sm + 5*4096;
    float* s_cv  = sm + 6*4096;

    const int bh = blockIdx.x;
    const int tid = threadIdx.x;

    for (int idx = tid; idx < 4096; idx += 256) {
        int row = idx >> 6;
        float inv = 1.0f / (norm[bh*64 + row] + EPS);
        s_tok[idx] = tokens[(size_t)bh*4096 + idx] * inv;
    }
    __syncthreads();

    {
        const int pid = tid >> 6;
        const int i   = tid & 63;
        const float* W; const float* bb; float* dst;
        if (pid == 0)      { W = Wq;  bb = bq;  dst = s_q;  }
        else if (pid == 1) { W = Wk;  bb = bk;  dst = s_k;  }
        else if (pid == 2) { W = Wv;  bb = bv;  dst = s_v;  }
        else               { W = Wcq; bb = bcq; dst = s_cq; }
        row_gemm_cols<64>(&s_tok[i*64], 64, W, bb, &dst[i*64], 0);
    }
    {
        const int mat = tid >> 7;
        const int sub = tid & 127;
        const int i   = sub >> 1;
        const int c0  = (sub & 1) * 32;
        const float* crow = ctx + ((size_t)bh*64 + i) * 256;
        if (mat == 0) row_gemm_cols<32>(crow, 256, Wck, bck, &s_ck[i*64], c0);
        else          row_gemm_cols<32>(crow, 256, Wcv, bcv, &s_cv[i*64], c0);
    }
    __syncthreads();

    if (tid < 64) {
        float o[64];
        attn_row(&s_q[tid*64], s_k, s_v, o);
#pragma unroll
        for (int d = 0; d < 64; d++) s_tok[tid*64 + d] = o[d];
    } else if (tid < 128) {
        const int i = tid - 64;
        float o[64];
        attn_row(&s_cq[i*64], s_ck, s_cv, o);
#pragma unroll
        for (int d = 0; d < 64; d++) s_cq[i*64 + d] = o[d];
    }
    __syncthreads();

    const float gmix = 1.0f / (1.0f + expf(-smix[0]));
    for (int idx = tid; idx < 4096; idx += 256)
        ot[(size_t)bh*4096 + idx] = gmix * s_tok[idx] + (1.0f - gmix) * s_cq[idx];
}

// ============================================================
// M^T[b][c][hg] = sum_d out_tok[b,hg,d] * Wo[h*64+d, c]  (fp16 out)
// ============================================================
__global__ __launch_bounds__(256) void m_kernel(
    const float* __restrict__ Wo, const float* __restrict__ ot,
    __half* __restrict__ MT)
{
    __shared__ float s_ot[4096];
    __shared__ float s_wo[64 * 128];
    const int bh = blockIdx.y;
    const int h = bh & 7, b = bh >> 3;
    const int c0 = blockIdx.x * 128;
    const int tid = threadIdx.x;

    for (int idx = tid; idx < 1024; idx += 256)
        ((float4*)s_ot)[idx] = ((const float4*)(ot + (size_t)bh * 4096))[idx];
    for (int idx = tid; idx < 2048; idx += 256) {
        int d = idx >> 5;
        int c4 = idx & 31;
        ((float4*)s_wo)[idx] = *(const float4*)(Wo + (size_t)(h*64 + d)*512 + c0 + c4*4);
    }
    __syncthreads();

    const int g0 = (tid >> 3) * 2;
    const int ct = (tid & 7) * 16;
    float acc[2][16];
#pragma unroll
    for (int g = 0; g < 2; g++)
#pragma unroll
        for (int c = 0; c < 16; c++) acc[g][c] = 0.f;

    for (int d = 0; d < 64; d++) {
        float a0 = s_ot[g0*64 + d];
        float a1 = s_ot[(g0+1)*64 + d];
#pragma unroll
        for (int c4 = 0; c4 < 4; c4++) {
            float4 wv = *(const float4*)&s_wo[d*128 + ct + c4*4];
            acc[0][c4*4+0]+=a0*wv.x; acc[0][c4*4+1]+=a0*wv.y; acc[0][c4*4+2]+=a0*wv.z; acc[0][c4*4+3]+=a0*wv.w;
            acc[1][c4*4+0]+=a1*wv.x; acc[1][c4*4+1]+=a1*wv.y; acc[1][c4*4+2]+=a1*wv.z; acc[1][c4*4+3]+=a1*wv.w;
        }
    }

#pragma unroll
    for (int g = 0; g < 2; g++) {
        int hg = h*64 + g0 + g;
#pragma unroll
        for (int c = 0; c < 16; c++)
            MT[(size_t)b * 262144 + (size_t)(c0 + ct + c) * 512 + hg] =
                __float2half_rn(acc[g][c]);
    }
}

// ============================================================
// host launcher
// ============================================================
extern "C" void kernel_launch(void* const* d_in, const int* in_sizes, int n_in,
                              void* d_out, int out_size)
{
    const float* x      = (const float*)d_in[0];
    const float* ctx    = (const float*)d_in[1];
    const float* Wx     = (const float*)d_in[2];
    const float* bx     = (const float*)d_in[3];
    const float* Wfx    = (const float*)d_in[4];
    const float* bfx    = (const float*)d_in[5];
    const float* Wslice = (const float*)d_in[6];
    const float* bslice = (const float*)d_in[7];
    const float* temp   = (const float*)d_in[8];
    const float* Wq     = (const float*)d_in[9];
    const float* bq     = (const float*)d_in[10];
    const float* Wk     = (const float*)d_in[11];
    const float* bk     = (const float*)d_in[12];
    const float* Wv     = (const float*)d_in[13];
    const float* bv     = (const float*)d_in[14];
    const float* Wcq    = (const float*)d_in[15];
    const float* bcq    = (const float*)d_in[16];
    const float* Wck    = (const float*)d_in[17];
    const float* bck    = (const float*)d_in[18];
    const float* Wcv    = (const float*)d_in[19];
    const float* bcv    = (const float*)d_in[20];
    const float* smix   = (const float*)d_in[21];
    const float* Wo     = (const float*)d_in[22];
    const float* bo     = (const float*)d_in[23];
    float* out = (float*)d_out;

    void *p;
    cudaGetSymbolAddress(&p, g_xh);    __half* xh    = (__half*)p;
    cudaGetSymbolAddress(&p, g_wh);    __half* wh    = (__half*)p;
    cudaGetSymbolAddress(&p, g_fxh);   __half* fxh   = (__half*)p;
    cudaGetSymbolAddress(&p, g_npart); float* npart  = (float*)p;
    cudaGetSymbolAddress(&p, g_norm);  float* norm   = (float*)p;
    cudaGetSymbolAddress(&p, g_tpart); float* tpart  = (float*)p;
    cudaGetSymbolAddress(&p, g_tok);   float* tok    = (float*)p;
    cudaGetSymbolAddress(&p, g_ot);    float* ot     = (float*)p;
    cudaGetSymbolAddress(&p, g_MTh);   __half* MTh   = (__half*)p;
    cudaGetSymbolAddress(&p, g_WcatTh);__half* WcatT = (__half*)p;
    cudaGetSymbolAddress(&p, g_bcomb); float* bcomb  = (float*)p;

    cudaFuncSetAttribute(f16_gemm<1>, cudaFuncAttributeMaxDynamicSharedMemorySize, SM_GEMM);
    cudaFuncSetAttribute(f16_gemm<0>, cudaFuncAttributeMaxDynamicSharedMemorySize, SM_GEMM);
    cudaFuncSetAttribute(tokpart_mma_kernel, cudaFuncAttributeMaxDynamicSharedMemorySize, TPT_SMEM);
    cudaFuncSetAttribute(attn_kernel, cudaFuncAttributeMaxDynamicSharedMemorySize, 7*4096*4);

    // 0: x -> fp16; assemble WcatT^T fp16; bcomb
    round_f16_kernel<<<2048, 256>>>(x, xh, ROWS*CC/4);
    wfx_cat_kernel<<<1024, 256>>>(Wfx, WcatT);
    wcomb_kernel<<<512, 512>>>(Wx, Wslice, temp, bx, bslice, WcatT, bcomb);
    // 1: merged fp16 GEMM: softmax->wh(+npart) | bias->fxh
    f16_gemm<1><<<dim3(8, 512), 256, SM_GEMM>>>(
        xh, WcatT, bcomb, bfx, wh, fxh, nullptr, npart, CC, 0, 0);
    // 2: norm
    norm_reduce_kernel<<<4, 256>>>(npart, norm);
    // 3: tokens = w^T @ fx (tensor cores)
    tokpart_mma_kernel<<<dim3(TOK_CHUNKS, 16), 256, TPT_SMEM>>>(fxh, wh, tpart);
    tok_reduce_kernel<<<256, 256>>>(tpart, tok);
    // 4: tiny attention
    attn_kernel<<<16, 256, 7*4096*4>>>(ctx, Wq, bq, Wk, bk, Wv, bv,
                                       Wcq, bcq, Wck, bck, Wcv, bcv,
                                       smix, tok, norm, ot);
    // 5: fold out_tok @ Wo -> M^T (fp16)
    m_kernel<<<dim3(4, 16), 256>>>(Wo, ot, MTh);
    // 6: out = w @ M[b] + bo (fp16 GEMM, B per-batch)
    f16_gemm<0><<<dim3(4, 512), 256, SM_GEMM>>>(
        wh, MTh, bo, nullptr, nullptr, nullptr, out, nullptr, INNER, NN, 512*512);
}